// round 1
// baseline (speedup 1.0000x reference)
#include <cuda_runtime.h>
#include <math_constants.h>

// ---------------------------------------------------------------------------
// Problem constants
//   x: [8, 256, 32, 32]  C=256 HEADS=8 HD=32 N=1024 D=32
// ---------------------------------------------------------------------------
#define BATCH 8
#define CC 256
#define NPIX 1024
#define NHEAD 8
#define HDIM 32
#define DDIM 32

// Scratch (device globals: allocation-free, graph-capture safe)
__device__ float g_qkv[BATCH * 3 * CC * NPIX];    // [b][768][1024]
__device__ float g_ctx[BATCH * CC * NPIX];        // attention context
__device__ float g_ao[BATCH * CC * NPIX];         // after out_w projection
__device__ float g_feats[4 * BATCH * CC * NPIX];  // branch features
__device__ float g_wT[5505024];                   // repacked conv weights [tap][c][o]
__device__ float g_S[BATCH * CC];
__device__ float g_attnw[4 * BATCH * CC];

// wT branch offsets: k=1 -> 0, k=3 -> 65536, k=5 -> 655360, k=7 -> 2293760
#define WT_OFF1 0
#define WT_OFF3 65536
#define WT_OFF5 655360
#define WT_OFF7 2293760

// ---------------------------------------------------------------------------
// Repack conv weights OIHW -> [tap][c][o] (contiguous in o for coalesced A loads)
// ---------------------------------------------------------------------------
__global__ void wtrans_kernel(const float* __restrict__ w1, const float* __restrict__ w3,
                              const float* __restrict__ w5, const float* __restrict__ w7) {
    int idx = blockIdx.x * 256 + threadIdx.x;
    if (idx >= 5505024) return;
    const float* src;
    int k2, base;
    if (idx < 655360)       { if (idx < 65536) { src = w1; k2 = 1;  base = 0; }
                              else             { src = w3; k2 = 9;  base = 65536; } }
    else if (idx < 2293760) { src = w5; k2 = 25; base = 655360; }
    else                    { src = w7; k2 = 49; base = 2293760; }
    int r   = idx - base;
    int o   = r & 255;
    int c   = (r >> 8) & 255;
    int tap = r >> 16;
    g_wT[idx] = src[(o * 256 + c) * k2 + tap];
}

// ---------------------------------------------------------------------------
// SGEMM: D[b] = A[M,K] @ X[b][K,1024].  BM=BN=64, BK=16, 256 thr, 4x4 micro.
// ---------------------------------------------------------------------------
__global__ __launch_bounds__(256) void sgemm_kernel(
    const float* __restrict__ A, const float* __restrict__ X, float* __restrict__ D,
    int M, int K) {
    __shared__ float As[16][68];
    __shared__ float Bs[16][64];
    int t  = threadIdx.x;
    int n0 = blockIdx.x * 64, m0 = blockIdx.y * 64, b = blockIdx.z;
    const float* Xb = X + (size_t)b * K * NPIX;
    float*       Db = D + (size_t)b * M * NPIX;
    int tm = t >> 4, tn = t & 15;
    int am = t >> 2, ak = (t & 3) * 4;
    int bk = t >> 4, bn = (t & 15) * 4;
    float acc[4][4] = {};
    for (int k0 = 0; k0 < K; k0 += 16) {
        __syncthreads();
        float4 av = *(const float4*)&A[(size_t)(m0 + am) * K + k0 + ak];
        As[ak + 0][am] = av.x; As[ak + 1][am] = av.y;
        As[ak + 2][am] = av.z; As[ak + 3][am] = av.w;
        *(float4*)&Bs[bk][bn] = *(const float4*)&Xb[(size_t)(k0 + bk) * NPIX + n0 + bn];
        __syncthreads();
#pragma unroll
        for (int kk = 0; kk < 16; kk++) {
            float4 a4 = *(float4*)&As[kk][tm * 4];
            float4 b4 = *(float4*)&Bs[kk][tn * 4];
            float ar[4] = {a4.x, a4.y, a4.z, a4.w};
            float br[4] = {b4.x, b4.y, b4.z, b4.w};
#pragma unroll
            for (int i = 0; i < 4; i++)
#pragma unroll
                for (int j = 0; j < 4; j++) acc[i][j] += ar[i] * br[j];
        }
    }
#pragma unroll
    for (int i = 0; i < 4; i++) {
        float4 o4 = make_float4(acc[i][0], acc[i][1], acc[i][2], acc[i][3]);
        *(float4*)&Db[(size_t)(m0 + tm * 4 + i) * NPIX + n0 + tn * 4] = o4;
    }
}

// ---------------------------------------------------------------------------
// Attention: flash-style online softmax. Block = (qtile of 128, b*h). 128 thr,
// one query per thread; K/V streamed through smem in 128-key tiles.
// ---------------------------------------------------------------------------
__global__ __launch_bounds__(128) void attn_kernel(const float* __restrict__ qkv,
                                                   float* __restrict__ ctx) {
    __shared__ float Ks[128][36];
    __shared__ float Vs[128][36];
    int t  = threadIdx.x;
    int bh = blockIdx.y;
    int b = bh >> 3, h = bh & 7;
    const float* base = qkv + (size_t)b * (3 * CC * NPIX);
    const float* qp = base + (h * HDIM) * NPIX;
    const float* kp = base + (CC + h * HDIM) * NPIX;
    const float* vp = base + (2 * CC + h * HDIM) * NPIX;
    int i = blockIdx.x * 128 + t;
    const float scale = 0.17677669529663687f;  // 1/sqrt(32)
    float q[HDIM];
#pragma unroll
    for (int d = 0; d < HDIM; d++) q[d] = qp[d * NPIX + i] * scale;
    float acc[HDIM] = {};
    float m = -1e30f, l = 0.f;
    for (int j0 = 0; j0 < NPIX; j0 += 128) {
        __syncthreads();
#pragma unroll
        for (int d = 0; d < HDIM; d++) {
            Ks[t][d] = kp[d * NPIX + j0 + t];
            Vs[t][d] = vp[d * NPIX + j0 + t];
        }
        __syncthreads();
        for (int jj = 0; jj < 128; jj++) {
            float s = 0.f;
#pragma unroll
            for (int d4 = 0; d4 < 8; d4++) {
                float4 k4 = *(float4*)&Ks[jj][d4 * 4];
                s += q[d4 * 4 + 0] * k4.x + q[d4 * 4 + 1] * k4.y +
                     q[d4 * 4 + 2] * k4.z + q[d4 * 4 + 3] * k4.w;
            }
            if (s > m) {
                float corr = __expf(m - s);
                m = s;
                l *= corr;
#pragma unroll
                for (int d = 0; d < HDIM; d++) acc[d] *= corr;
            }
            float p = __expf(s - m);
            l += p;
#pragma unroll
            for (int d4 = 0; d4 < 8; d4++) {
                float4 v4 = *(float4*)&Vs[jj][d4 * 4];
                acc[d4 * 4 + 0] += p * v4.x;
                acc[d4 * 4 + 1] += p * v4.y;
                acc[d4 * 4 + 2] += p * v4.z;
                acc[d4 * 4 + 3] += p * v4.w;
            }
        }
    }
    float inv = 1.f / l;
#pragma unroll
    for (int d = 0; d < HDIM; d++)
        ctx[(size_t)b * (CC * NPIX) + (h * HDIM + d) * NPIX + i] = acc[d] * inv;
}

// ---------------------------------------------------------------------------
// Conv branch as implicit GEMM over repacked weights. Tap loop outer,
// channel-chunk (16) inner. Fused bias + eval-BN + ReLU epilogue.
// ---------------------------------------------------------------------------
template <int KS>
__global__ __launch_bounds__(256) void conv_kernel(
    const float* __restrict__ in, const float* __restrict__ wT,
    const float* __restrict__ bias, const float* __restrict__ gamma,
    const float* __restrict__ beta, const float* __restrict__ mean,
    const float* __restrict__ var, float* __restrict__ outf) {
    constexpr int PAD = KS / 2;
    __shared__ float As[16][64];
    __shared__ float Bs[16][64];
    int t  = threadIdx.x;
    int n0 = blockIdx.x * 64;
    int m0 = blockIdx.y * 64;
    int b  = blockIdx.z;
    const float* inb = in + (size_t)b * (CC * NPIX);
    int tm  = t >> 4, tn = t & 15;
    int lkk = t >> 4;
    int ln4 = (t & 15) * 4;
    float acc[4][4] = {};
    for (int tap = 0; tap < KS * KS; ++tap) {
        int dy = tap / KS - PAD;
        int dx = tap % KS - PAD;
        const float* wtap = wT + (size_t)tap * (CC * CC);
        for (int c0 = 0; c0 < CC; c0 += 16) {
            __syncthreads();
            *(float4*)&As[lkk][ln4] =
                *(const float4*)&wtap[(size_t)(c0 + lkk) * CC + m0 + ln4];
            const float* inc = inb + (size_t)(c0 + lkk) * NPIX;
#pragma unroll
            for (int i = 0; i < 4; i++) {
                int n  = n0 + ln4 + i;
                int r  = (n >> 5) + dy;
                int cc = (n & 31) + dx;
                Bs[lkk][ln4 + i] =
                    ((unsigned)r < 32u && (unsigned)cc < 32u) ? inc[r * 32 + cc] : 0.f;
            }
            __syncthreads();
#pragma unroll
            for (int kk = 0; kk < 16; kk++) {
                float4 a4 = *(float4*)&As[kk][tm * 4];
                float4 b4 = *(float4*)&Bs[kk][tn * 4];
                float ar[4] = {a4.x, a4.y, a4.z, a4.w};
                float br[4] = {b4.x, b4.y, b4.z, b4.w};
#pragma unroll
                for (int i = 0; i < 4; i++)
#pragma unroll
                    for (int j = 0; j < 4; j++) acc[i][j] += ar[i] * br[j];
            }
        }
    }
#pragma unroll
    for (int i = 0; i < 4; i++) {
        int o = m0 + tm * 4 + i;
        float inv = gamma[o] * rsqrtf(var[o] + 1e-5f);
        float sh  = beta[o] - mean[o] * inv;
        float bi  = bias[o];
        float4 o4;
        o4.x = fmaxf((acc[i][0] + bi) * inv + sh, 0.f);
        o4.y = fmaxf((acc[i][1] + bi) * inv + sh, 0.f);
        o4.z = fmaxf((acc[i][2] + bi) * inv + sh, 0.f);
        o4.w = fmaxf((acc[i][3] + bi) * inv + sh, 0.f);
        *(float4*)&outf[(size_t)(b * CC + o) * NPIX + n0 + tn * 4] = o4;
    }
}

// ---------------------------------------------------------------------------
// S[b,c] = mean over pixels of sum-over-branches of feats
// ---------------------------------------------------------------------------
__global__ __launch_bounds__(128) void sreduce_kernel(float* __restrict__ S) {
    int bc = blockIdx.x;  // 0..2047  (b*256+c)
    int t  = threadIdx.x; // 128
    float s = 0.f;
#pragma unroll
    for (int k = 0; k < 4; k++) {
        const float* p = g_feats + ((size_t)k * (BATCH * CC) + bc) * NPIX;
        for (int n = t; n < NPIX; n += 128) s += p[n];
    }
#pragma unroll
    for (int off = 16; off; off >>= 1) s += __shfl_down_sync(0xffffffffu, s, off);
    __shared__ float red[4];
    if ((t & 31) == 0) red[t >> 5] = s;
    __syncthreads();
    if (t == 0) S[bc] = (red[0] + red[1] + red[2] + red[3]) * (1.f / 1024.f);
}

// ---------------------------------------------------------------------------
// fc -> per-branch logits -> softmax over branches. Single block.
// ---------------------------------------------------------------------------
__global__ __launch_bounds__(256) void select_kernel(
    const float* __restrict__ S, const float* __restrict__ fc_w,
    const float* __restrict__ fc_b, const float* __restrict__ fcs_w,
    const float* __restrict__ fcs_b, float* __restrict__ attnw) {
    __shared__ float Ss[BATCH * CC];
    __shared__ float Zs[BATCH * DDIM];
    int t = threadIdx.x;  // 256
    for (int i = t; i < BATCH * CC; i += 256) Ss[i] = S[i];
    __syncthreads();
    {   // Z[b,d] = S[b] . fc_w[d] + fc_b[d]   (256 outputs = 8*32)
        int b = t >> 5, d = t & 31;
        float z = fc_b[d];
        const float* wr = fc_w + d * CC;
        for (int c = 0; c < CC; c++) z += Ss[b * CC + c] * wr[c];
        Zs[b * DDIM + d] = z;
    }
    __syncthreads();
    for (int it = 0; it < 8; it++) {
        int idx = it * 256 + t;       // b*256 + c
        int b = idx >> 8, c = idx & 255;
        float lg[4];
#pragma unroll
        for (int k = 0; k < 4; k++) {
            float v = fcs_b[k * CC + c];
            const float* wp = fcs_w + ((size_t)k * CC + c) * DDIM;
#pragma unroll
            for (int d = 0; d < DDIM; d++) v += wp[d] * Zs[b * DDIM + d];
            lg[k] = v;
        }
        float mx  = fmaxf(fmaxf(lg[0], lg[1]), fmaxf(lg[2], lg[3]));
        float e0 = __expf(lg[0] - mx), e1 = __expf(lg[1] - mx);
        float e2 = __expf(lg[2] - mx), e3 = __expf(lg[3] - mx);
        float inv = 1.f / (e0 + e1 + e2 + e3);
        attnw[0 * 2048 + idx] = e0 * inv;
        attnw[1 * 2048 + idx] = e1 * inv;
        attnw[2 * 2048 + idx] = e2 * inv;
        attnw[3 * 2048 + idx] = e3 * inv;
    }
}

// ---------------------------------------------------------------------------
// V = sum_k attn[k,b,c] * feats[k,b,c,:]
// ---------------------------------------------------------------------------
__global__ __launch_bounds__(256) void combine_kernel(const float* __restrict__ attnw,
                                                      float* __restrict__ out) {
    int idx = blockIdx.x * 256 + threadIdx.x;
    if (idx >= BATCH * CC * NPIX) return;
    int bc = idx >> 10;
    const size_t KSTRIDE = (size_t)BATCH * CC * NPIX;  // 2097152
    float v = attnw[bc]        * g_feats[idx] +
              attnw[2048 + bc] * g_feats[KSTRIDE + idx] +
              attnw[4096 + bc] * g_feats[2 * KSTRIDE + idx] +
              attnw[6144 + bc] * g_feats[3 * KSTRIDE + idx];
    out[idx] = v;
}

// ---------------------------------------------------------------------------
// Launch
// ---------------------------------------------------------------------------
extern "C" void kernel_launch(void* const* d_in, const int* in_sizes, int n_in,
                              void* d_out, int out_size) {
    const float* x      = (const float*)d_in[0];
    const float* qkv_w  = (const float*)d_in[1];
    const float* out_w  = (const float*)d_in[2];
    const float* w1     = (const float*)d_in[3];
    const float* w3     = (const float*)d_in[4];
    const float* w5     = (const float*)d_in[5];
    const float* w7     = (const float*)d_in[6];
    const float* conv_b = (const float*)d_in[7];
    const float* gamma  = (const float*)d_in[8];
    const float* beta   = (const float*)d_in[9];
    const float* mean   = (const float*)d_in[10];
    const float* var    = (const float*)d_in[11];
    const float* fc_w   = (const float*)d_in[12];
    const float* fc_b   = (const float*)d_in[13];
    const float* fcs_w  = (const float*)d_in[14];
    const float* fcs_b  = (const float*)d_in[15];
    float* out = (float*)d_out;

    float *p_qkv, *p_ctx, *p_ao, *p_feats, *p_S, *p_attnw, *p_wT;
    cudaGetSymbolAddress((void**)&p_qkv,   g_qkv);
    cudaGetSymbolAddress((void**)&p_ctx,   g_ctx);
    cudaGetSymbolAddress((void**)&p_ao,    g_ao);
    cudaGetSymbolAddress((void**)&p_feats, g_feats);
    cudaGetSymbolAddress((void**)&p_S,     g_S);
    cudaGetSymbolAddress((void**)&p_attnw, g_attnw);
    cudaGetSymbolAddress((void**)&p_wT,    g_wT);

    const size_t FSTR = (size_t)BATCH * CC * NPIX;  // per-branch feats stride

    wtrans_kernel<<<21504, 256>>>(w1, w3, w5, w7);
    sgemm_kernel<<<dim3(16, 12, 8), 256>>>(qkv_w, x, p_qkv, 3 * CC, CC);
    attn_kernel<<<dim3(8, 64), 128>>>(p_qkv, p_ctx);
    sgemm_kernel<<<dim3(16, 4, 8), 256>>>(out_w, p_ctx, p_ao, CC, CC);

    conv_kernel<1><<<dim3(16, 4, 8), 256>>>(p_ao, p_wT + WT_OFF1, conv_b + 0,
        gamma + 0,   beta + 0,   mean + 0,   var + 0,   p_feats + 0 * FSTR);
    conv_kernel<3><<<dim3(16, 4, 8), 256>>>(p_ao, p_wT + WT_OFF3, conv_b + 256,
        gamma + 256, beta + 256, mean + 256, var + 256, p_feats + 1 * FSTR);
    conv_kernel<5><<<dim3(16, 4, 8), 256>>>(p_ao, p_wT + WT_OFF5, conv_b + 512,
        gamma + 512, beta + 512, mean + 512, var + 512, p_feats + 2 * FSTR);
    conv_kernel<7><<<dim3(16, 4, 8), 256>>>(p_ao, p_wT + WT_OFF7, conv_b + 768,
        gamma + 768, beta + 768, mean + 768, var + 768, p_feats + 3 * FSTR);

    sreduce_kernel<<<2048, 128>>>(p_S);
    select_kernel<<<1, 256>>>(p_S, fc_w, fc_b, fcs_w, fcs_b, p_attnw);
    combine_kernel<<<8192, 256>>>(p_attnw, out);
}

// round 4
// speedup vs baseline: 2.2813x; 2.2813x over previous
#include <cuda_runtime.h>
#include <math_constants.h>
#include <cstdint>

// ---------------------------------------------------------------------------
// Problem constants: x [8, 256, 32, 32], C=256 HEADS=8 HD=32 N=1024 D=32
// ---------------------------------------------------------------------------
#define BATCH 8
#define CC 256
#define NPIX 1024
#define NHEAD 8
#define HDIM 32
#define DDIM 32

// Scratch (device globals: allocation-free, graph-capture safe)
__device__ float g_qkv[BATCH * 3 * CC * NPIX];
__device__ float g_ctx[BATCH * CC * NPIX];
__device__ float g_ao[BATCH * CC * NPIX];
__device__ float g_feats[4 * BATCH * CC * NPIX];
__device__ float g_wT[5505024];                   // conv weights [tap][c][o], tf32-rounded
__device__ float g_part[8 * BATCH * CC * NPIX];   // split-K conv partials (8 slots)
__device__ float g_bnA[4 * CC];                   // BN scale
__device__ float g_bnB[4 * CC];                   // BN shift (bias folded)
__device__ float g_S[BATCH * CC];
__device__ float g_attnw[4 * BATCH * CC];

#define WT_OFF1 0
#define WT_OFF3 65536
#define WT_OFF5 655360
#define WT_OFF7 2293760

// cvt.rna.tf32.f32 writes a .b32 destination in PTX -> use "=r" + bitcast
__device__ __forceinline__ float to_tf32(float x) {
    uint32_t y;
    asm("cvt.rna.tf32.f32 %0, %1;" : "=r"(y) : "f"(x));
    return __uint_as_float(y);
}

// ---------------------------------------------------------------------------
// Repack conv weights OIHW -> [tap][c][o], rounded to tf32
// ---------------------------------------------------------------------------
__global__ void wtrans_kernel(const float* __restrict__ w1, const float* __restrict__ w3,
                              const float* __restrict__ w5, const float* __restrict__ w7) {
    int idx = blockIdx.x * 256 + threadIdx.x;
    if (idx >= 5505024) return;
    const float* src;
    int k2, base;
    if (idx < 655360)       { if (idx < 65536) { src = w1; k2 = 1;  base = 0; }
                              else             { src = w3; k2 = 9;  base = 65536; } }
    else if (idx < 2293760) { src = w5; k2 = 25; base = 655360; }
    else                    { src = w7; k2 = 49; base = 2293760; }
    int r   = idx - base;
    int o   = r & 255;
    int c   = (r >> 8) & 255;
    int tap = r >> 16;
    g_wT[idx] = to_tf32(src[(o * 256 + c) * k2 + tap]);
}

// ---------------------------------------------------------------------------
// SGEMM (fp32 SIMT) for qkv / out projections (small share of total)
// ---------------------------------------------------------------------------
__global__ __launch_bounds__(256) void sgemm_kernel(
    const float* __restrict__ A, const float* __restrict__ X, float* __restrict__ D,
    int M, int K) {
    __shared__ float As[16][68];
    __shared__ float Bs[16][64];
    int t  = threadIdx.x;
    int n0 = blockIdx.x * 64, m0 = blockIdx.y * 64, b = blockIdx.z;
    const float* Xb = X + (size_t)b * K * NPIX;
    float*       Db = D + (size_t)b * M * NPIX;
    int tm = t >> 4, tn = t & 15;
    int am = t >> 2, ak = (t & 3) * 4;
    int bk = t >> 4, bn = (t & 15) * 4;
    float acc[4][4] = {};
    for (int k0 = 0; k0 < K; k0 += 16) {
        __syncthreads();
        float4 av = *(const float4*)&A[(size_t)(m0 + am) * K + k0 + ak];
        As[ak + 0][am] = av.x; As[ak + 1][am] = av.y;
        As[ak + 2][am] = av.z; As[ak + 3][am] = av.w;
        *(float4*)&Bs[bk][bn] = *(const float4*)&Xb[(size_t)(k0 + bk) * NPIX + n0 + bn];
        __syncthreads();
#pragma unroll
        for (int kk = 0; kk < 16; kk++) {
            float4 a4 = *(float4*)&As[kk][tm * 4];
            float4 b4 = *(float4*)&Bs[kk][tn * 4];
            float ar[4] = {a4.x, a4.y, a4.z, a4.w};
            float br[4] = {b4.x, b4.y, b4.z, b4.w};
#pragma unroll
            for (int i = 0; i < 4; i++)
#pragma unroll
                for (int j = 0; j < 4; j++) acc[i][j] += ar[i] * br[j];
        }
    }
#pragma unroll
    for (int i = 0; i < 4; i++) {
        float4 o4 = make_float4(acc[i][0], acc[i][1], acc[i][2], acc[i][3]);
        *(float4*)&Db[(size_t)(m0 + tm * 4 + i) * NPIX + n0 + tn * 4] = o4;
    }
}

// ---------------------------------------------------------------------------
// Attention: flash-style online softmax (fp32)
// ---------------------------------------------------------------------------
__global__ __launch_bounds__(128) void attn_kernel(const float* __restrict__ qkv,
                                                   float* __restrict__ ctx) {
    __shared__ float Ks[128][36];
    __shared__ float Vs[128][36];
    int t  = threadIdx.x;
    int bh = blockIdx.y;
    int b = bh >> 3, h = bh & 7;
    const float* base = qkv + (size_t)b * (3 * CC * NPIX);
    const float* qp = base + (h * HDIM) * NPIX;
    const float* kp = base + (CC + h * HDIM) * NPIX;
    const float* vp = base + (2 * CC + h * HDIM) * NPIX;
    int i = blockIdx.x * 128 + t;
    const float scale = 0.17677669529663687f;
    float q[HDIM];
#pragma unroll
    for (int d = 0; d < HDIM; d++) q[d] = qp[d * NPIX + i] * scale;
    float acc[HDIM] = {};
    float m = -1e30f, l = 0.f;
    for (int j0 = 0; j0 < NPIX; j0 += 128) {
        __syncthreads();
#pragma unroll
        for (int d = 0; d < HDIM; d++) {
            Ks[t][d] = kp[d * NPIX + j0 + t];
            Vs[t][d] = vp[d * NPIX + j0 + t];
        }
        __syncthreads();
        for (int jj = 0; jj < 128; jj++) {
            float s = 0.f;
#pragma unroll
            for (int d4 = 0; d4 < 8; d4++) {
                float4 k4 = *(float4*)&Ks[jj][d4 * 4];
                s += q[d4 * 4 + 0] * k4.x + q[d4 * 4 + 1] * k4.y +
                     q[d4 * 4 + 2] * k4.z + q[d4 * 4 + 3] * k4.w;
            }
            if (s > m) {
                float corr = __expf(m - s);
                m = s;
                l *= corr;
#pragma unroll
                for (int d = 0; d < HDIM; d++) acc[d] *= corr;
            }
            float p = __expf(s - m);
            l += p;
#pragma unroll
            for (int d4 = 0; d4 < 8; d4++) {
                float4 v4 = *(float4*)&Vs[jj][d4 * 4];
                acc[d4 * 4 + 0] += p * v4.x;
                acc[d4 * 4 + 1] += p * v4.y;
                acc[d4 * 4 + 2] += p * v4.z;
                acc[d4 * 4 + 3] += p * v4.w;
            }
        }
    }
    float inv = 1.f / l;
#pragma unroll
    for (int d = 0; d < HDIM; d++)
        ctx[(size_t)b * (CC * NPIX) + (h * HDIM + d) * NPIX + i] = acc[d] * inv;
}

// ---------------------------------------------------------------------------
// Conv via tf32 mma.sync implicit GEMM.
// CTA tile: M=128 (out ch) x N=256 (pixels = 8 image rows). 8 warps (2m x 4n),
// warp tile 64x64 via m16n8k8. Input patch [16c][14row][32col] in smem per
// c-chunk; taps read shifted views (per-lane column predicate for halo).
// Split-K over taps -> g_part slots. Epilogue kernel applies BN/ReLU.
// ---------------------------------------------------------------------------
#define PATCH_CSTRIDE 456   // 14*32=448 +8 pad: bank spread conflict-free
#define A_STRIDE 136        // 128 + 8 pad
#define A_BUF (16 * A_STRIDE)

__device__ __forceinline__ void mma_tf32(float* d, const uint32_t* a, const uint32_t* b) {
    asm volatile(
        "mma.sync.aligned.m16n8k8.row.col.f32.tf32.tf32.f32 "
        "{%0,%1,%2,%3}, {%4,%5,%6,%7}, {%8,%9}, {%0,%1,%2,%3};"
        : "+f"(d[0]), "+f"(d[1]), "+f"(d[2]), "+f"(d[3])
        : "r"(a[0]), "r"(a[1]), "r"(a[2]), "r"(a[3]), "r"(b[0]), "r"(b[1]));
}

__global__ __launch_bounds__(256) void conv_mma_kernel(const float* __restrict__ in) {
    __shared__ float sP[16 * PATCH_CSTRIDE];  // input patch
    __shared__ float sA[2 * A_BUF];           // double-buffered weight tile

    // Decode blockIdx.z -> (ks, tap range, slot, batch). Heavy branches first.
    int z = blockIdx.z;
    int ks, tap0, tap1, slot, wtoff, b;
    if (z < 32) {        // k=7, 4 splits
        int s = z >> 3; b = z & 7;
        ks = 7; tap0 = (s * 49) >> 2; tap1 = ((s + 1) * 49) >> 2;
        slot = 4 + s; wtoff = WT_OFF7;
    } else if (z < 48) { // k=5, 2 splits
        int s = (z - 32) >> 3; b = z & 7;
        ks = 5; tap0 = (s * 25) >> 1; tap1 = ((s + 1) * 25) >> 1;
        slot = 2 + s; wtoff = WT_OFF5;
    } else if (z < 56) { // k=3
        b = z - 48; ks = 3; tap0 = 0; tap1 = 9; slot = 1; wtoff = WT_OFF3;
    } else {             // k=1
        b = z - 56; ks = 1; tap0 = 0; tap1 = 1; slot = 0; wtoff = WT_OFF1;
    }
    const int P = ks >> 1;
    const int rows = 8 + 2 * P;

    int n0 = blockIdx.x * 256;        // pixel tile (8 image rows)
    int m0 = blockIdx.y * 128;        // out-channel tile
    int r0 = n0 >> 5;                 // first image row of tile
    int tid = threadIdx.x;
    int wid = tid >> 5, lane = tid & 31;
    int mw = (wid >> 2) * 64;         // warp m offset (0/64)
    int nw = (wid & 3) * 64;          // warp n offset (0/64/128/192)
    int lg = lane >> 2;               // lane group 0..7
    int lk = lane & 3;                // lane k-slot 0..3

    // Per-lane pixel coords for the 8 n8-tiles of the warp
    int yj[8], xj[8];
#pragma unroll
    for (int j = 0; j < 8; j++) {
        int n = nw + 8 * j + lg;
        yj[j] = n >> 5;
        xj[j] = n & 31;
    }

    const float* inb = in + (size_t)b * (CC * NPIX);
    float acc[4][8][4] = {};

    for (int c0 = 0; c0 < 256; c0 += 16) {
        __syncthreads();  // all prior MMAs done before overwriting sP / sA[0]
        // --- load input patch: 16 c-planes x rows x 32, tf32-rounded ---
        {
            int total = 16 * rows * 8;  // float4 count
            int per_row = rows * 8;
            for (int i = tid; i < total; i += 256) {
                int c  = i / per_row;
                int rm = i - c * per_row;
                int py = rm >> 3;
                int xq = (rm & 7) * 4;
                int iy = r0 - P + py;
                float4 v = make_float4(0.f, 0.f, 0.f, 0.f);
                if ((unsigned)iy < 32u)
                    v = *(const float4*)&inb[(size_t)(c0 + c) * NPIX + iy * 32 + xq];
                v.x = to_tf32(v.x); v.y = to_tf32(v.y);
                v.z = to_tf32(v.z); v.w = to_tf32(v.w);
                *(float4*)&sP[c * PATCH_CSTRIDE + py * 32 + xq] = v;
            }
        }
        // --- preload A(tap0) into buffer 0 ---
        {
            const float* wt = g_wT + (size_t)wtoff + (size_t)tap0 * (CC * CC);
            for (int i = tid; i < 512; i += 256) {
                int k = i >> 5, col = (i & 31) * 4;
                *(float4*)&sA[k * A_STRIDE + col] =
                    *(const float4*)&wt[(size_t)(c0 + k) * CC + m0 + col];
            }
        }
        __syncthreads();

        int buf = 0;
        for (int tap = tap0; tap < tap1; tap++) {
            // prefetch next tap's weights into other buffer
            if (tap + 1 < tap1) {
                const float* wt = g_wT + (size_t)wtoff + (size_t)(tap + 1) * (CC * CC);
                float* dst = sA + (buf ^ 1) * A_BUF;
                for (int i = tid; i < 512; i += 256) {
                    int k = i >> 5, col = (i & 31) * 4;
                    *(float4*)&dst[k * A_STRIDE + col] =
                        *(const float4*)&wt[(size_t)(c0 + k) * CC + m0 + col];
                }
            }
            int ty = tap / ks;
            int tx = tap - ty * ks;
            const uint32_t* A = (const uint32_t*)(sA + buf * A_BUF);
            const uint32_t* Pp = (const uint32_t*)sP;
#pragma unroll
            for (int s = 0; s < 2; s++) {
                int k = s * 8 + lk;
                uint32_t a[4][4];
#pragma unroll
                for (int t = 0; t < 4; t++) {
                    int m = mw + 16 * t + lg;
                    a[t][0] = A[k * A_STRIDE + m];
                    a[t][1] = A[k * A_STRIDE + m + 8];
                    a[t][2] = A[(k + 4) * A_STRIDE + m];
                    a[t][3] = A[(k + 4) * A_STRIDE + m + 8];
                }
                uint32_t bb[8][2];
#pragma unroll
                for (int j = 0; j < 8; j++) {
                    int py = yj[j] + ty;
                    int ix = xj[j] + tx - P;
                    bool ok = (unsigned)ix < 32u;
                    int off = py * 32 + ix;
                    bb[j][0] = ok ? Pp[k * PATCH_CSTRIDE + off] : 0u;
                    bb[j][1] = ok ? Pp[(k + 4) * PATCH_CSTRIDE + off] : 0u;
                }
#pragma unroll
                for (int t = 0; t < 4; t++)
#pragma unroll
                    for (int j = 0; j < 8; j++) mma_tf32(acc[t][j], a[t], bb[j]);
            }
            __syncthreads();
            buf ^= 1;
        }
    }

    // --- write raw partials to slot ---
    float* pp = g_part + (size_t)slot * (BATCH * CC * NPIX) + (size_t)b * (CC * NPIX);
#pragma unroll
    for (int t = 0; t < 4; t++) {
        int o = m0 + mw + 16 * t + lg;
#pragma unroll
        for (int j = 0; j < 8; j++) {
            int n = n0 + nw + 8 * j + 2 * lk;
            *(float2*)&pp[(size_t)o * NPIX + n] =
                make_float2(acc[t][j][0], acc[t][j][1]);
            *(float2*)&pp[(size_t)(o + 8) * NPIX + n] =
                make_float2(acc[t][j][2], acc[t][j][3]);
        }
    }
}

// ---------------------------------------------------------------------------
// BN constants: A = gamma/sqrt(var+eps); B = beta - mean*A + bias*A
// ---------------------------------------------------------------------------
__global__ void bnprep_kernel(const float* __restrict__ conv_b,
                              const float* __restrict__ gamma,
                              const float* __restrict__ beta,
                              const float* __restrict__ mean,
                              const float* __restrict__ var) {
    int i = threadIdx.x;  // 1024 = 4*256
    float inv = gamma[i] * rsqrtf(var[i] + 1e-5f);
    g_bnA[i] = inv;
    g_bnB[i] = beta[i] - mean[i] * inv + conv_b[i] * inv;
}

// ---------------------------------------------------------------------------
// Epilogue: sum split-K partials, BN + ReLU -> feats
// ---------------------------------------------------------------------------
__global__ __launch_bounds__(256) void epi_kernel(float* __restrict__ feats) {
    int row = blockIdx.x;          // k*2048 + b*256 + o
    int k   = row >> 11;
    int bc  = row & 2047;
    int o   = bc & 255;
    float Aa = g_bnA[k * 256 + o];
    float Bb = g_bnB[k * 256 + o];
    size_t base = (size_t)bc * NPIX + threadIdx.x * 4;
    const size_t SL = (size_t)BATCH * CC * NPIX;
    float4 s;
    if (k == 0) {
        s = *(const float4*)&g_part[base];
    } else if (k == 1) {
        s = *(const float4*)&g_part[SL + base];
    } else if (k == 2) {
        float4 s0 = *(const float4*)&g_part[2 * SL + base];
        float4 s1 = *(const float4*)&g_part[3 * SL + base];
        s = make_float4(s0.x + s1.x, s0.y + s1.y, s0.z + s1.z, s0.w + s1.w);
    } else {
        float4 s0 = *(const float4*)&g_part[4 * SL + base];
        float4 s1 = *(const float4*)&g_part[5 * SL + base];
        float4 s2 = *(const float4*)&g_part[6 * SL + base];
        float4 s3 = *(const float4*)&g_part[7 * SL + base];
        s = make_float4(s0.x + s1.x + s2.x + s3.x, s0.y + s1.y + s2.y + s3.y,
                        s0.z + s1.z + s2.z + s3.z, s0.w + s1.w + s2.w + s3.w);
    }
    float4 v;
    v.x = fmaxf(s.x * Aa + Bb, 0.f);
    v.y = fmaxf(s.y * Aa + Bb, 0.f);
    v.z = fmaxf(s.z * Aa + Bb, 0.f);
    v.w = fmaxf(s.w * Aa + Bb, 0.f);
    *(float4*)&feats[(size_t)k * SL + base] = v;
}

// ---------------------------------------------------------------------------
// S[b,c] = mean over pixels of sum-over-branches of feats
// ---------------------------------------------------------------------------
__global__ __launch_bounds__(128) void sreduce_kernel(float* __restrict__ S) {
    int bc = blockIdx.x;
    int t  = threadIdx.x;
    float s = 0.f;
#pragma unroll
    for (int k = 0; k < 4; k++) {
        const float* p = g_feats + ((size_t)k * (BATCH * CC) + bc) * NPIX;
        for (int n = t; n < NPIX; n += 128) s += p[n];
    }
#pragma unroll
    for (int off = 16; off; off >>= 1) s += __shfl_down_sync(0xffffffffu, s, off);
    __shared__ float red[4];
    if ((t & 31) == 0) red[t >> 5] = s;
    __syncthreads();
    if (t == 0) S[bc] = (red[0] + red[1] + red[2] + red[3]) * (1.f / 1024.f);
}

// ---------------------------------------------------------------------------
// fc -> per-branch logits -> softmax over branches
// ---------------------------------------------------------------------------
__global__ __launch_bounds__(256) void select_kernel(
    const float* __restrict__ S, const float* __restrict__ fc_w,
    const float* __restrict__ fc_b, const float* __restrict__ fcs_w,
    const float* __restrict__ fcs_b, float* __restrict__ attnw) {
    __shared__ float Ss[BATCH * CC];
    __shared__ float Zs[BATCH * DDIM];
    int t = threadIdx.x;
    for (int i = t; i < BATCH * CC; i += 256) Ss[i] = S[i];
    __syncthreads();
    {
        int b = t >> 5, d = t & 31;
        float z = fc_b[d];
        const float* wr = fc_w + d * CC;
        for (int c = 0; c < CC; c++) z += Ss[b * CC + c] * wr[c];
        Zs[b * DDIM + d] = z;
    }
    __syncthreads();
    for (int it = 0; it < 8; it++) {
        int idx = it * 256 + t;
        int b = idx >> 8, c = idx & 255;
        float lg[4];
#pragma unroll
        for (int k = 0; k < 4; k++) {
            float v = fcs_b[k * CC + c];
            const float* wp = fcs_w + ((size_t)k * CC + c) * DDIM;
#pragma unroll
            for (int d = 0; d < DDIM; d++) v += wp[d] * Zs[b * DDIM + d];
            lg[k] = v;
        }
        float mx  = fmaxf(fmaxf(lg[0], lg[1]), fmaxf(lg[2], lg[3]));
        float e0 = __expf(lg[0] - mx), e1 = __expf(lg[1] - mx);
        float e2 = __expf(lg[2] - mx), e3 = __expf(lg[3] - mx);
        float inv = 1.f / (e0 + e1 + e2 + e3);
        attnw[0 * 2048 + idx] = e0 * inv;
        attnw[1 * 2048 + idx] = e1 * inv;
        attnw[2 * 2048 + idx] = e2 * inv;
        attnw[3 * 2048 + idx] = e3 * inv;
    }
}

// ---------------------------------------------------------------------------
// V = sum_k attn[k,b,c] * feats[k,b,c,:]
// ---------------------------------------------------------------------------
__global__ __launch_bounds__(256) void combine_kernel(const float* __restrict__ attnw,
                                                      float* __restrict__ out) {
    int idx = blockIdx.x * 256 + threadIdx.x;
    if (idx >= BATCH * CC * NPIX) return;
    int bc = idx >> 10;
    const size_t KSTRIDE = (size_t)BATCH * CC * NPIX;
    float v = attnw[bc]        * g_feats[idx] +
              attnw[2048 + bc] * g_feats[KSTRIDE + idx] +
              attnw[4096 + bc] * g_feats[2 * KSTRIDE + idx] +
              attnw[6144 + bc] * g_feats[3 * KSTRIDE + idx];
    out[idx] = v;
}

// ---------------------------------------------------------------------------
// Launch
// ---------------------------------------------------------------------------
extern "C" void kernel_launch(void* const* d_in, const int* in_sizes, int n_in,
                              void* d_out, int out_size) {
    const float* x      = (const float*)d_in[0];
    const float* qkv_w  = (const float*)d_in[1];
    const float* out_w  = (const float*)d_in[2];
    const float* w1     = (const float*)d_in[3];
    const float* w3     = (const float*)d_in[4];
    const float* w5     = (const float*)d_in[5];
    const float* w7     = (const float*)d_in[6];
    const float* conv_b = (const float*)d_in[7];
    const float* gamma  = (const float*)d_in[8];
    const float* beta   = (const float*)d_in[9];
    const float* mean   = (const float*)d_in[10];
    const float* var    = (const float*)d_in[11];
    const float* fc_w   = (const float*)d_in[12];
    const float* fc_b   = (const float*)d_in[13];
    const float* fcs_w  = (const float*)d_in[14];
    const float* fcs_b  = (const float*)d_in[15];
    float* out = (float*)d_out;

    float *p_qkv, *p_ctx, *p_ao, *p_feats, *p_S, *p_attnw;
    cudaGetSymbolAddress((void**)&p_qkv,   g_qkv);
    cudaGetSymbolAddress((void**)&p_ctx,   g_ctx);
    cudaGetSymbolAddress((void**)&p_ao,    g_ao);
    cudaGetSymbolAddress((void**)&p_feats, g_feats);
    cudaGetSymbolAddress((void**)&p_S,     g_S);
    cudaGetSymbolAddress((void**)&p_attnw, g_attnw);

    wtrans_kernel<<<21504, 256>>>(w1, w3, w5, w7);
    bnprep_kernel<<<1, 1024>>>(conv_b, gamma, beta, mean, var);
    sgemm_kernel<<<dim3(16, 12, 8), 256>>>(qkv_w, x, p_qkv, 3 * CC, CC);
    attn_kernel<<<dim3(8, 64), 128>>>(p_qkv, p_ctx);
    sgemm_kernel<<<dim3(16, 4, 8), 256>>>(out_w, p_ctx, p_ao, CC, CC);

    // Conv: all branches + split-K in one launch (512 CTAs, heavy first)
    conv_mma_kernel<<<dim3(4, 2, 64), 256>>>(p_ao);
    epi_kernel<<<4 * 2048, 256>>>(p_feats);

    sreduce_kernel<<<2048, 128>>>(p_S);
    select_kernel<<<1, 256>>>(p_S, fc_w, fc_b, fcs_w, fcs_b, p_attnw);
    combine_kernel<<<8192, 256>>>(p_attnw, out);
}

// round 5
// speedup vs baseline: 2.5562x; 1.1205x over previous
#include <cuda_runtime.h>
#include <math_constants.h>
#include <cstdint>

// ---------------------------------------------------------------------------
// Problem constants: x [8, 256, 32, 32], C=256 HEADS=8 HD=32 N=1024 D=32
// ---------------------------------------------------------------------------
#define BATCH 8
#define CC 256
#define NPIX 1024
#define NHEAD 8
#define HDIM 32
#define DDIM 32

// Scratch (device globals: allocation-free, graph-capture safe)
__device__ float g_qkv[BATCH * 3 * CC * NPIX];
__device__ float g_ctx[BATCH * CC * NPIX];
__device__ float g_ao[BATCH * CC * NPIX];
__device__ float g_feats[4 * BATCH * CC * NPIX];
__device__ float g_wT[5505024];                   // conv weights [tap][c][o], tf32-rounded
__device__ float g_part[8 * BATCH * CC * NPIX];   // split-K conv partials (8 slots)
__device__ float g_bnA[4 * CC];
__device__ float g_bnB[4 * CC];
__device__ float g_S[BATCH * CC];
__device__ float g_attnw[4 * BATCH * CC];

#define WT_OFF1 0
#define WT_OFF3 65536
#define WT_OFF5 655360
#define WT_OFF7 2293760

// cvt.rna.tf32.f32 writes a .b32 destination in PTX -> use "=r" + bitcast
__device__ __forceinline__ float to_tf32(float x) {
    uint32_t y;
    asm("cvt.rna.tf32.f32 %0, %1;" : "=r"(y) : "f"(x));
    return __uint_as_float(y);
}
__device__ __forceinline__ uint32_t to_tf32_u(float x) {
    uint32_t y;
    asm("cvt.rna.tf32.f32 %0, %1;" : "=r"(y) : "f"(x));
    return y;
}

__device__ __forceinline__ void mma_tf32(float* d, const uint32_t* a, const uint32_t* b) {
    asm volatile(
        "mma.sync.aligned.m16n8k8.row.col.f32.tf32.tf32.f32 "
        "{%0,%1,%2,%3}, {%4,%5,%6,%7}, {%8,%9}, {%0,%1,%2,%3};"
        : "+f"(d[0]), "+f"(d[1]), "+f"(d[2]), "+f"(d[3])
        : "r"(a[0]), "r"(a[1]), "r"(a[2]), "r"(a[3]), "r"(b[0]), "r"(b[1]));
}

// ---------------------------------------------------------------------------
// Repack conv weights OIHW -> [tap][c][o], rounded to tf32
// ---------------------------------------------------------------------------
__global__ void wtrans_kernel(const float* __restrict__ w1, const float* __restrict__ w3,
                              const float* __restrict__ w5, const float* __restrict__ w7) {
    int idx = blockIdx.x * 256 + threadIdx.x;
    if (idx >= 5505024) return;
    const float* src;
    int k2, base;
    if (idx < 655360)       { if (idx < 65536) { src = w1; k2 = 1;  base = 0; }
                              else             { src = w3; k2 = 9;  base = 65536; } }
    else if (idx < 2293760) { src = w5; k2 = 25; base = 655360; }
    else                    { src = w7; k2 = 49; base = 2293760; }
    int r   = idx - base;
    int o   = r & 255;
    int c   = (r >> 8) & 255;
    int tap = r >> 16;
    g_wT[idx] = to_tf32(src[(o * 256 + c) * k2 + tap]);
}

// ---------------------------------------------------------------------------
// SGEMM (fp32 SIMT) for qkv / out projections
// ---------------------------------------------------------------------------
__global__ __launch_bounds__(256) void sgemm_kernel(
    const float* __restrict__ A, const float* __restrict__ X, float* __restrict__ D,
    int M, int K) {
    __shared__ float As[16][68];
    __shared__ float Bs[16][64];
    int t  = threadIdx.x;
    int n0 = blockIdx.x * 64, m0 = blockIdx.y * 64, b = blockIdx.z;
    const float* Xb = X + (size_t)b * K * NPIX;
    float*       Db = D + (size_t)b * M * NPIX;
    int tm = t >> 4, tn = t & 15;
    int am = t >> 2, ak = (t & 3) * 4;
    int bk = t >> 4, bn = (t & 15) * 4;
    float acc[4][4] = {};
    for (int k0 = 0; k0 < K; k0 += 16) {
        __syncthreads();
        float4 av = *(const float4*)&A[(size_t)(m0 + am) * K + k0 + ak];
        As[ak + 0][am] = av.x; As[ak + 1][am] = av.y;
        As[ak + 2][am] = av.z; As[ak + 3][am] = av.w;
        *(float4*)&Bs[bk][bn] = *(const float4*)&Xb[(size_t)(k0 + bk) * NPIX + n0 + bn];
        __syncthreads();
#pragma unroll
        for (int kk = 0; kk < 16; kk++) {
            float4 a4 = *(float4*)&As[kk][tm * 4];
            float4 b4 = *(float4*)&Bs[kk][tn * 4];
            float ar[4] = {a4.x, a4.y, a4.z, a4.w};
            float br[4] = {b4.x, b4.y, b4.z, b4.w};
#pragma unroll
            for (int i = 0; i < 4; i++)
#pragma unroll
                for (int j = 0; j < 4; j++) acc[i][j] += ar[i] * br[j];
        }
    }
#pragma unroll
    for (int i = 0; i < 4; i++) {
        float4 o4 = make_float4(acc[i][0], acc[i][1], acc[i][2], acc[i][3]);
        *(float4*)&Db[(size_t)(m0 + tm * 4 + i) * NPIX + n0 + tn * 4] = o4;
    }
}

// ---------------------------------------------------------------------------
// Attention via tf32 mma.sync, flash-style online softmax.
// CTA: 128 queries x (b,h). 8 warps x 16 queries. Key tiles of 64.
// QK uses 3-mma precision split (Qhi*Khi + Qlo*Khi + Qhi*Klo): scores ~fp32.
// PV single tf32 (probs <= 1, error averages out over 1024 keys).
// Probs are reshaped C-frag -> A-frag through a per-warp smem buffer.
//
// Dynamic smem layout (floats):
//   sKhi [32][72]  @ 0       (2304)
//   sKlo [32][72]  @ 2304    (2304)
//   sV   [32][72]  @ 4608    (2304)
//   sQ   [128][36] @ 6912    (4608)  -- init only, then overlaid by sP
//   sP   [8][16][72] @ 6912  (9216)  -- per-warp probs buffer
// total 16128 floats = 64512 bytes
// ---------------------------------------------------------------------------
#define ATTN_SMEM_BYTES 64512

__global__ __launch_bounds__(256) void attn_mma_kernel(const float* __restrict__ qkv,
                                                       float* __restrict__ ctx) {
    extern __shared__ float sm[];
    float* sKhi = sm;
    float* sKlo = sm + 2304;
    float* sV   = sm + 4608;
    float* sQ   = sm + 6912;

    int t    = threadIdx.x;
    int wid  = t >> 5, lane = t & 31;
    int g    = lane >> 2;          // row group 0..7
    int tq   = lane & 3;           // thread-in-group 0..3
    int qw   = wid * 16;           // warp's query offset within CTA tile
    float* sP = sm + 6912 + wid * (16 * 72);

    int bh = blockIdx.y;
    int b = bh >> 3, h = bh & 7;
    int q0 = blockIdx.x * 128;
    const float* base = qkv + (size_t)b * (3 * CC * NPIX);
    const float* qp = base + (h * HDIM) * NPIX;
    const float* kp = base + (CC + h * HDIM) * NPIX;
    const float* vp = base + (2 * CC + h * HDIM) * NPIX;
    const float scale = 0.17677669529663687f;  // 1/sqrt(32)

    // --- transpose Q tile [32d][128q] -> sQ[q][d], scaled ---
    for (int i = t; i < 1024; i += 256) {      // 1024 float4 reads
        int d  = i >> 5;
        int q4 = (i & 31) * 4;
        float4 v = *(const float4*)&qp[(size_t)d * NPIX + q0 + q4];
        sQ[(q4 + 0) * 36 + d] = v.x * scale;
        sQ[(q4 + 1) * 36 + d] = v.y * scale;
        sQ[(q4 + 2) * 36 + d] = v.z * scale;
        sQ[(q4 + 3) * 36 + d] = v.w * scale;
    }
    __syncthreads();

    // --- extract Q fragments (hi/lo split), 4 k-chunks ---
    uint32_t qhi[4][4], qlo[4][4];
#pragma unroll
    for (int kc = 0; kc < 4; kc++) {
#pragma unroll
        for (int r = 0; r < 4; r++) {
            int row = qw + ((r & 1) ? g + 8 : g);
            int col = 8 * kc + tq + ((r >> 1) ? 4 : 0);
            float v  = sQ[row * 36 + col];
            float hi = to_tf32(v);
            qhi[kc][r] = __float_as_uint(hi);
            qlo[kc][r] = to_tf32_u(v - hi);
        }
    }

    float mrow[2] = {-1e30f, -1e30f};
    float lrow[2] = {0.f, 0.f};
    float oacc[4][4] = {};   // 4 d-tiles x (c0..c3)

    for (int k0 = 0; k0 < NPIX; k0 += 64) {
        __syncthreads();   // prior tile's MMAs done; safe to overwrite K/V (and sQ->sP)
        // --- load K tile (hi/lo split) and V tile (tf32) : 32 x 64 each ---
        for (int i = t; i < 512; i += 256) {
            int d  = i >> 4;
            int c4 = (i & 15) * 4;
            float4 v = *(const float4*)&kp[(size_t)d * NPIX + k0 + c4];
            float4 hi, lo;
            hi.x = to_tf32(v.x); lo.x = to_tf32(v.x - hi.x);
            hi.y = to_tf32(v.y); lo.y = to_tf32(v.y - hi.y);
            hi.z = to_tf32(v.z); lo.z = to_tf32(v.z - hi.z);
            hi.w = to_tf32(v.w); lo.w = to_tf32(v.w - hi.w);
            *(float4*)&sKhi[d * 72 + c4] = hi;
            *(float4*)&sKlo[d * 72 + c4] = lo;
            float4 vv = *(const float4*)&vp[(size_t)d * NPIX + k0 + c4];
            vv.x = to_tf32(vv.x); vv.y = to_tf32(vv.y);
            vv.z = to_tf32(vv.z); vv.w = to_tf32(vv.w);
            *(float4*)&sV[d * 72 + c4] = vv;
        }
        __syncthreads();

        // --- QK: scores for 8 n8 tiles (64 keys) ---
        float sv[8][4];
#pragma unroll
        for (int nt = 0; nt < 8; nt++) {
            float acc[4] = {0.f, 0.f, 0.f, 0.f};
#pragma unroll
            for (int kc = 0; kc < 4; kc++) {
                int i0 = (8 * kc + tq) * 72 + 8 * nt + g;
                int i1 = (8 * kc + tq + 4) * 72 + 8 * nt + g;
                uint32_t bh2[2] = {__float_as_uint(sKhi[i0]), __float_as_uint(sKhi[i1])};
                uint32_t bl2[2] = {__float_as_uint(sKlo[i0]), __float_as_uint(sKlo[i1])};
                mma_tf32(acc, qhi[kc], bh2);
                mma_tf32(acc, qlo[kc], bh2);
                mma_tf32(acc, qhi[kc], bl2);
            }
            sv[nt][0] = acc[0]; sv[nt][1] = acc[1];
            sv[nt][2] = acc[2]; sv[nt][3] = acc[3];
        }

        // --- online softmax update ---
        float tm0 = -1e30f, tm1 = -1e30f;
#pragma unroll
        for (int nt = 0; nt < 8; nt++) {
            tm0 = fmaxf(tm0, fmaxf(sv[nt][0], sv[nt][1]));
            tm1 = fmaxf(tm1, fmaxf(sv[nt][2], sv[nt][3]));
        }
        tm0 = fmaxf(tm0, __shfl_xor_sync(0xffffffffu, tm0, 1));
        tm0 = fmaxf(tm0, __shfl_xor_sync(0xffffffffu, tm0, 2));
        tm1 = fmaxf(tm1, __shfl_xor_sync(0xffffffffu, tm1, 1));
        tm1 = fmaxf(tm1, __shfl_xor_sync(0xffffffffu, tm1, 2));
        float m0n = fmaxf(mrow[0], tm0);
        float m1n = fmaxf(mrow[1], tm1);
        float c0 = __expf(mrow[0] - m0n);
        float c1 = __expf(mrow[1] - m1n);
        mrow[0] = m0n; mrow[1] = m1n;
        lrow[0] *= c0; lrow[1] *= c1;
#pragma unroll
        for (int dt = 0; dt < 4; dt++) {
            oacc[dt][0] *= c0; oacc[dt][1] *= c0;
            oacc[dt][2] *= c1; oacc[dt][3] *= c1;
        }
        // probs -> sP (tf32-rounded) + l accumulation
#pragma unroll
        for (int nt = 0; nt < 8; nt++) {
            float p0 = __expf(sv[nt][0] - m0n);
            float p1 = __expf(sv[nt][1] - m0n);
            float p2 = __expf(sv[nt][2] - m1n);
            float p3 = __expf(sv[nt][3] - m1n);
            lrow[0] += p0 + p1;
            lrow[1] += p2 + p3;
            *(float2*)&sP[g * 72 + 8 * nt + 2 * tq] =
                make_float2(to_tf32(p0), to_tf32(p1));
            *(float2*)&sP[(g + 8) * 72 + 8 * nt + 2 * tq] =
                make_float2(to_tf32(p2), to_tf32(p3));
        }
        __syncwarp();

        // --- PV: accumulate ctx ---
#pragma unroll
        for (int kc = 0; kc < 8; kc++) {
            uint32_t a[4];
            a[0] = __float_as_uint(sP[g * 72 + 8 * kc + tq]);
            a[1] = __float_as_uint(sP[(g + 8) * 72 + 8 * kc + tq]);
            a[2] = __float_as_uint(sP[g * 72 + 8 * kc + tq + 4]);
            a[3] = __float_as_uint(sP[(g + 8) * 72 + 8 * kc + tq + 4]);
#pragma unroll
            for (int dt = 0; dt < 4; dt++) {
                uint32_t bb[2];
                bb[0] = __float_as_uint(sV[(8 * dt + g) * 72 + 8 * kc + tq]);
                bb[1] = __float_as_uint(sV[(8 * dt + g) * 72 + 8 * kc + tq + 4]);
                mma_tf32(oacc[dt], a, bb);
            }
        }
        __syncwarp();
    }

    // --- finalize: l reduce over quad, normalize, write ctx [d][n] ---
    lrow[0] += __shfl_xor_sync(0xffffffffu, lrow[0], 1);
    lrow[0] += __shfl_xor_sync(0xffffffffu, lrow[0], 2);
    lrow[1] += __shfl_xor_sync(0xffffffffu, lrow[1], 1);
    lrow[1] += __shfl_xor_sync(0xffffffffu, lrow[1], 2);
    float inv0 = 1.f / lrow[0];
    float inv1 = 1.f / lrow[1];
    float* cp = ctx + (size_t)b * (CC * NPIX) + (size_t)(h * HDIM) * NPIX;
    int qr0 = q0 + qw + g;
    int qr1 = qr0 + 8;
#pragma unroll
    for (int dt = 0; dt < 4; dt++) {
        int d0 = 8 * dt + 2 * tq;
        cp[(size_t)d0 * NPIX + qr0]       = oacc[dt][0] * inv0;
        cp[(size_t)(d0 + 1) * NPIX + qr0] = oacc[dt][1] * inv0;
        cp[(size_t)d0 * NPIX + qr1]       = oacc[dt][2] * inv1;
        cp[(size_t)(d0 + 1) * NPIX + qr1] = oacc[dt][3] * inv1;
    }
}

// ---------------------------------------------------------------------------
// Conv via tf32 mma.sync implicit GEMM (unchanged from R4 - passing).
// ---------------------------------------------------------------------------
#define PATCH_CSTRIDE 456
#define A_STRIDE 136
#define A_BUF (16 * A_STRIDE)

__global__ __launch_bounds__(256) void conv_mma_kernel(const float* __restrict__ in) {
    __shared__ float sP[16 * PATCH_CSTRIDE];
    __shared__ float sA[2 * A_BUF];

    int z = blockIdx.z;
    int ks, tap0, tap1, slot, wtoff, b;
    if (z < 32) {
        int s = z >> 3; b = z & 7;
        ks = 7; tap0 = (s * 49) >> 2; tap1 = ((s + 1) * 49) >> 2;
        slot = 4 + s; wtoff = WT_OFF7;
    } else if (z < 48) {
        int s = (z - 32) >> 3; b = z & 7;
        ks = 5; tap0 = (s * 25) >> 1; tap1 = ((s + 1) * 25) >> 1;
        slot = 2 + s; wtoff = WT_OFF5;
    } else if (z < 56) {
        b = z - 48; ks = 3; tap0 = 0; tap1 = 9; slot = 1; wtoff = WT_OFF3;
    } else {
        b = z - 56; ks = 1; tap0 = 0; tap1 = 1; slot = 0; wtoff = WT_OFF1;
    }
    const int P = ks >> 1;
    const int rows = 8 + 2 * P;

    int n0 = blockIdx.x * 256;
    int m0 = blockIdx.y * 128;
    int r0 = n0 >> 5;
    int tid = threadIdx.x;
    int wid = tid >> 5, lane = tid & 31;
    int mw = (wid >> 2) * 64;
    int nw = (wid & 3) * 64;
    int lg = lane >> 2;
    int lk = lane & 3;

    int yj[8], xj[8];
#pragma unroll
    for (int j = 0; j < 8; j++) {
        int n = nw + 8 * j + lg;
        yj[j] = n >> 5;
        xj[j] = n & 31;
    }

    const float* inb = in + (size_t)b * (CC * NPIX);
    float acc[4][8][4] = {};

    for (int c0 = 0; c0 < 256; c0 += 16) {
        __syncthreads();
        {
            int total = 16 * rows * 8;
            int per_row = rows * 8;
            for (int i = tid; i < total; i += 256) {
                int c  = i / per_row;
                int rm = i - c * per_row;
                int py = rm >> 3;
                int xq = (rm & 7) * 4;
                int iy = r0 - P + py;
                float4 v = make_float4(0.f, 0.f, 0.f, 0.f);
                if ((unsigned)iy < 32u)
                    v = *(const float4*)&inb[(size_t)(c0 + c) * NPIX + iy * 32 + xq];
                v.x = to_tf32(v.x); v.y = to_tf32(v.y);
                v.z = to_tf32(v.z); v.w = to_tf32(v.w);
                *(float4*)&sP[c * PATCH_CSTRIDE + py * 32 + xq] = v;
            }
        }
        {
            const float* wt = g_wT + (size_t)wtoff + (size_t)tap0 * (CC * CC);
            for (int i = tid; i < 512; i += 256) {
                int k = i >> 5, col = (i & 31) * 4;
                *(float4*)&sA[k * A_STRIDE + col] =
                    *(const float4*)&wt[(size_t)(c0 + k) * CC + m0 + col];
            }
        }
        __syncthreads();

        int buf = 0;
        for (int tap = tap0; tap < tap1; tap++) {
            if (tap + 1 < tap1) {
                const float* wt = g_wT + (size_t)wtoff + (size_t)(tap + 1) * (CC * CC);
                float* dst = sA + (buf ^ 1) * A_BUF;
                for (int i = tid; i < 512; i += 256) {
                    int k = i >> 5, col = (i & 31) * 4;
                    *(float4*)&dst[k * A_STRIDE + col] =
                        *(const float4*)&wt[(size_t)(c0 + k) * CC + m0 + col];
                }
            }
            int ty = tap / ks;
            int tx = tap - ty * ks;
            const uint32_t* A = (const uint32_t*)(sA + buf * A_BUF);
            const uint32_t* Pp = (const uint32_t*)sP;
#pragma unroll
            for (int s = 0; s < 2; s++) {
                int k = s * 8 + lk;
                uint32_t a[4][4];
#pragma unroll
                for (int t = 0; t < 4; t++) {
                    int m = mw + 16 * t + lg;
                    a[t][0] = A[k * A_STRIDE + m];
                    a[t][1] = A[k * A_STRIDE + m + 8];
                    a[t][2] = A[(k + 4) * A_STRIDE + m];
                    a[t][3] = A[(k + 4) * A_STRIDE + m + 8];
                }
                uint32_t bb[8][2];
#pragma unroll
                for (int j = 0; j < 8; j++) {
                    int py = yj[j] + ty;
                    int ix = xj[j] + tx - P;
                    bool ok = (unsigned)ix < 32u;
                    int off = py * 32 + ix;
                    bb[j][0] = ok ? Pp[k * PATCH_CSTRIDE + off] : 0u;
                    bb[j][1] = ok ? Pp[(k + 4) * PATCH_CSTRIDE + off] : 0u;
                }
#pragma unroll
                for (int t = 0; t < 4; t++)
#pragma unroll
                    for (int j = 0; j < 8; j++) mma_tf32(acc[t][j], a[t], bb[j]);
            }
            __syncthreads();
            buf ^= 1;
        }
    }

    float* pp = g_part + (size_t)slot * (BATCH * CC * NPIX) + (size_t)b * (CC * NPIX);
#pragma unroll
    for (int t = 0; t < 4; t++) {
        int o = m0 + mw + 16 * t + lg;
#pragma unroll
        for (int j = 0; j < 8; j++) {
            int n = n0 + nw + 8 * j + 2 * lk;
            *(float2*)&pp[(size_t)o * NPIX + n] =
                make_float2(acc[t][j][0], acc[t][j][1]);
            *(float2*)&pp[(size_t)(o + 8) * NPIX + n] =
                make_float2(acc[t][j][2], acc[t][j][3]);
        }
    }
}

// ---------------------------------------------------------------------------
// BN constants
// ---------------------------------------------------------------------------
__global__ void bnprep_kernel(const float* __restrict__ conv_b,
                              const float* __restrict__ gamma,
                              const float* __restrict__ beta,
                              const float* __restrict__ mean,
                              const float* __restrict__ var) {
    int i = threadIdx.x;
    float inv = gamma[i] * rsqrtf(var[i] + 1e-5f);
    g_bnA[i] = inv;
    g_bnB[i] = beta[i] - mean[i] * inv + conv_b[i] * inv;
}

// ---------------------------------------------------------------------------
// Epilogue: sum split-K partials, BN + ReLU -> feats
// ---------------------------------------------------------------------------
__global__ __launch_bounds__(256) void epi_kernel(float* __restrict__ feats) {
    int row = blockIdx.x;
    int k   = row >> 11;
    int bc  = row & 2047;
    int o   = bc & 255;
    float Aa = g_bnA[k * 256 + o];
    float Bb = g_bnB[k * 256 + o];
    size_t base = (size_t)bc * NPIX + threadIdx.x * 4;
    const size_t SL = (size_t)BATCH * CC * NPIX;
    float4 s;
    if (k == 0) {
        s = *(const float4*)&g_part[base];
    } else if (k == 1) {
        s = *(const float4*)&g_part[SL + base];
    } else if (k == 2) {
        float4 s0 = *(const float4*)&g_part[2 * SL + base];
        float4 s1 = *(const float4*)&g_part[3 * SL + base];
        s = make_float4(s0.x + s1.x, s0.y + s1.y, s0.z + s1.z, s0.w + s1.w);
    } else {
        float4 s0 = *(const float4*)&g_part[4 * SL + base];
        float4 s1 = *(const float4*)&g_part[5 * SL + base];
        float4 s2 = *(const float4*)&g_part[6 * SL + base];
        float4 s3 = *(const float4*)&g_part[7 * SL + base];
        s = make_float4(s0.x + s1.x + s2.x + s3.x, s0.y + s1.y + s2.y + s3.y,
                        s0.z + s1.z + s2.z + s3.z, s0.w + s1.w + s2.w + s3.w);
    }
    float4 v;
    v.x = fmaxf(s.x * Aa + Bb, 0.f);
    v.y = fmaxf(s.y * Aa + Bb, 0.f);
    v.z = fmaxf(s.z * Aa + Bb, 0.f);
    v.w = fmaxf(s.w * Aa + Bb, 0.f);
    *(float4*)&feats[(size_t)k * SL + base] = v;
}

// ---------------------------------------------------------------------------
// S[b,c] = mean over pixels of sum-over-branches of feats
// ---------------------------------------------------------------------------
__global__ __launch_bounds__(128) void sreduce_kernel(float* __restrict__ S) {
    int bc = blockIdx.x;
    int t  = threadIdx.x;
    float s = 0.f;
#pragma unroll
    for (int k = 0; k < 4; k++) {
        const float* p = g_feats + ((size_t)k * (BATCH * CC) + bc) * NPIX;
        for (int n = t; n < NPIX; n += 128) s += p[n];
    }
#pragma unroll
    for (int off = 16; off; off >>= 1) s += __shfl_down_sync(0xffffffffu, s, off);
    __shared__ float red[4];
    if ((t & 31) == 0) red[t >> 5] = s;
    __syncthreads();
    if (t == 0) S[bc] = (red[0] + red[1] + red[2] + red[3]) * (1.f / 1024.f);
}

// ---------------------------------------------------------------------------
// fc -> per-branch logits -> softmax over branches
// ---------------------------------------------------------------------------
__global__ __launch_bounds__(256) void select_kernel(
    const float* __restrict__ S, const float* __restrict__ fc_w,
    const float* __restrict__ fc_b, const float* __restrict__ fcs_w,
    const float* __restrict__ fcs_b, float* __restrict__ attnw) {
    __shared__ float Ss[BATCH * CC];
    __shared__ float Zs[BATCH * DDIM];
    int t = threadIdx.x;
    for (int i = t; i < BATCH * CC; i += 256) Ss[i] = S[i];
    __syncthreads();
    {
        int b = t >> 5, d = t & 31;
        float z = fc_b[d];
        const float* wr = fc_w + d * CC;
        for (int c = 0; c < CC; c++) z += Ss[b * CC + c] * wr[c];
        Zs[b * DDIM + d] = z;
    }
    __syncthreads();
    for (int it = 0; it < 8; it++) {
        int idx = it * 256 + t;
        int b = idx >> 8, c = idx & 255;
        float lg[4];
#pragma unroll
        for (int k = 0; k < 4; k++) {
            float v = fcs_b[k * CC + c];
            const float* wp = fcs_w + ((size_t)k * CC + c) * DDIM;
#pragma unroll
            for (int d = 0; d < DDIM; d++) v += wp[d] * Zs[b * DDIM + d];
            lg[k] = v;
        }
        float mx  = fmaxf(fmaxf(lg[0], lg[1]), fmaxf(lg[2], lg[3]));
        float e0 = __expf(lg[0] - mx), e1 = __expf(lg[1] - mx);
        float e2 = __expf(lg[2] - mx), e3 = __expf(lg[3] - mx);
        float inv = 1.f / (e0 + e1 + e2 + e3);
        attnw[0 * 2048 + idx] = e0 * inv;
        attnw[1 * 2048 + idx] = e1 * inv;
        attnw[2 * 2048 + idx] = e2 * inv;
        attnw[3 * 2048 + idx] = e3 * inv;
    }
}

// ---------------------------------------------------------------------------
// V = sum_k attn[k,b,c] * feats[k,b,c,:]
// ---------------------------------------------------------------------------
__global__ __launch_bounds__(256) void combine_kernel(const float* __restrict__ attnw,
                                                      float* __restrict__ out) {
    int idx = blockIdx.x * 256 + threadIdx.x;
    if (idx >= BATCH * CC * NPIX) return;
    int bc = idx >> 10;
    const size_t KSTRIDE = (size_t)BATCH * CC * NPIX;
    float v = attnw[bc]        * g_feats[idx] +
              attnw[2048 + bc] * g_feats[KSTRIDE + idx] +
              attnw[4096 + bc] * g_feats[2 * KSTRIDE + idx] +
              attnw[6144 + bc] * g_feats[3 * KSTRIDE + idx];
    out[idx] = v;
}

// ---------------------------------------------------------------------------
// Launch
// ---------------------------------------------------------------------------
extern "C" void kernel_launch(void* const* d_in, const int* in_sizes, int n_in,
                              void* d_out, int out_size) {
    const float* x      = (const float*)d_in[0];
    const float* qkv_w  = (const float*)d_in[1];
    const float* out_w  = (const float*)d_in[2];
    const float* w1     = (const float*)d_in[3];
    const float* w3     = (const float*)d_in[4];
    const float* w5     = (const float*)d_in[5];
    const float* w7     = (const float*)d_in[6];
    const float* conv_b = (const float*)d_in[7];
    const float* gamma  = (const float*)d_in[8];
    const float* beta   = (const float*)d_in[9];
    const float* mean   = (const float*)d_in[10];
    const float* var    = (const float*)d_in[11];
    const float* fc_w   = (const float*)d_in[12];
    const float* fc_b   = (const float*)d_in[13];
    const float* fcs_w  = (const float*)d_in[14];
    const float* fcs_b  = (const float*)d_in[15];
    float* out = (float*)d_out;

    float *p_qkv, *p_ctx, *p_ao, *p_feats, *p_S, *p_attnw;
    cudaGetSymbolAddress((void**)&p_qkv,   g_qkv);
    cudaGetSymbolAddress((void**)&p_ctx,   g_ctx);
    cudaGetSymbolAddress((void**)&p_ao,    g_ao);
    cudaGetSymbolAddress((void**)&p_feats, g_feats);
    cudaGetSymbolAddress((void**)&p_S,     g_S);
    cudaGetSymbolAddress((void**)&p_attnw, g_attnw);

    static int attn_attr_set = 0;
    if (!attn_attr_set) {
        cudaFuncSetAttribute(attn_mma_kernel,
                             cudaFuncAttributeMaxDynamicSharedMemorySize,
                             ATTN_SMEM_BYTES);
        attn_attr_set = 1;
    }

    wtrans_kernel<<<21504, 256>>>(w1, w3, w5, w7);
    bnprep_kernel<<<1, 1024>>>(conv_b, gamma, beta, mean, var);
    sgemm_kernel<<<dim3(16, 12, 8), 256>>>(qkv_w, x, p_qkv, 3 * CC, CC);
    attn_mma_kernel<<<dim3(8, 64), 256, ATTN_SMEM_BYTES>>>(p_qkv, p_ctx);
    sgemm_kernel<<<dim3(16, 4, 8), 256>>>(out_w, p_ctx, p_ao, CC, CC);

    conv_mma_kernel<<<dim3(4, 2, 64), 256>>>(p_ao);
    epi_kernel<<<4 * 2048, 256>>>(p_feats);

    sreduce_kernel<<<2048, 128>>>(p_S);
    select_kernel<<<1, 256>>>(p_S, fc_w, fc_b, fcs_w, fcs_b, p_attnw);
    combine_kernel<<<8192, 256>>>(p_attnw, out);
}

// round 6
// speedup vs baseline: 3.3310x; 1.3031x over previous
#include <cuda_runtime.h>
#include <math_constants.h>
#include <cstdint>

// ---------------------------------------------------------------------------
// Problem constants: x [8, 256, 32, 32], C=256 HEADS=8 HD=32 N=1024 D=32
// ---------------------------------------------------------------------------
#define BATCH 8
#define CC 256
#define NPIX 1024
#define NHEAD 8
#define HDIM 32
#define DDIM 32

// Scratch (device globals: allocation-free, graph-capture safe)
__device__ float g_qkv[BATCH * 3 * CC * NPIX];
__device__ float g_ctx[BATCH * CC * NPIX];
__device__ float g_ao[BATCH * CC * NPIX];
__device__ float g_feats[4 * BATCH * CC * NPIX];
__device__ float g_wT[5505024];                   // conv weights [tap][c][o], tf32
__device__ float g_part[8 * BATCH * CC * NPIX];   // split-K conv partials
__device__ float g_bnA[4 * CC];
__device__ float g_bnB[4 * CC];
__device__ float g_S[BATCH * CC];
__device__ float g_attnw[4 * BATCH * CC];
// Projection weights: transposed [k][m], hi/lo tf32 split
__device__ float g_qkvw_hi[768 * 256];
__device__ float g_qkvw_lo[768 * 256];
__device__ float g_outw_hi[256 * 256];
__device__ float g_outw_lo[256 * 256];

#define WT_OFF1 0
#define WT_OFF3 65536
#define WT_OFF5 655360
#define WT_OFF7 2293760

__device__ __forceinline__ float to_tf32(float x) {
    uint32_t y;
    asm("cvt.rna.tf32.f32 %0, %1;" : "=r"(y) : "f"(x));
    return __uint_as_float(y);
}
__device__ __forceinline__ uint32_t to_tf32_u(float x) {
    uint32_t y;
    asm("cvt.rna.tf32.f32 %0, %1;" : "=r"(y) : "f"(x));
    return y;
}

__device__ __forceinline__ void mma_tf32(float* d, const uint32_t* a, const uint32_t* b) {
    asm volatile(
        "mma.sync.aligned.m16n8k8.row.col.f32.tf32.tf32.f32 "
        "{%0,%1,%2,%3}, {%4,%5,%6,%7}, {%8,%9}, {%0,%1,%2,%3};"
        : "+f"(d[0]), "+f"(d[1]), "+f"(d[2]), "+f"(d[3])
        : "r"(a[0]), "r"(a[1]), "r"(a[2]), "r"(a[3]), "r"(b[0]), "r"(b[1]));
}

// ---------------------------------------------------------------------------
// Repack conv weights OIHW -> [tap][c][o], tf32-rounded
// ---------------------------------------------------------------------------
__global__ void wtrans_kernel(const float* __restrict__ w1, const float* __restrict__ w3,
                              const float* __restrict__ w5, const float* __restrict__ w7) {
    int idx = blockIdx.x * 256 + threadIdx.x;
    if (idx >= 5505024) return;
    const float* src;
    int k2, base;
    if (idx < 655360)       { if (idx < 65536) { src = w1; k2 = 1;  base = 0; }
                              else             { src = w3; k2 = 9;  base = 65536; } }
    else if (idx < 2293760) { src = w5; k2 = 25; base = 655360; }
    else                    { src = w7; k2 = 49; base = 2293760; }
    int r   = idx - base;
    int o   = r & 255;
    int c   = (r >> 8) & 255;
    int tap = r >> 16;
    g_wT[idx] = to_tf32(src[(o * 256 + c) * k2 + tap]);
}

// ---------------------------------------------------------------------------
// Split + transpose projection weights: W[m][k] -> WT_hi/lo[k][m]
// ---------------------------------------------------------------------------
__global__ void wsplit_kernel(const float* __restrict__ qkv_w,
                              const float* __restrict__ out_w) {
    int idx = blockIdx.x * 256 + threadIdx.x;  // 262144 total
    if (idx < 196608) {
        int m = idx / 256, k = idx & 255;
        float v  = qkv_w[idx];
        float hi = to_tf32(v);
        g_qkvw_hi[k * 768 + m] = hi;
        g_qkvw_lo[k * 768 + m] = to_tf32(v - hi);
    } else {
        int r = idx - 196608;
        int m = r / 256, k = r & 255;
        float v  = out_w[r];
        float hi = to_tf32(v);
        g_outw_hi[k * 256 + m] = hi;
        g_outw_lo[k * 256 + m] = to_tf32(v - hi);
    }
}

// ---------------------------------------------------------------------------
// GEMM via tf32 mma with 3-mma hi/lo split (fp32-accurate).
// D[b] = W[M,256] @ X[b][256,1024]. CTA: M=64 x N=256, 8 warps (2m x 4n),
// warp tile 32x64. W pre-split/transposed; X split on fragment extraction.
// ---------------------------------------------------------------------------
#define GW_STRIDE 72
#define GX_STRIDE 264

__global__ __launch_bounds__(256) void gemm_mma_kernel(
    const float* __restrict__ WhiT, const float* __restrict__ WloT,
    const float* __restrict__ X, float* __restrict__ D, int M) {
    __shared__ float sWhi[16 * GW_STRIDE];
    __shared__ float sWlo[16 * GW_STRIDE];
    __shared__ float sX[16 * GX_STRIDE];
    int tid = threadIdx.x;
    int n0 = blockIdx.x * 256, m0 = blockIdx.y * 64, b = blockIdx.z;
    const float* Xb = X + (size_t)b * 256 * NPIX;
    float*       Db = D + (size_t)b * M * NPIX;
    int wid = tid >> 5, lane = tid & 31;
    int g = lane >> 2, tq = lane & 3;
    int mw = (wid >> 2) * 32;
    int nw = (wid & 3) * 64;
    float acc[2][8][4] = {};
    for (int k0 = 0; k0 < 256; k0 += 16) {
        __syncthreads();
        {
            int k = tid >> 4, col = (tid & 15) * 4;
            *(float4*)&sWhi[k * GW_STRIDE + col] =
                *(const float4*)&WhiT[(size_t)(k0 + k) * M + m0 + col];
            *(float4*)&sWlo[k * GW_STRIDE + col] =
                *(const float4*)&WloT[(size_t)(k0 + k) * M + m0 + col];
        }
        for (int i = tid; i < 1024; i += 256) {
            int k = i >> 6, c4 = (i & 63) * 4;
            *(float4*)&sX[k * GX_STRIDE + c4] =
                *(const float4*)&Xb[(size_t)(k0 + k) * NPIX + n0 + c4];
        }
        __syncthreads();
#pragma unroll
        for (int s = 0; s < 2; s++) {
            int k = 8 * s + tq;
            uint32_t ahi[2][4], alo[2][4];
#pragma unroll
            for (int t = 0; t < 2; t++) {
                int m = mw + 16 * t + g;
                ahi[t][0] = __float_as_uint(sWhi[k * GW_STRIDE + m]);
                ahi[t][1] = __float_as_uint(sWhi[k * GW_STRIDE + m + 8]);
                ahi[t][2] = __float_as_uint(sWhi[(k + 4) * GW_STRIDE + m]);
                ahi[t][3] = __float_as_uint(sWhi[(k + 4) * GW_STRIDE + m + 8]);
                alo[t][0] = __float_as_uint(sWlo[k * GW_STRIDE + m]);
                alo[t][1] = __float_as_uint(sWlo[k * GW_STRIDE + m + 8]);
                alo[t][2] = __float_as_uint(sWlo[(k + 4) * GW_STRIDE + m]);
                alo[t][3] = __float_as_uint(sWlo[(k + 4) * GW_STRIDE + m + 8]);
            }
#pragma unroll
            for (int j = 0; j < 8; j++) {
                float v0 = sX[k * GX_STRIDE + nw + 8 * j + g];
                float v1 = sX[(k + 4) * GX_STRIDE + nw + 8 * j + g];
                float h0 = to_tf32(v0), h1 = to_tf32(v1);
                uint32_t bhi[2] = {__float_as_uint(h0), __float_as_uint(h1)};
                uint32_t blo[2] = {to_tf32_u(v0 - h0), to_tf32_u(v1 - h1)};
#pragma unroll
                for (int t = 0; t < 2; t++) {
                    mma_tf32(acc[t][j], ahi[t], bhi);
                    mma_tf32(acc[t][j], alo[t], bhi);
                    mma_tf32(acc[t][j], ahi[t], blo);
                }
            }
        }
    }
#pragma unroll
    for (int t = 0; t < 2; t++) {
        int o = m0 + mw + 16 * t + g;
#pragma unroll
        for (int j = 0; j < 8; j++) {
            int n = n0 + nw + 8 * j + 2 * tq;
            *(float2*)&Db[(size_t)o * NPIX + n] =
                make_float2(acc[t][j][0], acc[t][j][1]);
            *(float2*)&Db[(size_t)(o + 8) * NPIX + n] =
                make_float2(acc[t][j][2], acc[t][j][3]);
        }
    }
}

// ---------------------------------------------------------------------------
// Attention via tf32 mma.sync, flash-style online softmax (unchanged, passing)
// ---------------------------------------------------------------------------
#define ATTN_SMEM_BYTES 64512

__global__ __launch_bounds__(256) void attn_mma_kernel(const float* __restrict__ qkv,
                                                       float* __restrict__ ctx) {
    extern __shared__ float sm[];
    float* sKhi = sm;
    float* sKlo = sm + 2304;
    float* sV   = sm + 4608;
    float* sQ   = sm + 6912;

    int t    = threadIdx.x;
    int wid  = t >> 5, lane = t & 31;
    int g    = lane >> 2;
    int tq   = lane & 3;
    int qw   = wid * 16;
    float* sP = sm + 6912 + wid * (16 * 72);

    int bh = blockIdx.y;
    int b = bh >> 3, h = bh & 7;
    int q0 = blockIdx.x * 128;
    const float* base = qkv + (size_t)b * (3 * CC * NPIX);
    const float* qp = base + (h * HDIM) * NPIX;
    const float* kp = base + (CC + h * HDIM) * NPIX;
    const float* vp = base + (2 * CC + h * HDIM) * NPIX;
    const float scale = 0.17677669529663687f;

    for (int i = t; i < 1024; i += 256) {
        int d  = i >> 5;
        int q4 = (i & 31) * 4;
        float4 v = *(const float4*)&qp[(size_t)d * NPIX + q0 + q4];
        sQ[(q4 + 0) * 36 + d] = v.x * scale;
        sQ[(q4 + 1) * 36 + d] = v.y * scale;
        sQ[(q4 + 2) * 36 + d] = v.z * scale;
        sQ[(q4 + 3) * 36 + d] = v.w * scale;
    }
    __syncthreads();

    uint32_t qhi[4][4], qlo[4][4];
#pragma unroll
    for (int kc = 0; kc < 4; kc++) {
#pragma unroll
        for (int r = 0; r < 4; r++) {
            int row = qw + ((r & 1) ? g + 8 : g);
            int col = 8 * kc + tq + ((r >> 1) ? 4 : 0);
            float v  = sQ[row * 36 + col];
            float hi = to_tf32(v);
            qhi[kc][r] = __float_as_uint(hi);
            qlo[kc][r] = to_tf32_u(v - hi);
        }
    }

    float mrow[2] = {-1e30f, -1e30f};
    float lrow[2] = {0.f, 0.f};
    float oacc[4][4] = {};

    for (int k0 = 0; k0 < NPIX; k0 += 64) {
        __syncthreads();
        for (int i = t; i < 512; i += 256) {
            int d  = i >> 4;
            int c4 = (i & 15) * 4;
            float4 v = *(const float4*)&kp[(size_t)d * NPIX + k0 + c4];
            float4 hi, lo;
            hi.x = to_tf32(v.x); lo.x = to_tf32(v.x - hi.x);
            hi.y = to_tf32(v.y); lo.y = to_tf32(v.y - hi.y);
            hi.z = to_tf32(v.z); lo.z = to_tf32(v.z - hi.z);
            hi.w = to_tf32(v.w); lo.w = to_tf32(v.w - hi.w);
            *(float4*)&sKhi[d * 72 + c4] = hi;
            *(float4*)&sKlo[d * 72 + c4] = lo;
            float4 vv = *(const float4*)&vp[(size_t)d * NPIX + k0 + c4];
            vv.x = to_tf32(vv.x); vv.y = to_tf32(vv.y);
            vv.z = to_tf32(vv.z); vv.w = to_tf32(vv.w);
            *(float4*)&sV[d * 72 + c4] = vv;
        }
        __syncthreads();

        float sv[8][4];
#pragma unroll
        for (int nt = 0; nt < 8; nt++) {
            float acc[4] = {0.f, 0.f, 0.f, 0.f};
#pragma unroll
            for (int kc = 0; kc < 4; kc++) {
                int i0 = (8 * kc + tq) * 72 + 8 * nt + g;
                int i1 = (8 * kc + tq + 4) * 72 + 8 * nt + g;
                uint32_t bh2[2] = {__float_as_uint(sKhi[i0]), __float_as_uint(sKhi[i1])};
                uint32_t bl2[2] = {__float_as_uint(sKlo[i0]), __float_as_uint(sKlo[i1])};
                mma_tf32(acc, qhi[kc], bh2);
                mma_tf32(acc, qlo[kc], bh2);
                mma_tf32(acc, qhi[kc], bl2);
            }
            sv[nt][0] = acc[0]; sv[nt][1] = acc[1];
            sv[nt][2] = acc[2]; sv[nt][3] = acc[3];
        }

        float tm0 = -1e30f, tm1 = -1e30f;
#pragma unroll
        for (int nt = 0; nt < 8; nt++) {
            tm0 = fmaxf(tm0, fmaxf(sv[nt][0], sv[nt][1]));
            tm1 = fmaxf(tm1, fmaxf(sv[nt][2], sv[nt][3]));
        }
        tm0 = fmaxf(tm0, __shfl_xor_sync(0xffffffffu, tm0, 1));
        tm0 = fmaxf(tm0, __shfl_xor_sync(0xffffffffu, tm0, 2));
        tm1 = fmaxf(tm1, __shfl_xor_sync(0xffffffffu, tm1, 1));
        tm1 = fmaxf(tm1, __shfl_xor_sync(0xffffffffu, tm1, 2));
        float m0n = fmaxf(mrow[0], tm0);
        float m1n = fmaxf(mrow[1], tm1);
        float c0 = __expf(mrow[0] - m0n);
        float c1 = __expf(mrow[1] - m1n);
        mrow[0] = m0n; mrow[1] = m1n;
        lrow[0] *= c0; lrow[1] *= c1;
#pragma unroll
        for (int dt = 0; dt < 4; dt++) {
            oacc[dt][0] *= c0; oacc[dt][1] *= c0;
            oacc[dt][2] *= c1; oacc[dt][3] *= c1;
        }
#pragma unroll
        for (int nt = 0; nt < 8; nt++) {
            float p0 = __expf(sv[nt][0] - m0n);
            float p1 = __expf(sv[nt][1] - m0n);
            float p2 = __expf(sv[nt][2] - m1n);
            float p3 = __expf(sv[nt][3] - m1n);
            lrow[0] += p0 + p1;
            lrow[1] += p2 + p3;
            *(float2*)&sP[g * 72 + 8 * nt + 2 * tq] =
                make_float2(to_tf32(p0), to_tf32(p1));
            *(float2*)&sP[(g + 8) * 72 + 8 * nt + 2 * tq] =
                make_float2(to_tf32(p2), to_tf32(p3));
        }
        __syncwarp();

#pragma unroll
        for (int kc = 0; kc < 8; kc++) {
            uint32_t a[4];
            a[0] = __float_as_uint(sP[g * 72 + 8 * kc + tq]);
            a[1] = __float_as_uint(sP[(g + 8) * 72 + 8 * kc + tq]);
            a[2] = __float_as_uint(sP[g * 72 + 8 * kc + tq + 4]);
            a[3] = __float_as_uint(sP[(g + 8) * 72 + 8 * kc + tq + 4]);
#pragma unroll
            for (int dt = 0; dt < 4; dt++) {
                uint32_t bb[2];
                bb[0] = __float_as_uint(sV[(8 * dt + g) * 72 + 8 * kc + tq]);
                bb[1] = __float_as_uint(sV[(8 * dt + g) * 72 + 8 * kc + tq + 4]);
                mma_tf32(oacc[dt], a, bb);
            }
        }
        __syncwarp();
    }

    lrow[0] += __shfl_xor_sync(0xffffffffu, lrow[0], 1);
    lrow[0] += __shfl_xor_sync(0xffffffffu, lrow[0], 2);
    lrow[1] += __shfl_xor_sync(0xffffffffu, lrow[1], 1);
    lrow[1] += __shfl_xor_sync(0xffffffffu, lrow[1], 2);
    float inv0 = 1.f / lrow[0];
    float inv1 = 1.f / lrow[1];
    float* cp = ctx + (size_t)b * (CC * NPIX) + (size_t)(h * HDIM) * NPIX;
    int qr0 = q0 + qw + g;
    int qr1 = qr0 + 8;
#pragma unroll
    for (int dt = 0; dt < 4; dt++) {
        int d0 = 8 * dt + 2 * tq;
        cp[(size_t)d0 * NPIX + qr0]       = oacc[dt][0] * inv0;
        cp[(size_t)(d0 + 1) * NPIX + qr0] = oacc[dt][1] * inv0;
        cp[(size_t)d0 * NPIX + qr1]       = oacc[dt][2] * inv1;
        cp[(size_t)(d0 + 1) * NPIX + qr1] = oacc[dt][3] * inv1;
    }
}

// ---------------------------------------------------------------------------
// Conv via tf32 mma.sync implicit GEMM. Re-tiled: CTA M=64 x N=256, 8 warps
// (2m x 4n), warp tile 32x64 -> 64 accum regs -> 2 CTAs/SM (latency hiding).
// ---------------------------------------------------------------------------
#define PATCH_CSTRIDE 456
#define A2_STRIDE 72
#define A2_BUF (16 * A2_STRIDE)

__global__ __launch_bounds__(256, 2) void conv_mma_kernel(const float* __restrict__ in) {
    __shared__ float sP[16 * PATCH_CSTRIDE];
    __shared__ float sA[2 * A2_BUF];

    int z = blockIdx.z;
    int ks, tap0, tap1, slot, wtoff, b;
    if (z < 32) {
        int s = z >> 3; b = z & 7;
        ks = 7; tap0 = (s * 49) >> 2; tap1 = ((s + 1) * 49) >> 2;
        slot = 4 + s; wtoff = WT_OFF7;
    } else if (z < 48) {
        int s = (z - 32) >> 3; b = z & 7;
        ks = 5; tap0 = (s * 25) >> 1; tap1 = ((s + 1) * 25) >> 1;
        slot = 2 + s; wtoff = WT_OFF5;
    } else if (z < 56) {
        b = z - 48; ks = 3; tap0 = 0; tap1 = 9; slot = 1; wtoff = WT_OFF3;
    } else {
        b = z - 56; ks = 1; tap0 = 0; tap1 = 1; slot = 0; wtoff = WT_OFF1;
    }
    const int P = ks >> 1;
    const int rows = 8 + 2 * P;

    int n0 = blockIdx.x * 256;
    int m0 = blockIdx.y * 64;
    int r0 = n0 >> 5;
    int tid = threadIdx.x;
    int wid = tid >> 5, lane = tid & 31;
    int mw = (wid >> 2) * 32;        // 0 / 32
    int nw = (wid & 3) * 64;
    int lg = lane >> 2;
    int lk = lane & 3;

    int yj[8], xj[8];
#pragma unroll
    for (int j = 0; j < 8; j++) {
        int n = nw + 8 * j + lg;
        yj[j] = n >> 5;
        xj[j] = n & 31;
    }

    const float* inb = in + (size_t)b * (CC * NPIX);
    float acc[2][8][4] = {};

    for (int c0 = 0; c0 < 256; c0 += 16) {
        __syncthreads();
        {
            int total = 16 * rows * 8;
            int per_row = rows * 8;
            for (int i = tid; i < total; i += 256) {
                int c  = i / per_row;
                int rm = i - c * per_row;
                int py = rm >> 3;
                int xq = (rm & 7) * 4;
                int iy = r0 - P + py;
                float4 v = make_float4(0.f, 0.f, 0.f, 0.f);
                if ((unsigned)iy < 32u)
                    v = *(const float4*)&inb[(size_t)(c0 + c) * NPIX + iy * 32 + xq];
                v.x = to_tf32(v.x); v.y = to_tf32(v.y);
                v.z = to_tf32(v.z); v.w = to_tf32(v.w);
                *(float4*)&sP[c * PATCH_CSTRIDE + py * 32 + xq] = v;
            }
        }
        {   // preload A(tap0): 16k x 64m = 256 float4, one per thread
            const float* wt = g_wT + (size_t)wtoff + (size_t)tap0 * (CC * CC);
            int k = tid >> 4, col = (tid & 15) * 4;
            *(float4*)&sA[k * A2_STRIDE + col] =
                *(const float4*)&wt[(size_t)(c0 + k) * CC + m0 + col];
        }
        __syncthreads();

        int buf = 0;
        for (int tap = tap0; tap < tap1; tap++) {
            if (tap + 1 < tap1) {
                const float* wt = g_wT + (size_t)wtoff + (size_t)(tap + 1) * (CC * CC);
                float* dst = sA + (buf ^ 1) * A2_BUF;
                int k = tid >> 4, col = (tid & 15) * 4;
                *(float4*)&dst[k * A2_STRIDE + col] =
                    *(const float4*)&wt[(size_t)(c0 + k) * CC + m0 + col];
            }
            int ty = tap / ks;
            int tx = tap - ty * ks;
            const uint32_t* A = (const uint32_t*)(sA + buf * A2_BUF);
            const uint32_t* Pp = (const uint32_t*)sP;
#pragma unroll
            for (int s = 0; s < 2; s++) {
                int k = s * 8 + lk;
                uint32_t a[2][4];
#pragma unroll
                for (int t = 0; t < 2; t++) {
                    int m = mw + 16 * t + lg;
                    a[t][0] = A[k * A2_STRIDE + m];
                    a[t][1] = A[k * A2_STRIDE + m + 8];
                    a[t][2] = A[(k + 4) * A2_STRIDE + m];
                    a[t][3] = A[(k + 4) * A2_STRIDE + m + 8];
                }
                uint32_t bb[8][2];
#pragma unroll
                for (int j = 0; j < 8; j++) {
                    int py = yj[j] + ty;
                    int ix = xj[j] + tx - P;
                    bool ok = (unsigned)ix < 32u;
                    int off = py * 32 + ix;
                    bb[j][0] = ok ? Pp[k * PATCH_CSTRIDE + off] : 0u;
                    bb[j][1] = ok ? Pp[(k + 4) * PATCH_CSTRIDE + off] : 0u;
                }
#pragma unroll
                for (int t = 0; t < 2; t++)
#pragma unroll
                    for (int j = 0; j < 8; j++) mma_tf32(acc[t][j], a[t], bb[j]);
            }
            __syncthreads();
            buf ^= 1;
        }
    }

    float* pp = g_part + (size_t)slot * (BATCH * CC * NPIX) + (size_t)b * (CC * NPIX);
#pragma unroll
    for (int t = 0; t < 2; t++) {
        int o = m0 + mw + 16 * t + lg;
#pragma unroll
        for (int j = 0; j < 8; j++) {
            int n = n0 + nw + 8 * j + 2 * lk;
            *(float2*)&pp[(size_t)o * NPIX + n] =
                make_float2(acc[t][j][0], acc[t][j][1]);
            *(float2*)&pp[(size_t)(o + 8) * NPIX + n] =
                make_float2(acc[t][j][2], acc[t][j][3]);
        }
    }
}

// ---------------------------------------------------------------------------
// BN constants
// ---------------------------------------------------------------------------
__global__ void bnprep_kernel(const float* __restrict__ conv_b,
                              const float* __restrict__ gamma,
                              const float* __restrict__ beta,
                              const float* __restrict__ mean,
                              const float* __restrict__ var) {
    int i = threadIdx.x;
    float inv = gamma[i] * rsqrtf(var[i] + 1e-5f);
    g_bnA[i] = inv;
    g_bnB[i] = beta[i] - mean[i] * inv + conv_b[i] * inv;
}

// ---------------------------------------------------------------------------
// Epilogue: sum split-K partials, BN + ReLU -> feats
// ---------------------------------------------------------------------------
__global__ __launch_bounds__(256) void epi_kernel(float* __restrict__ feats) {
    int row = blockIdx.x;
    int k   = row >> 11;
    int bc  = row & 2047;
    int o   = bc & 255;
    float Aa = g_bnA[k * 256 + o];
    float Bb = g_bnB[k * 256 + o];
    size_t base = (size_t)bc * NPIX + threadIdx.x * 4;
    const size_t SL = (size_t)BATCH * CC * NPIX;
    float4 s;
    if (k == 0) {
        s = *(const float4*)&g_part[base];
    } else if (k == 1) {
        s = *(const float4*)&g_part[SL + base];
    } else if (k == 2) {
        float4 s0 = *(const float4*)&g_part[2 * SL + base];
        float4 s1 = *(const float4*)&g_part[3 * SL + base];
        s = make_float4(s0.x + s1.x, s0.y + s1.y, s0.z + s1.z, s0.w + s1.w);
    } else {
        float4 s0 = *(const float4*)&g_part[4 * SL + base];
        float4 s1 = *(const float4*)&g_part[5 * SL + base];
        float4 s2 = *(const float4*)&g_part[6 * SL + base];
        float4 s3 = *(const float4*)&g_part[7 * SL + base];
        s = make_float4(s0.x + s1.x + s2.x + s3.x, s0.y + s1.y + s2.y + s3.y,
                        s0.z + s1.z + s2.z + s3.z, s0.w + s1.w + s2.w + s3.w);
    }
    float4 v;
    v.x = fmaxf(s.x * Aa + Bb, 0.f);
    v.y = fmaxf(s.y * Aa + Bb, 0.f);
    v.z = fmaxf(s.z * Aa + Bb, 0.f);
    v.w = fmaxf(s.w * Aa + Bb, 0.f);
    *(float4*)&feats[(size_t)k * SL + base] = v;
}

// ---------------------------------------------------------------------------
// S[b,c] = mean over pixels of sum-over-branches of feats
// ---------------------------------------------------------------------------
__global__ __launch_bounds__(128) void sreduce_kernel(float* __restrict__ S) {
    int bc = blockIdx.x;
    int t  = threadIdx.x;
    float s = 0.f;
#pragma unroll
    for (int k = 0; k < 4; k++) {
        const float* p = g_feats + ((size_t)k * (BATCH * CC) + bc) * NPIX;
        for (int n = t; n < NPIX; n += 128) s += p[n];
    }
#pragma unroll
    for (int off = 16; off; off >>= 1) s += __shfl_down_sync(0xffffffffu, s, off);
    __shared__ float red[4];
    if ((t & 31) == 0) red[t >> 5] = s;
    __syncthreads();
    if (t == 0) S[bc] = (red[0] + red[1] + red[2] + red[3]) * (1.f / 1024.f);
}

// ---------------------------------------------------------------------------
// fc -> per-branch logits -> softmax over branches
// ---------------------------------------------------------------------------
__global__ __launch_bounds__(256) void select_kernel(
    const float* __restrict__ S, const float* __restrict__ fc_w,
    const float* __restrict__ fc_b, const float* __restrict__ fcs_w,
    const float* __restrict__ fcs_b, float* __restrict__ attnw) {
    __shared__ float Ss[BATCH * CC];
    __shared__ float Zs[BATCH * DDIM];
    int t = threadIdx.x;
    for (int i = t; i < BATCH * CC; i += 256) Ss[i] = S[i];
    __syncthreads();
    {
        int b = t >> 5, d = t & 31;
        float z = fc_b[d];
        const float* wr = fc_w + d * CC;
        for (int c = 0; c < CC; c++) z += Ss[b * CC + c] * wr[c];
        Zs[b * DDIM + d] = z;
    }
    __syncthreads();
    for (int it = 0; it < 8; it++) {
        int idx = it * 256 + t;
        int b = idx >> 8, c = idx & 255;
        float lg[4];
#pragma unroll
        for (int k = 0; k < 4; k++) {
            float v = fcs_b[k * CC + c];
            const float* wp = fcs_w + ((size_t)k * CC + c) * DDIM;
#pragma unroll
            for (int d = 0; d < DDIM; d++) v += wp[d] * Zs[b * DDIM + d];
            lg[k] = v;
        }
        float mx  = fmaxf(fmaxf(lg[0], lg[1]), fmaxf(lg[2], lg[3]));
        float e0 = __expf(lg[0] - mx), e1 = __expf(lg[1] - mx);
        float e2 = __expf(lg[2] - mx), e3 = __expf(lg[3] - mx);
        float inv = 1.f / (e0 + e1 + e2 + e3);
        attnw[0 * 2048 + idx] = e0 * inv;
        attnw[1 * 2048 + idx] = e1 * inv;
        attnw[2 * 2048 + idx] = e2 * inv;
        attnw[3 * 2048 + idx] = e3 * inv;
    }
}

// ---------------------------------------------------------------------------
// V = sum_k attn[k,b,c] * feats[k,b,c,:]
// ---------------------------------------------------------------------------
__global__ __launch_bounds__(256) void combine_kernel(const float* __restrict__ attnw,
                                                      float* __restrict__ out) {
    int idx = blockIdx.x * 256 + threadIdx.x;
    if (idx >= BATCH * CC * NPIX) return;
    int bc = idx >> 10;
    const size_t KSTRIDE = (size_t)BATCH * CC * NPIX;
    float v = attnw[bc]        * g_feats[idx] +
              attnw[2048 + bc] * g_feats[KSTRIDE + idx] +
              attnw[4096 + bc] * g_feats[2 * KSTRIDE + idx] +
              attnw[6144 + bc] * g_feats[3 * KSTRIDE + idx];
    out[idx] = v;
}

// ---------------------------------------------------------------------------
// Launch
// ---------------------------------------------------------------------------
extern "C" void kernel_launch(void* const* d_in, const int* in_sizes, int n_in,
                              void* d_out, int out_size) {
    const float* x      = (const float*)d_in[0];
    const float* qkv_w  = (const float*)d_in[1];
    const float* out_w  = (const float*)d_in[2];
    const float* w1     = (const float*)d_in[3];
    const float* w3     = (const float*)d_in[4];
    const float* w5     = (const float*)d_in[5];
    const float* w7     = (const float*)d_in[6];
    const float* conv_b = (const float*)d_in[7];
    const float* gamma  = (const float*)d_in[8];
    const float* beta   = (const float*)d_in[9];
    const float* mean   = (const float*)d_in[10];
    const float* var    = (const float*)d_in[11];
    const float* fc_w   = (const float*)d_in[12];
    const float* fc_b   = (const float*)d_in[13];
    const float* fcs_w  = (const float*)d_in[14];
    const float* fcs_b  = (const float*)d_in[15];
    float* out = (float*)d_out;

    float *p_qkv, *p_ctx, *p_ao, *p_feats, *p_S, *p_attnw;
    float *p_qh, *p_ql, *p_oh, *p_ol;
    cudaGetSymbolAddress((void**)&p_qkv,   g_qkv);
    cudaGetSymbolAddress((void**)&p_ctx,   g_ctx);
    cudaGetSymbolAddress((void**)&p_ao,    g_ao);
    cudaGetSymbolAddress((void**)&p_feats, g_feats);
    cudaGetSymbolAddress((void**)&p_S,     g_S);
    cudaGetSymbolAddress((void**)&p_attnw, g_attnw);
    cudaGetSymbolAddress((void**)&p_qh,    g_qkvw_hi);
    cudaGetSymbolAddress((void**)&p_ql,    g_qkvw_lo);
    cudaGetSymbolAddress((void**)&p_oh,    g_outw_hi);
    cudaGetSymbolAddress((void**)&p_ol,    g_outw_lo);

    static int attn_attr_set = 0;
    if (!attn_attr_set) {
        cudaFuncSetAttribute(attn_mma_kernel,
                             cudaFuncAttributeMaxDynamicSharedMemorySize,
                             ATTN_SMEM_BYTES);
        attn_attr_set = 1;
    }

    wtrans_kernel<<<21504, 256>>>(w1, w3, w5, w7);
    wsplit_kernel<<<1024, 256>>>(qkv_w, out_w);
    bnprep_kernel<<<1, 1024>>>(conv_b, gamma, beta, mean, var);

    gemm_mma_kernel<<<dim3(4, 12, 8), 256>>>(p_qh, p_ql, x, p_qkv, 768);
    attn_mma_kernel<<<dim3(8, 64), 256, ATTN_SMEM_BYTES>>>(p_qkv, p_ctx);
    gemm_mma_kernel<<<dim3(4, 4, 8), 256>>>(p_oh, p_ol, p_ctx, p_ao, 256);

    conv_mma_kernel<<<dim3(4, 4, 64), 256>>>(p_ao);
    epi_kernel<<<4 * 2048, 256>>>(p_feats);

    sreduce_kernel<<<2048, 128>>>(p_S);
    select_kernel<<<1, 256>>>(p_S, fc_w, fc_b, fcs_w, fcs_b, p_attnw);
    combine_kernel<<<8192, 256>>>(p_attnw, out);
}

// round 7
// speedup vs baseline: 3.4992x; 1.0505x over previous
#include <cuda_runtime.h>
#include <math_constants.h>
#include <cstdint>

// ---------------------------------------------------------------------------
// Problem constants: x [8, 256, 32, 32], C=256 HEADS=8 HD=32 N=1024 D=32
// ---------------------------------------------------------------------------
#define BATCH 8
#define CC 256
#define NPIX 1024
#define NHEAD 8
#define HDIM 32
#define DDIM 32

// Scratch (device globals: allocation-free, graph-capture safe)
__device__ float g_qkv[BATCH * 3 * CC * NPIX];
__device__ float g_ctx[BATCH * CC * NPIX];
__device__ float g_ao[BATCH * CC * NPIX];
__device__ float g_feats[4 * BATCH * CC * NPIX];
__device__ float g_wT[5505024];                   // conv weights [tap][c][o], tf32
__device__ float g_part[8 * BATCH * CC * NPIX];   // split-K conv partials
__device__ float g_bnA[4 * CC];
__device__ float g_bnB[4 * CC];
__device__ float g_S[BATCH * CC];
__device__ float g_attnw[4 * BATCH * CC];
__device__ float g_qkvw_hi[768 * 256];
__device__ float g_qkvw_lo[768 * 256];
__device__ float g_outw_hi[256 * 256];
__device__ float g_outw_lo[256 * 256];

#define WT_OFF1 0
#define WT_OFF3 65536
#define WT_OFF5 655360
#define WT_OFF7 2293760

__device__ __forceinline__ float to_tf32(float x) {
    uint32_t y;
    asm("cvt.rna.tf32.f32 %0, %1;" : "=r"(y) : "f"(x));
    return __uint_as_float(y);
}
__device__ __forceinline__ uint32_t to_tf32_u(float x) {
    uint32_t y;
    asm("cvt.rna.tf32.f32 %0, %1;" : "=r"(y) : "f"(x));
    return y;
}

__device__ __forceinline__ void mma_tf32(float* d, const uint32_t* a, const uint32_t* b) {
    asm volatile(
        "mma.sync.aligned.m16n8k8.row.col.f32.tf32.tf32.f32 "
        "{%0,%1,%2,%3}, {%4,%5,%6,%7}, {%8,%9}, {%0,%1,%2,%3};"
        : "+f"(d[0]), "+f"(d[1]), "+f"(d[2]), "+f"(d[3])
        : "r"(a[0]), "r"(a[1]), "r"(a[2]), "r"(a[3]), "r"(b[0]), "r"(b[1]));
}

// ---------------------------------------------------------------------------
// Repack conv weights OIHW -> [tap][c][o], tf32-rounded
// ---------------------------------------------------------------------------
__global__ void wtrans_kernel(const float* __restrict__ w1, const float* __restrict__ w3,
                              const float* __restrict__ w5, const float* __restrict__ w7) {
    int idx = blockIdx.x * 256 + threadIdx.x;
    if (idx >= 5505024) return;
    const float* src;
    int k2, base;
    if (idx < 655360)       { if (idx < 65536) { src = w1; k2 = 1;  base = 0; }
                              else             { src = w3; k2 = 9;  base = 65536; } }
    else if (idx < 2293760) { src = w5; k2 = 25; base = 655360; }
    else                    { src = w7; k2 = 49; base = 2293760; }
    int r   = idx - base;
    int o   = r & 255;
    int c   = (r >> 8) & 255;
    int tap = r >> 16;
    g_wT[idx] = to_tf32(src[(o * 256 + c) * k2 + tap]);
}

// ---------------------------------------------------------------------------
// Split + transpose projection weights: W[m][k] -> WT_hi/lo[k][m]
// ---------------------------------------------------------------------------
__global__ void wsplit_kernel(const float* __restrict__ qkv_w,
                              const float* __restrict__ out_w) {
    int idx = blockIdx.x * 256 + threadIdx.x;
    if (idx < 196608) {
        int m = idx / 256, k = idx & 255;
        float v  = qkv_w[idx];
        float hi = to_tf32(v);
        g_qkvw_hi[k * 768 + m] = hi;
        g_qkvw_lo[k * 768 + m] = to_tf32(v - hi);
    } else {
        int r = idx - 196608;
        int m = r / 256, k = r & 255;
        float v  = out_w[r];
        float hi = to_tf32(v);
        g_outw_hi[k * 256 + m] = hi;
        g_outw_lo[k * 256 + m] = to_tf32(v - hi);
    }
}

// ---------------------------------------------------------------------------
// GEMM via tf32 mma, 3-mma hi/lo split. X pre-split into smem (hi/lo) during
// load phase -> mainloop is pure LDS+mma (issue-lean).
// CTA: M=64 x N=256, 8 warps (2m x 4n), warp tile 32x64.
// ---------------------------------------------------------------------------
#define GW_STRIDE 72
#define GX_STRIDE 264

__global__ __launch_bounds__(256) void gemm_mma_kernel(
    const float* __restrict__ WhiT, const float* __restrict__ WloT,
    const float* __restrict__ X, float* __restrict__ D, int M) {
    __shared__ float sWhi[16 * GW_STRIDE];
    __shared__ float sWlo[16 * GW_STRIDE];
    __shared__ float sXhi[16 * GX_STRIDE];
    __shared__ float sXlo[16 * GX_STRIDE];
    int tid = threadIdx.x;
    int n0 = blockIdx.x * 256, m0 = blockIdx.y * 64, b = blockIdx.z;
    const float* Xb = X + (size_t)b * 256 * NPIX;
    float*       Db = D + (size_t)b * M * NPIX;
    int wid = tid >> 5, lane = tid & 31;
    int g = lane >> 2, tq = lane & 3;
    int mw = (wid >> 2) * 32;
    int nw = (wid & 3) * 64;
    float acc[2][8][4] = {};
    for (int k0 = 0; k0 < 256; k0 += 16) {
        __syncthreads();
        {
            int k = tid >> 4, col = (tid & 15) * 4;
            *(float4*)&sWhi[k * GW_STRIDE + col] =
                *(const float4*)&WhiT[(size_t)(k0 + k) * M + m0 + col];
            *(float4*)&sWlo[k * GW_STRIDE + col] =
                *(const float4*)&WloT[(size_t)(k0 + k) * M + m0 + col];
        }
        for (int i = tid; i < 1024; i += 256) {
            int k = i >> 6, c4 = (i & 63) * 4;
            float4 v = *(const float4*)&Xb[(size_t)(k0 + k) * NPIX + n0 + c4];
            float4 hi, lo;
            hi.x = to_tf32(v.x); lo.x = to_tf32(v.x - hi.x);
            hi.y = to_tf32(v.y); lo.y = to_tf32(v.y - hi.y);
            hi.z = to_tf32(v.z); lo.z = to_tf32(v.z - hi.z);
            hi.w = to_tf32(v.w); lo.w = to_tf32(v.w - hi.w);
            *(float4*)&sXhi[k * GX_STRIDE + c4] = hi;
            *(float4*)&sXlo[k * GX_STRIDE + c4] = lo;
        }
        __syncthreads();
#pragma unroll
        for (int s = 0; s < 2; s++) {
            int k = 8 * s + tq;
            uint32_t ahi[2][4], alo[2][4];
#pragma unroll
            for (int t = 0; t < 2; t++) {
                int m = mw + 16 * t + g;
                ahi[t][0] = __float_as_uint(sWhi[k * GW_STRIDE + m]);
                ahi[t][1] = __float_as_uint(sWhi[k * GW_STRIDE + m + 8]);
                ahi[t][2] = __float_as_uint(sWhi[(k + 4) * GW_STRIDE + m]);
                ahi[t][3] = __float_as_uint(sWhi[(k + 4) * GW_STRIDE + m + 8]);
                alo[t][0] = __float_as_uint(sWlo[k * GW_STRIDE + m]);
                alo[t][1] = __float_as_uint(sWlo[k * GW_STRIDE + m + 8]);
                alo[t][2] = __float_as_uint(sWlo[(k + 4) * GW_STRIDE + m]);
                alo[t][3] = __float_as_uint(sWlo[(k + 4) * GW_STRIDE + m + 8]);
            }
#pragma unroll
            for (int j = 0; j < 8; j++) {
                int nj = nw + 8 * j + g;
                uint32_t bhi[2], blo[2];
                bhi[0] = __float_as_uint(sXhi[k * GX_STRIDE + nj]);
                bhi[1] = __float_as_uint(sXhi[(k + 4) * GX_STRIDE + nj]);
                blo[0] = __float_as_uint(sXlo[k * GX_STRIDE + nj]);
                blo[1] = __float_as_uint(sXlo[(k + 4) * GX_STRIDE + nj]);
#pragma unroll
                for (int t = 0; t < 2; t++) {
                    mma_tf32(acc[t][j], ahi[t], bhi);
                    mma_tf32(acc[t][j], alo[t], bhi);
                    mma_tf32(acc[t][j], ahi[t], blo);
                }
            }
        }
    }
#pragma unroll
    for (int t = 0; t < 2; t++) {
        int o = m0 + mw + 16 * t + g;
#pragma unroll
        for (int j = 0; j < 8; j++) {
            int n = n0 + nw + 8 * j + 2 * tq;
            *(float2*)&Db[(size_t)o * NPIX + n] =
                make_float2(acc[t][j][0], acc[t][j][1]);
            *(float2*)&Db[(size_t)(o + 8) * NPIX + n] =
                make_float2(acc[t][j][2], acc[t][j][3]);
        }
    }
}

// ---------------------------------------------------------------------------
// Attention via tf32 mma.sync, flash-style online softmax (unchanged, passing)
// ---------------------------------------------------------------------------
#define ATTN_SMEM_BYTES 64512

__global__ __launch_bounds__(256) void attn_mma_kernel(const float* __restrict__ qkv,
                                                       float* __restrict__ ctx) {
    extern __shared__ float sm[];
    float* sKhi = sm;
    float* sKlo = sm + 2304;
    float* sV   = sm + 4608;
    float* sQ   = sm + 6912;

    int t    = threadIdx.x;
    int wid  = t >> 5, lane = t & 31;
    int g    = lane >> 2;
    int tq   = lane & 3;
    int qw   = wid * 16;
    float* sP = sm + 6912 + wid * (16 * 72);

    int bh = blockIdx.y;
    int b = bh >> 3, h = bh & 7;
    int q0 = blockIdx.x * 128;
    const float* base = qkv + (size_t)b * (3 * CC * NPIX);
    const float* qp = base + (h * HDIM) * NPIX;
    const float* kp = base + (CC + h * HDIM) * NPIX;
    const float* vp = base + (2 * CC + h * HDIM) * NPIX;
    const float scale = 0.17677669529663687f;

    for (int i = t; i < 1024; i += 256) {
        int d  = i >> 5;
        int q4 = (i & 31) * 4;
        float4 v = *(const float4*)&qp[(size_t)d * NPIX + q0 + q4];
        sQ[(q4 + 0) * 36 + d] = v.x * scale;
        sQ[(q4 + 1) * 36 + d] = v.y * scale;
        sQ[(q4 + 2) * 36 + d] = v.z * scale;
        sQ[(q4 + 3) * 36 + d] = v.w * scale;
    }
    __syncthreads();

    uint32_t qhi[4][4], qlo[4][4];
#pragma unroll
    for (int kc = 0; kc < 4; kc++) {
#pragma unroll
        for (int r = 0; r < 4; r++) {
            int row = qw + ((r & 1) ? g + 8 : g);
            int col = 8 * kc + tq + ((r >> 1) ? 4 : 0);
            float v  = sQ[row * 36 + col];
            float hi = to_tf32(v);
            qhi[kc][r] = __float_as_uint(hi);
            qlo[kc][r] = to_tf32_u(v - hi);
        }
    }

    float mrow[2] = {-1e30f, -1e30f};
    float lrow[2] = {0.f, 0.f};
    float oacc[4][4] = {};

    for (int k0 = 0; k0 < NPIX; k0 += 64) {
        __syncthreads();
        for (int i = t; i < 512; i += 256) {
            int d  = i >> 4;
            int c4 = (i & 15) * 4;
            float4 v = *(const float4*)&kp[(size_t)d * NPIX + k0 + c4];
            float4 hi, lo;
            hi.x = to_tf32(v.x); lo.x = to_tf32(v.x - hi.x);
            hi.y = to_tf32(v.y); lo.y = to_tf32(v.y - hi.y);
            hi.z = to_tf32(v.z); lo.z = to_tf32(v.z - hi.z);
            hi.w = to_tf32(v.w); lo.w = to_tf32(v.w - hi.w);
            *(float4*)&sKhi[d * 72 + c4] = hi;
            *(float4*)&sKlo[d * 72 + c4] = lo;
            float4 vv = *(const float4*)&vp[(size_t)d * NPIX + k0 + c4];
            vv.x = to_tf32(vv.x); vv.y = to_tf32(vv.y);
            vv.z = to_tf32(vv.z); vv.w = to_tf32(vv.w);
            *(float4*)&sV[d * 72 + c4] = vv;
        }
        __syncthreads();

        float sv[8][4];
#pragma unroll
        for (int nt = 0; nt < 8; nt++) {
            float acc[4] = {0.f, 0.f, 0.f, 0.f};
#pragma unroll
            for (int kc = 0; kc < 4; kc++) {
                int i0 = (8 * kc + tq) * 72 + 8 * nt + g;
                int i1 = (8 * kc + tq + 4) * 72 + 8 * nt + g;
                uint32_t bh2[2] = {__float_as_uint(sKhi[i0]), __float_as_uint(sKhi[i1])};
                uint32_t bl2[2] = {__float_as_uint(sKlo[i0]), __float_as_uint(sKlo[i1])};
                mma_tf32(acc, qhi[kc], bh2);
                mma_tf32(acc, qlo[kc], bh2);
                mma_tf32(acc, qhi[kc], bl2);
            }
            sv[nt][0] = acc[0]; sv[nt][1] = acc[1];
            sv[nt][2] = acc[2]; sv[nt][3] = acc[3];
        }

        float tm0 = -1e30f, tm1 = -1e30f;
#pragma unroll
        for (int nt = 0; nt < 8; nt++) {
            tm0 = fmaxf(tm0, fmaxf(sv[nt][0], sv[nt][1]));
            tm1 = fmaxf(tm1, fmaxf(sv[nt][2], sv[nt][3]));
        }
        tm0 = fmaxf(tm0, __shfl_xor_sync(0xffffffffu, tm0, 1));
        tm0 = fmaxf(tm0, __shfl_xor_sync(0xffffffffu, tm0, 2));
        tm1 = fmaxf(tm1, __shfl_xor_sync(0xffffffffu, tm1, 1));
        tm1 = fmaxf(tm1, __shfl_xor_sync(0xffffffffu, tm1, 2));
        float m0n = fmaxf(mrow[0], tm0);
        float m1n = fmaxf(mrow[1], tm1);
        float c0 = __expf(mrow[0] - m0n);
        float c1 = __expf(mrow[1] - m1n);
        mrow[0] = m0n; mrow[1] = m1n;
        lrow[0] *= c0; lrow[1] *= c1;
#pragma unroll
        for (int dt = 0; dt < 4; dt++) {
            oacc[dt][0] *= c0; oacc[dt][1] *= c0;
            oacc[dt][2] *= c1; oacc[dt][3] *= c1;
        }
#pragma unroll
        for (int nt = 0; nt < 8; nt++) {
            float p0 = __expf(sv[nt][0] - m0n);
            float p1 = __expf(sv[nt][1] - m0n);
            float p2 = __expf(sv[nt][2] - m1n);
            float p3 = __expf(sv[nt][3] - m1n);
            lrow[0] += p0 + p1;
            lrow[1] += p2 + p3;
            *(float2*)&sP[g * 72 + 8 * nt + 2 * tq] =
                make_float2(to_tf32(p0), to_tf32(p1));
            *(float2*)&sP[(g + 8) * 72 + 8 * nt + 2 * tq] =
                make_float2(to_tf32(p2), to_tf32(p3));
        }
        __syncwarp();

#pragma unroll
        for (int kc = 0; kc < 8; kc++) {
            uint32_t a[4];
            a[0] = __float_as_uint(sP[g * 72 + 8 * kc + tq]);
            a[1] = __float_as_uint(sP[(g + 8) * 72 + 8 * kc + tq]);
            a[2] = __float_as_uint(sP[g * 72 + 8 * kc + tq + 4]);
            a[3] = __float_as_uint(sP[(g + 8) * 72 + 8 * kc + tq + 4]);
#pragma unroll
            for (int dt = 0; dt < 4; dt++) {
                uint32_t bb[2];
                bb[0] = __float_as_uint(sV[(8 * dt + g) * 72 + 8 * kc + tq]);
                bb[1] = __float_as_uint(sV[(8 * dt + g) * 72 + 8 * kc + tq + 4]);
                mma_tf32(oacc[dt], a, bb);
            }
        }
        __syncwarp();
    }

    lrow[0] += __shfl_xor_sync(0xffffffffu, lrow[0], 1);
    lrow[0] += __shfl_xor_sync(0xffffffffu, lrow[0], 2);
    lrow[1] += __shfl_xor_sync(0xffffffffu, lrow[1], 1);
    lrow[1] += __shfl_xor_sync(0xffffffffu, lrow[1], 2);
    float inv0 = 1.f / lrow[0];
    float inv1 = 1.f / lrow[1];
    float* cp = ctx + (size_t)b * (CC * NPIX) + (size_t)(h * HDIM) * NPIX;
    int qr0 = q0 + qw + g;
    int qr1 = qr0 + 8;
#pragma unroll
    for (int dt = 0; dt < 4; dt++) {
        int d0 = 8 * dt + 2 * tq;
        cp[(size_t)d0 * NPIX + qr0]       = oacc[dt][0] * inv0;
        cp[(size_t)(d0 + 1) * NPIX + qr0] = oacc[dt][1] * inv0;
        cp[(size_t)d0 * NPIX + qr1]       = oacc[dt][2] * inv1;
        cp[(size_t)(d0 + 1) * NPIX + qr1] = oacc[dt][3] * inv1;
    }
}

// ---------------------------------------------------------------------------
// Conv via tf32 mma. v3: zero-padded patch (no halo predicates, linear
// offsets) + A staged in 4-tap groups, double-buffered (1 sync / 4 taps).
// CTA: M=64 x N=256, 8 warps (2m x 4n), warp tile 32x64, 2 CTAs/SM.
// Dynamic smem: patch 16*568 floats, A 2*4*16*72 floats -> 73216 B.
// ---------------------------------------------------------------------------
#define PPW 40            // padded patch width: 4 | 32 | 4
#define PSTR 568          // c-plane stride (14*40 + 8): conflict-free
#define AT_STRIDE 72
#define AT_TAP (16 * AT_STRIDE)        // one tap's A tile
#define AT_GRP (4 * AT_TAP)            // 4-tap group
#define CONV_SMEM_FLOATS (16 * PSTR + 2 * AT_GRP)
#define CONV_SMEM_BYTES (CONV_SMEM_FLOATS * 4)

__global__ __launch_bounds__(256, 2) void conv_mma_kernel(const float* __restrict__ in) {
    extern __shared__ float cs[];
    float* sPatch = cs;
    float* sA     = cs + 16 * PSTR;

    int z = blockIdx.z;
    int ks, tap0, tap1, slot, wtoff, b;
    if (z < 32) {
        int s = z >> 3; b = z & 7;
        ks = 7; tap0 = (s * 49) >> 2; tap1 = ((s + 1) * 49) >> 2;
        slot = 4 + s; wtoff = WT_OFF7;
    } else if (z < 48) {
        int s = (z - 32) >> 3; b = z & 7;
        ks = 5; tap0 = (s * 25) >> 1; tap1 = ((s + 1) * 25) >> 1;
        slot = 2 + s; wtoff = WT_OFF5;
    } else if (z < 56) {
        b = z - 48; ks = 3; tap0 = 0; tap1 = 9; slot = 1; wtoff = WT_OFF3;
    } else {
        b = z - 56; ks = 1; tap0 = 0; tap1 = 1; slot = 0; wtoff = WT_OFF1;
    }
    const int P = ks >> 1;
    const int rows = 8 + 2 * P;

    int n0 = blockIdx.x * 256;
    int m0 = blockIdx.y * 64;
    int r0 = n0 >> 5;
    int tid = threadIdx.x;
    int wid = tid >> 5, lane = tid & 31;
    int mw = (wid >> 2) * 32;
    int nw = (wid & 3) * 64;
    int lg = lane >> 2;
    int lk = lane & 3;

    // zero entire patch once (halo cols + out-of-image rows stay zero)
    for (int i = tid; i < 16 * PSTR / 4; i += 256)
        *(float4*)&sPatch[i * 4] = make_float4(0.f, 0.f, 0.f, 0.f);

    int njoff[8];
#pragma unroll
    for (int j = 0; j < 8; j++) {
        int n = nw + 8 * j + lg;
        njoff[j] = (n >> 5) * PPW + (n & 31) + 4;
    }

    const float* inb = in + (size_t)b * (CC * NPIX);
    const float* wbase = g_wT + (size_t)wtoff;
    float acc[2][8][4] = {};

    for (int c0 = 0; c0 < 256; c0 += 16) {
        __syncthreads();  // prior MMAs done before overwriting patch / sA[0]
        // --- patch: 16 c-planes x rows x 32 (valid region only) ---
        {
            int per_plane = rows * 8;
            int total = 16 * per_plane;
            for (int i = tid; i < total; i += 256) {
                int c  = i / per_plane;
                int rm = i - c * per_plane;
                int py = rm >> 3;
                int xq = (rm & 7) * 4;
                int iy = r0 - P + py;
                if ((unsigned)iy < 32u) {
                    float4 v = *(const float4*)&inb[(size_t)(c0 + c) * NPIX + iy * 32 + xq];
                    v.x = to_tf32(v.x); v.y = to_tf32(v.y);
                    v.z = to_tf32(v.z); v.w = to_tf32(v.w);
                    *(float4*)&sPatch[c * PSTR + py * PPW + 4 + xq] = v;
                }
            }
        }
        // --- preload first tap group into buffer 0 ---
        {
            int gcnt = tap1 - tap0; if (gcnt > 4) gcnt = 4;
            for (int i = tid; i < gcnt * 256; i += 256) {
                int tp = i >> 8;
                int k = (i >> 4) & 15, col = (i & 15) * 4;
                *(float4*)&sA[tp * AT_TAP + k * AT_STRIDE + col] =
                    *(const float4*)&wbase[(size_t)(tap0 + tp) * (CC * CC) +
                                           (size_t)(c0 + k) * CC + m0 + col];
            }
        }
        __syncthreads();

        int buf = 0;
        for (int g0 = tap0; g0 < tap1; g0 += 4) {
            int gcnt = tap1 - g0; if (gcnt > 4) gcnt = 4;
            // prefetch next group
            int h0 = g0 + 4;
            if (h0 < tap1) {
                int hcnt = tap1 - h0; if (hcnt > 4) hcnt = 4;
                float* dst = sA + (buf ^ 1) * AT_GRP;
                for (int i = tid; i < hcnt * 256; i += 256) {
                    int tp = i >> 8;
                    int k = (i >> 4) & 15, col = (i & 15) * 4;
                    *(float4*)&dst[tp * AT_TAP + k * AT_STRIDE + col] =
                        *(const float4*)&wbase[(size_t)(h0 + tp) * (CC * CC) +
                                               (size_t)(c0 + k) * CC + m0 + col];
                }
            }
            const uint32_t* Pp = (const uint32_t*)sPatch;
            for (int ti = 0; ti < gcnt; ti++) {
                int tap = g0 + ti;
                int ty = tap / ks;
                int tx = tap - ty * ks;
                int tadd = ty * PPW + tx - P;
                const uint32_t* A =
                    (const uint32_t*)(sA + buf * AT_GRP + ti * AT_TAP);
#pragma unroll
                for (int s = 0; s < 2; s++) {
                    int k = s * 8 + lk;
                    uint32_t a[2][4];
#pragma unroll
                    for (int t = 0; t < 2; t++) {
                        int m = mw + 16 * t + lg;
                        a[t][0] = A[k * AT_STRIDE + m];
                        a[t][1] = A[k * AT_STRIDE + m + 8];
                        a[t][2] = A[(k + 4) * AT_STRIDE + m];
                        a[t][3] = A[(k + 4) * AT_STRIDE + m + 8];
                    }
                    uint32_t bb[8][2];
#pragma unroll
                    for (int j = 0; j < 8; j++) {
                        int off = k * PSTR + njoff[j] + tadd;
                        bb[j][0] = Pp[off];
                        bb[j][1] = Pp[off + 4 * PSTR];
                    }
#pragma unroll
                    for (int t = 0; t < 2; t++)
#pragma unroll
                        for (int j = 0; j < 8; j++) mma_tf32(acc[t][j], a[t], bb[j]);
                }
            }
            __syncthreads();
            buf ^= 1;
        }
    }

    float* pp = g_part + (size_t)slot * (BATCH * CC * NPIX) + (size_t)b * (CC * NPIX);
#pragma unroll
    for (int t = 0; t < 2; t++) {
        int o = m0 + mw + 16 * t + lg;
#pragma unroll
        for (int j = 0; j < 8; j++) {
            int n = n0 + nw + 8 * j + 2 * lk;
            *(float2*)&pp[(size_t)o * NPIX + n] =
                make_float2(acc[t][j][0], acc[t][j][1]);
            *(float2*)&pp[(size_t)(o + 8) * NPIX + n] =
                make_float2(acc[t][j][2], acc[t][j][3]);
        }
    }
}

// ---------------------------------------------------------------------------
// BN constants
// ---------------------------------------------------------------------------
__global__ void bnprep_kernel(const float* __restrict__ conv_b,
                              const float* __restrict__ gamma,
                              const float* __restrict__ beta,
                              const float* __restrict__ mean,
                              const float* __restrict__ var) {
    int i = threadIdx.x;
    float inv = gamma[i] * rsqrtf(var[i] + 1e-5f);
    g_bnA[i] = inv;
    g_bnB[i] = beta[i] - mean[i] * inv + conv_b[i] * inv;
}

// ---------------------------------------------------------------------------
// Epilogue: sum split-K partials, BN + ReLU -> feats
// ---------------------------------------------------------------------------
__global__ __launch_bounds__(256) void epi_kernel(float* __restrict__ feats) {
    int row = blockIdx.x;
    int k   = row >> 11;
    int bc  = row & 2047;
    int o   = bc & 255;
    float Aa = g_bnA[k * 256 + o];
    float Bb = g_bnB[k * 256 + o];
    size_t base = (size_t)bc * NPIX + threadIdx.x * 4;
    const size_t SL = (size_t)BATCH * CC * NPIX;
    float4 s;
    if (k == 0) {
        s = *(const float4*)&g_part[base];
    } else if (k == 1) {
        s = *(const float4*)&g_part[SL + base];
    } else if (k == 2) {
        float4 s0 = *(const float4*)&g_part[2 * SL + base];
        float4 s1 = *(const float4*)&g_part[3 * SL + base];
        s = make_float4(s0.x + s1.x, s0.y + s1.y, s0.z + s1.z, s0.w + s1.w);
    } else {
        float4 s0 = *(const float4*)&g_part[4 * SL + base];
        float4 s1 = *(const float4*)&g_part[5 * SL + base];
        float4 s2 = *(const float4*)&g_part[6 * SL + base];
        float4 s3 = *(const float4*)&g_part[7 * SL + base];
        s = make_float4(s0.x + s1.x + s2.x + s3.x, s0.y + s1.y + s2.y + s3.y,
                        s0.z + s1.z + s2.z + s3.z, s0.w + s1.w + s2.w + s3.w);
    }
    float4 v;
    v.x = fmaxf(s.x * Aa + Bb, 0.f);
    v.y = fmaxf(s.y * Aa + Bb, 0.f);
    v.z = fmaxf(s.z * Aa + Bb, 0.f);
    v.w = fmaxf(s.w * Aa + Bb, 0.f);
    *(float4*)&feats[(size_t)k * SL + base] = v;
}

// ---------------------------------------------------------------------------
// S[b,c] = mean over pixels of sum-over-branches of feats
// ---------------------------------------------------------------------------
__global__ __launch_bounds__(128) void sreduce_kernel(float* __restrict__ S) {
    int bc = blockIdx.x;
    int t  = threadIdx.x;
    float s = 0.f;
#pragma unroll
    for (int k = 0; k < 4; k++) {
        const float* p = g_feats + ((size_t)k * (BATCH * CC) + bc) * NPIX;
        for (int n = t; n < NPIX; n += 128) s += p[n];
    }
#pragma unroll
    for (int off = 16; off; off >>= 1) s += __shfl_down_sync(0xffffffffu, s, off);
    __shared__ float red[4];
    if ((t & 31) == 0) red[t >> 5] = s;
    __syncthreads();
    if (t == 0) S[bc] = (red[0] + red[1] + red[2] + red[3]) * (1.f / 1024.f);
}

// ---------------------------------------------------------------------------
// fc -> per-branch logits -> softmax over branches
// ---------------------------------------------------------------------------
__global__ __launch_bounds__(256) void select_kernel(
    const float* __restrict__ S, const float* __restrict__ fc_w,
    const float* __restrict__ fc_b, const float* __restrict__ fcs_w,
    const float* __restrict__ fcs_b, float* __restrict__ attnw) {
    __shared__ float Ss[BATCH * CC];
    __shared__ float Zs[BATCH * DDIM];
    int t = threadIdx.x;
    for (int i = t; i < BATCH * CC; i += 256) Ss[i] = S[i];
    __syncthreads();
    {
        int b = t >> 5, d = t & 31;
        float z = fc_b[d];
        const float* wr = fc_w + d * CC;
        for (int c = 0; c < CC; c++) z += Ss[b * CC + c] * wr[c];
        Zs[b * DDIM + d] = z;
    }
    __syncthreads();
    for (int it = 0; it < 8; it++) {
        int idx = it * 256 + t;
        int b = idx >> 8, c = idx & 255;
        float lg[4];
#pragma unroll
        for (int k = 0; k < 4; k++) {
            float v = fcs_b[k * CC + c];
            const float* wp = fcs_w + ((size_t)k * CC + c) * DDIM;
#pragma unroll
            for (int d = 0; d < DDIM; d++) v += wp[d] * Zs[b * DDIM + d];
            lg[k] = v;
        }
        float mx  = fmaxf(fmaxf(lg[0], lg[1]), fmaxf(lg[2], lg[3]));
        float e0 = __expf(lg[0] - mx), e1 = __expf(lg[1] - mx);
        float e2 = __expf(lg[2] - mx), e3 = __expf(lg[3] - mx);
        float inv = 1.f / (e0 + e1 + e2 + e3);
        attnw[0 * 2048 + idx] = e0 * inv;
        attnw[1 * 2048 + idx] = e1 * inv;
        attnw[2 * 2048 + idx] = e2 * inv;
        attnw[3 * 2048 + idx] = e3 * inv;
    }
}

// ---------------------------------------------------------------------------
// V = sum_k attn[k,b,c] * feats[k,b,c,:]
// ---------------------------------------------------------------------------
__global__ __launch_bounds__(256) void combine_kernel(const float* __restrict__ attnw,
                                                      float* __restrict__ out) {
    int idx = blockIdx.x * 256 + threadIdx.x;
    if (idx >= BATCH * CC * NPIX) return;
    int bc = idx >> 10;
    const size_t KSTRIDE = (size_t)BATCH * CC * NPIX;
    float v = attnw[bc]        * g_feats[idx] +
              attnw[2048 + bc] * g_feats[KSTRIDE + idx] +
              attnw[4096 + bc] * g_feats[2 * KSTRIDE + idx] +
              attnw[6144 + bc] * g_feats[3 * KSTRIDE + idx];
    out[idx] = v;
}

// ---------------------------------------------------------------------------
// Launch
// ---------------------------------------------------------------------------
extern "C" void kernel_launch(void* const* d_in, const int* in_sizes, int n_in,
                              void* d_out, int out_size) {
    const float* x      = (const float*)d_in[0];
    const float* qkv_w  = (const float*)d_in[1];
    const float* out_w  = (const float*)d_in[2];
    const float* w1     = (const float*)d_in[3];
    const float* w3     = (const float*)d_in[4];
    const float* w5     = (const float*)d_in[5];
    const float* w7     = (const float*)d_in[6];
    const float* conv_b = (const float*)d_in[7];
    const float* gamma  = (const float*)d_in[8];
    const float* beta   = (const float*)d_in[9];
    const float* mean   = (const float*)d_in[10];
    const float* var    = (const float*)d_in[11];
    const float* fc_w   = (const float*)d_in[12];
    const float* fc_b   = (const float*)d_in[13];
    const float* fcs_w  = (const float*)d_in[14];
    const float* fcs_b  = (const float*)d_in[15];
    float* out = (float*)d_out;

    float *p_qkv, *p_ctx, *p_ao, *p_feats, *p_S, *p_attnw;
    float *p_qh, *p_ql, *p_oh, *p_ol;
    cudaGetSymbolAddress((void**)&p_qkv,   g_qkv);
    cudaGetSymbolAddress((void**)&p_ctx,   g_ctx);
    cudaGetSymbolAddress((void**)&p_ao,    g_ao);
    cudaGetSymbolAddress((void**)&p_feats, g_feats);
    cudaGetSymbolAddress((void**)&p_S,     g_S);
    cudaGetSymbolAddress((void**)&p_attnw, g_attnw);
    cudaGetSymbolAddress((void**)&p_qh,    g_qkvw_hi);
    cudaGetSymbolAddress((void**)&p_ql,    g_qkvw_lo);
    cudaGetSymbolAddress((void**)&p_oh,    g_outw_hi);
    cudaGetSymbolAddress((void**)&p_ol,    g_outw_lo);

    static int attr_set = 0;
    if (!attr_set) {
        cudaFuncSetAttribute(attn_mma_kernel,
                             cudaFuncAttributeMaxDynamicSharedMemorySize,
                             ATTN_SMEM_BYTES);
        cudaFuncSetAttribute(conv_mma_kernel,
                             cudaFuncAttributeMaxDynamicSharedMemorySize,
                             CONV_SMEM_BYTES);
        attr_set = 1;
    }

    wtrans_kernel<<<21504, 256>>>(w1, w3, w5, w7);
    wsplit_kernel<<<1024, 256>>>(qkv_w, out_w);
    bnprep_kernel<<<1, 1024>>>(conv_b, gamma, beta, mean, var);

    gemm_mma_kernel<<<dim3(4, 12, 8), 256>>>(p_qh, p_ql, x, p_qkv, 768);
    attn_mma_kernel<<<dim3(8, 64), 256, ATTN_SMEM_BYTES>>>(p_qkv, p_ctx);
    gemm_mma_kernel<<<dim3(4, 4, 8), 256>>>(p_oh, p_ol, p_ctx, p_ao, 256);

    conv_mma_kernel<<<dim3(4, 4, 64), 256, CONV_SMEM_BYTES>>>(p_ao);
    epi_kernel<<<4 * 2048, 256>>>(p_feats);

    sreduce_kernel<<<2048, 128>>>(p_S);
    select_kernel<<<1, 256>>>(p_S, fc_w, fc_b, fcs_w, fcs_b, p_attnw);
    combine_kernel<<<8192, 256>>>(p_attnw, out);
}

// round 8
// speedup vs baseline: 3.7903x; 1.0832x over previous
#include <cuda_runtime.h>
#include <math_constants.h>
#include <cstdint>

// ---------------------------------------------------------------------------
// Problem constants: x [8, 256, 32, 32], C=256 HEADS=8 HD=32 N=1024 D=32
// ---------------------------------------------------------------------------
#define BATCH 8
#define CC 256
#define NPIX 1024
#define NHEAD 8
#define HDIM 32
#define DDIM 32

// Scratch (device globals: allocation-free, graph-capture safe)
__device__ float g_qkv[BATCH * 3 * CC * NPIX];
__device__ float g_ctx[BATCH * CC * NPIX];
__device__ float g_ao[BATCH * CC * NPIX];
__device__ float g_feats[4 * BATCH * CC * NPIX];
__device__ float g_wT[5505024];                   // conv weights [tap][c][o], tf32
__device__ float g_part[8 * BATCH * CC * NPIX];   // split-K conv partials
__device__ float g_bnA[4 * CC];
__device__ float g_bnB[4 * CC];
__device__ float g_S[BATCH * CC];
__device__ float g_attnw[4 * BATCH * CC];
__device__ float g_qkvwT[768 * 256];              // transposed, tf32
__device__ float g_outwT[256 * 256];              // transposed, tf32

#define WT_OFF1 0
#define WT_OFF3 65536
#define WT_OFF5 655360
#define WT_OFF7 2293760

__device__ __forceinline__ float to_tf32(float x) {
    uint32_t y;
    asm("cvt.rna.tf32.f32 %0, %1;" : "=r"(y) : "f"(x));
    return __uint_as_float(y);
}
__device__ __forceinline__ uint32_t to_tf32_u(float x) {
    uint32_t y;
    asm("cvt.rna.tf32.f32 %0, %1;" : "=r"(y) : "f"(x));
    return y;
}

__device__ __forceinline__ void mma_tf32(float* d, const uint32_t* a, const uint32_t* b) {
    asm volatile(
        "mma.sync.aligned.m16n8k8.row.col.f32.tf32.tf32.f32 "
        "{%0,%1,%2,%3}, {%4,%5,%6,%7}, {%8,%9}, {%0,%1,%2,%3};"
        : "+f"(d[0]), "+f"(d[1]), "+f"(d[2]), "+f"(d[3])
        : "r"(a[0]), "r"(a[1]), "r"(a[2]), "r"(a[3]), "r"(b[0]), "r"(b[1]));
}

// ---------------------------------------------------------------------------
// Repack conv weights OIHW -> [tap][c][o], tf32-rounded
// ---------------------------------------------------------------------------
__global__ void wtrans_kernel(const float* __restrict__ w1, const float* __restrict__ w3,
                              const float* __restrict__ w5, const float* __restrict__ w7) {
    int idx = blockIdx.x * 256 + threadIdx.x;
    if (idx >= 5505024) return;
    const float* src;
    int k2, base;
    if (idx < 655360)       { if (idx < 65536) { src = w1; k2 = 1;  base = 0; }
                              else             { src = w3; k2 = 9;  base = 65536; } }
    else if (idx < 2293760) { src = w5; k2 = 25; base = 655360; }
    else                    { src = w7; k2 = 49; base = 2293760; }
    int r   = idx - base;
    int o   = r & 255;
    int c   = (r >> 8) & 255;
    int tap = r >> 16;
    g_wT[idx] = to_tf32(src[(o * 256 + c) * k2 + tap]);
}

// ---------------------------------------------------------------------------
// Transpose projection weights: W[m][k] -> WT[k][m], tf32-rounded
// ---------------------------------------------------------------------------
__global__ void wsplit_kernel(const float* __restrict__ qkv_w,
                              const float* __restrict__ out_w) {
    int idx = blockIdx.x * 256 + threadIdx.x;
    if (idx < 196608) {
        int m = idx / 256, k = idx & 255;
        g_qkvwT[k * 768 + m] = to_tf32(qkv_w[idx]);
    } else {
        int r = idx - 196608;
        int m = r / 256, k = r & 255;
        g_outwT[k * 256 + m] = to_tf32(out_w[r]);
    }
}

// ---------------------------------------------------------------------------
// GEMM via tf32 mma (single-precision tf32; X rounded at smem load).
// CTA: M=64 x N=256, 8 warps (2m x 4n), warp tile 32x64.
// ---------------------------------------------------------------------------
#define GW_STRIDE 72
#define GX_STRIDE 264

__global__ __launch_bounds__(256) void gemm_mma_kernel(
    const float* __restrict__ WT, const float* __restrict__ X,
    float* __restrict__ D, int M) {
    __shared__ float sW[16 * GW_STRIDE];
    __shared__ float sX[16 * GX_STRIDE];
    int tid = threadIdx.x;
    int n0 = blockIdx.x * 256, m0 = blockIdx.y * 64, b = blockIdx.z;
    const float* Xb = X + (size_t)b * 256 * NPIX;
    float*       Db = D + (size_t)b * M * NPIX;
    int wid = tid >> 5, lane = tid & 31;
    int g = lane >> 2, tq = lane & 3;
    int mw = (wid >> 2) * 32;
    int nw = (wid & 3) * 64;
    float acc[2][8][4] = {};
    for (int k0 = 0; k0 < 256; k0 += 16) {
        __syncthreads();
        {
            int k = tid >> 4, col = (tid & 15) * 4;
            *(float4*)&sW[k * GW_STRIDE + col] =
                *(const float4*)&WT[(size_t)(k0 + k) * M + m0 + col];
        }
        for (int i = tid; i < 1024; i += 256) {
            int k = i >> 6, c4 = (i & 63) * 4;
            float4 v = *(const float4*)&Xb[(size_t)(k0 + k) * NPIX + n0 + c4];
            v.x = to_tf32(v.x); v.y = to_tf32(v.y);
            v.z = to_tf32(v.z); v.w = to_tf32(v.w);
            *(float4*)&sX[k * GX_STRIDE + c4] = v;
        }
        __syncthreads();
#pragma unroll
        for (int s = 0; s < 2; s++) {
            int k = 8 * s + tq;
            uint32_t a[2][4];
#pragma unroll
            for (int t = 0; t < 2; t++) {
                int m = mw + 16 * t + g;
                a[t][0] = __float_as_uint(sW[k * GW_STRIDE + m]);
                a[t][1] = __float_as_uint(sW[k * GW_STRIDE + m + 8]);
                a[t][2] = __float_as_uint(sW[(k + 4) * GW_STRIDE + m]);
                a[t][3] = __float_as_uint(sW[(k + 4) * GW_STRIDE + m + 8]);
            }
#pragma unroll
            for (int j = 0; j < 8; j++) {
                int nj = nw + 8 * j + g;
                uint32_t bb[2];
                bb[0] = __float_as_uint(sX[k * GX_STRIDE + nj]);
                bb[1] = __float_as_uint(sX[(k + 4) * GX_STRIDE + nj]);
#pragma unroll
                for (int t = 0; t < 2; t++) mma_tf32(acc[t][j], a[t], bb);
            }
        }
    }
#pragma unroll
    for (int t = 0; t < 2; t++) {
        int o = m0 + mw + 16 * t + g;
#pragma unroll
        for (int j = 0; j < 8; j++) {
            int n = n0 + nw + 8 * j + 2 * tq;
            *(float2*)&Db[(size_t)o * NPIX + n] =
                make_float2(acc[t][j][0], acc[t][j][1]);
            *(float2*)&Db[(size_t)(o + 8) * NPIX + n] =
                make_float2(acc[t][j][2], acc[t][j][3]);
        }
    }
}

// ---------------------------------------------------------------------------
// Attention via tf32 mma, flash-style online softmax. Single-tf32 QK
// (q/k already tf32-limited from single-tf32 qkv projection) and PV.
// Dynamic smem (floats): sK[32][72]@0 (2304), sV[32][72]@2304 (2304),
// sQ[128][36]@4608 (4608, overlaid by sP), sP[8][16][72]@4608 (9216).
// Total 13824 floats = 55296 B.
// ---------------------------------------------------------------------------
#define ATTN_SMEM_BYTES 55296

__global__ __launch_bounds__(256) void attn_mma_kernel(const float* __restrict__ qkv,
                                                       float* __restrict__ ctx) {
    extern __shared__ float sm[];
    float* sK = sm;
    float* sV = sm + 2304;
    float* sQ = sm + 4608;

    int t    = threadIdx.x;
    int wid  = t >> 5, lane = t & 31;
    int g    = lane >> 2;
    int tq   = lane & 3;
    int qw   = wid * 16;
    float* sP = sm + 4608 + wid * (16 * 72);

    int bh = blockIdx.y;
    int b = bh >> 3, h = bh & 7;
    int q0 = blockIdx.x * 128;
    const float* base = qkv + (size_t)b * (3 * CC * NPIX);
    const float* qp = base + (h * HDIM) * NPIX;
    const float* kp = base + (CC + h * HDIM) * NPIX;
    const float* vp = base + (2 * CC + h * HDIM) * NPIX;
    const float scale = 0.17677669529663687f;

    for (int i = t; i < 1024; i += 256) {
        int d  = i >> 5;
        int q4 = (i & 31) * 4;
        float4 v = *(const float4*)&qp[(size_t)d * NPIX + q0 + q4];
        sQ[(q4 + 0) * 36 + d] = v.x * scale;
        sQ[(q4 + 1) * 36 + d] = v.y * scale;
        sQ[(q4 + 2) * 36 + d] = v.z * scale;
        sQ[(q4 + 3) * 36 + d] = v.w * scale;
    }
    __syncthreads();

    uint32_t qf[4][4];
#pragma unroll
    for (int kc = 0; kc < 4; kc++) {
#pragma unroll
        for (int r = 0; r < 4; r++) {
            int row = qw + ((r & 1) ? g + 8 : g);
            int col = 8 * kc + tq + ((r >> 1) ? 4 : 0);
            qf[kc][r] = to_tf32_u(sQ[row * 36 + col]);
        }
    }

    float mrow[2] = {-1e30f, -1e30f};
    float lrow[2] = {0.f, 0.f};
    float oacc[4][4] = {};

    for (int k0 = 0; k0 < NPIX; k0 += 64) {
        __syncthreads();
        for (int i = t; i < 512; i += 256) {
            int d  = i >> 4;
            int c4 = (i & 15) * 4;
            float4 v = *(const float4*)&kp[(size_t)d * NPIX + k0 + c4];
            v.x = to_tf32(v.x); v.y = to_tf32(v.y);
            v.z = to_tf32(v.z); v.w = to_tf32(v.w);
            *(float4*)&sK[d * 72 + c4] = v;
            float4 vv = *(const float4*)&vp[(size_t)d * NPIX + k0 + c4];
            vv.x = to_tf32(vv.x); vv.y = to_tf32(vv.y);
            vv.z = to_tf32(vv.z); vv.w = to_tf32(vv.w);
            *(float4*)&sV[d * 72 + c4] = vv;
        }
        __syncthreads();

        float sv[8][4];
#pragma unroll
        for (int nt = 0; nt < 8; nt++) {
            float acc[4] = {0.f, 0.f, 0.f, 0.f};
#pragma unroll
            for (int kc = 0; kc < 4; kc++) {
                int i0 = (8 * kc + tq) * 72 + 8 * nt + g;
                int i1 = (8 * kc + tq + 4) * 72 + 8 * nt + g;
                uint32_t bb[2] = {__float_as_uint(sK[i0]), __float_as_uint(sK[i1])};
                mma_tf32(acc, qf[kc], bb);
            }
            sv[nt][0] = acc[0]; sv[nt][1] = acc[1];
            sv[nt][2] = acc[2]; sv[nt][3] = acc[3];
        }

        float tm0 = -1e30f, tm1 = -1e30f;
#pragma unroll
        for (int nt = 0; nt < 8; nt++) {
            tm0 = fmaxf(tm0, fmaxf(sv[nt][0], sv[nt][1]));
            tm1 = fmaxf(tm1, fmaxf(sv[nt][2], sv[nt][3]));
        }
        tm0 = fmaxf(tm0, __shfl_xor_sync(0xffffffffu, tm0, 1));
        tm0 = fmaxf(tm0, __shfl_xor_sync(0xffffffffu, tm0, 2));
        tm1 = fmaxf(tm1, __shfl_xor_sync(0xffffffffu, tm1, 1));
        tm1 = fmaxf(tm1, __shfl_xor_sync(0xffffffffu, tm1, 2));
        float m0n = fmaxf(mrow[0], tm0);
        float m1n = fmaxf(mrow[1], tm1);
        float c0 = __expf(mrow[0] - m0n);
        float c1 = __expf(mrow[1] - m1n);
        mrow[0] = m0n; mrow[1] = m1n;
        lrow[0] *= c0; lrow[1] *= c1;
#pragma unroll
        for (int dt = 0; dt < 4; dt++) {
            oacc[dt][0] *= c0; oacc[dt][1] *= c0;
            oacc[dt][2] *= c1; oacc[dt][3] *= c1;
        }
#pragma unroll
        for (int nt = 0; nt < 8; nt++) {
            float p0 = __expf(sv[nt][0] - m0n);
            float p1 = __expf(sv[nt][1] - m0n);
            float p2 = __expf(sv[nt][2] - m1n);
            float p3 = __expf(sv[nt][3] - m1n);
            lrow[0] += p0 + p1;
            lrow[1] += p2 + p3;
            *(float2*)&sP[g * 72 + 8 * nt + 2 * tq] =
                make_float2(to_tf32(p0), to_tf32(p1));
            *(float2*)&sP[(g + 8) * 72 + 8 * nt + 2 * tq] =
                make_float2(to_tf32(p2), to_tf32(p3));
        }
        __syncwarp();

#pragma unroll
        for (int kc = 0; kc < 8; kc++) {
            uint32_t a[4];
            a[0] = __float_as_uint(sP[g * 72 + 8 * kc + tq]);
            a[1] = __float_as_uint(sP[(g + 8) * 72 + 8 * kc + tq]);
            a[2] = __float_as_uint(sP[g * 72 + 8 * kc + tq + 4]);
            a[3] = __float_as_uint(sP[(g + 8) * 72 + 8 * kc + tq + 4]);
#pragma unroll
            for (int dt = 0; dt < 4; dt++) {
                uint32_t bb[2];
                bb[0] = __float_as_uint(sV[(8 * dt + g) * 72 + 8 * kc + tq]);
                bb[1] = __float_as_uint(sV[(8 * dt + g) * 72 + 8 * kc + tq + 4]);
                mma_tf32(oacc[dt], a, bb);
            }
        }
        __syncwarp();
    }

    lrow[0] += __shfl_xor_sync(0xffffffffu, lrow[0], 1);
    lrow[0] += __shfl_xor_sync(0xffffffffu, lrow[0], 2);
    lrow[1] += __shfl_xor_sync(0xffffffffu, lrow[1], 1);
    lrow[1] += __shfl_xor_sync(0xffffffffu, lrow[1], 2);
    float inv0 = 1.f / lrow[0];
    float inv1 = 1.f / lrow[1];
    float* cp = ctx + (size_t)b * (CC * NPIX) + (size_t)(h * HDIM) * NPIX;
    int qr0 = q0 + qw + g;
    int qr1 = qr0 + 8;
#pragma unroll
    for (int dt = 0; dt < 4; dt++) {
        int d0 = 8 * dt + 2 * tq;
        cp[(size_t)d0 * NPIX + qr0]       = oacc[dt][0] * inv0;
        cp[(size_t)(d0 + 1) * NPIX + qr0] = oacc[dt][1] * inv0;
        cp[(size_t)d0 * NPIX + qr1]       = oacc[dt][2] * inv1;
        cp[(size_t)(d0 + 1) * NPIX + qr1] = oacc[dt][3] * inv1;
    }
}

// ---------------------------------------------------------------------------
// Conv via tf32 mma (unchanged from R7 - passing): zero-padded patch + 4-tap
// A groups, double-buffered. CTA M=64 x N=256, 2 CTAs/SM.
// ---------------------------------------------------------------------------
#define PPW 40
#define PSTR 568
#define AT_STRIDE 72
#define AT_TAP (16 * AT_STRIDE)
#define AT_GRP (4 * AT_TAP)
#define CONV_SMEM_FLOATS (16 * PSTR + 2 * AT_GRP)
#define CONV_SMEM_BYTES (CONV_SMEM_FLOATS * 4)

__global__ __launch_bounds__(256, 2) void conv_mma_kernel(const float* __restrict__ in) {
    extern __shared__ float cs[];
    float* sPatch = cs;
    float* sA     = cs + 16 * PSTR;

    int z = blockIdx.z;
    int ks, tap0, tap1, slot, wtoff, b;
    if (z < 32) {
        int s = z >> 3; b = z & 7;
        ks = 7; tap0 = (s * 49) >> 2; tap1 = ((s + 1) * 49) >> 2;
        slot = 4 + s; wtoff = WT_OFF7;
    } else if (z < 48) {
        int s = (z - 32) >> 3; b = z & 7;
        ks = 5; tap0 = (s * 25) >> 1; tap1 = ((s + 1) * 25) >> 1;
        slot = 2 + s; wtoff = WT_OFF5;
    } else if (z < 56) {
        b = z - 48; ks = 3; tap0 = 0; tap1 = 9; slot = 1; wtoff = WT_OFF3;
    } else {
        b = z - 56; ks = 1; tap0 = 0; tap1 = 1; slot = 0; wtoff = WT_OFF1;
    }
    const int P = ks >> 1;
    const int rows = 8 + 2 * P;

    int n0 = blockIdx.x * 256;
    int m0 = blockIdx.y * 64;
    int r0 = n0 >> 5;
    int tid = threadIdx.x;
    int wid = tid >> 5, lane = tid & 31;
    int mw = (wid >> 2) * 32;
    int nw = (wid & 3) * 64;
    int lg = lane >> 2;
    int lk = lane & 3;

    for (int i = tid; i < 16 * PSTR / 4; i += 256)
        *(float4*)&sPatch[i * 4] = make_float4(0.f, 0.f, 0.f, 0.f);

    int njoff[8];
#pragma unroll
    for (int j = 0; j < 8; j++) {
        int n = nw + 8 * j + lg;
        njoff[j] = (n >> 5) * PPW + (n & 31) + 4;
    }

    const float* inb = in + (size_t)b * (CC * NPIX);
    const float* wbase = g_wT + (size_t)wtoff;
    float acc[2][8][4] = {};

    for (int c0 = 0; c0 < 256; c0 += 16) {
        __syncthreads();
        {
            int per_plane = rows * 8;
            int total = 16 * per_plane;
            for (int i = tid; i < total; i += 256) {
                int c  = i / per_plane;
                int rm = i - c * per_plane;
                int py = rm >> 3;
                int xq = (rm & 7) * 4;
                int iy = r0 - P + py;
                if ((unsigned)iy < 32u) {
                    float4 v = *(const float4*)&inb[(size_t)(c0 + c) * NPIX + iy * 32 + xq];
                    v.x = to_tf32(v.x); v.y = to_tf32(v.y);
                    v.z = to_tf32(v.z); v.w = to_tf32(v.w);
                    *(float4*)&sPatch[c * PSTR + py * PPW + 4 + xq] = v;
                }
            }
        }
        {
            int gcnt = tap1 - tap0; if (gcnt > 4) gcnt = 4;
            for (int i = tid; i < gcnt * 256; i += 256) {
                int tp = i >> 8;
                int k = (i >> 4) & 15, col = (i & 15) * 4;
                *(float4*)&sA[tp * AT_TAP + k * AT_STRIDE + col] =
                    *(const float4*)&wbase[(size_t)(tap0 + tp) * (CC * CC) +
                                           (size_t)(c0 + k) * CC + m0 + col];
            }
        }
        __syncthreads();

        int buf = 0;
        for (int g0 = tap0; g0 < tap1; g0 += 4) {
            int gcnt = tap1 - g0; if (gcnt > 4) gcnt = 4;
            int h0 = g0 + 4;
            if (h0 < tap1) {
                int hcnt = tap1 - h0; if (hcnt > 4) hcnt = 4;
                float* dst = sA + (buf ^ 1) * AT_GRP;
                for (int i = tid; i < hcnt * 256; i += 256) {
                    int tp = i >> 8;
                    int k = (i >> 4) & 15, col = (i & 15) * 4;
                    *(float4*)&dst[tp * AT_TAP + k * AT_STRIDE + col] =
                        *(const float4*)&wbase[(size_t)(h0 + tp) * (CC * CC) +
                                               (size_t)(c0 + k) * CC + m0 + col];
                }
            }
            const uint32_t* Pp = (const uint32_t*)sPatch;
            for (int ti = 0; ti < gcnt; ti++) {
                int tap = g0 + ti;
                int ty = tap / ks;
                int tx = tap - ty * ks;
                int tadd = ty * PPW + tx - P;
                const uint32_t* A =
                    (const uint32_t*)(sA + buf * AT_GRP + ti * AT_TAP);
#pragma unroll
                for (int s = 0; s < 2; s++) {
                    int k = s * 8 + lk;
                    uint32_t a[2][4];
#pragma unroll
                    for (int t = 0; t < 2; t++) {
                        int m = mw + 16 * t + lg;
                        a[t][0] = A[k * AT_STRIDE + m];
                        a[t][1] = A[k * AT_STRIDE + m + 8];
                        a[t][2] = A[(k + 4) * AT_STRIDE + m];
                        a[t][3] = A[(k + 4) * AT_STRIDE + m + 8];
                    }
                    uint32_t bb[8][2];
#pragma unroll
                    for (int j = 0; j < 8; j++) {
                        int off = k * PSTR + njoff[j] + tadd;
                        bb[j][0] = Pp[off];
                        bb[j][1] = Pp[off + 4 * PSTR];
                    }
#pragma unroll
                    for (int t = 0; t < 2; t++)
#pragma unroll
                        for (int j = 0; j < 8; j++) mma_tf32(acc[t][j], a[t], bb[j]);
                }
            }
            __syncthreads();
            buf ^= 1;
        }
    }

    float* pp = g_part + (size_t)slot * (BATCH * CC * NPIX) + (size_t)b * (CC * NPIX);
#pragma unroll
    for (int t = 0; t < 2; t++) {
        int o = m0 + mw + 16 * t + lg;
#pragma unroll
        for (int j = 0; j < 8; j++) {
            int n = n0 + nw + 8 * j + 2 * lk;
            *(float2*)&pp[(size_t)o * NPIX + n] =
                make_float2(acc[t][j][0], acc[t][j][1]);
            *(float2*)&pp[(size_t)(o + 8) * NPIX + n] =
                make_float2(acc[t][j][2], acc[t][j][3]);
        }
    }
}

// ---------------------------------------------------------------------------
// BN constants
// ---------------------------------------------------------------------------
__global__ void bnprep_kernel(const float* __restrict__ conv_b,
                              const float* __restrict__ gamma,
                              const float* __restrict__ beta,
                              const float* __restrict__ mean,
                              const float* __restrict__ var) {
    int i = threadIdx.x;
    float inv = gamma[i] * rsqrtf(var[i] + 1e-5f);
    g_bnA[i] = inv;
    g_bnB[i] = beta[i] - mean[i] * inv + conv_b[i] * inv;
}

// ---------------------------------------------------------------------------
// Epilogue: sum split-K partials, BN + ReLU -> feats
// ---------------------------------------------------------------------------
__global__ __launch_bounds__(256) void epi_kernel(float* __restrict__ feats) {
    int row = blockIdx.x;
    int k   = row >> 11;
    int bc  = row & 2047;
    int o   = bc & 255;
    float Aa = g_bnA[k * 256 + o];
    float Bb = g_bnB[k * 256 + o];
    size_t base = (size_t)bc * NPIX + threadIdx.x * 4;
    const size_t SL = (size_t)BATCH * CC * NPIX;
    float4 s;
    if (k == 0) {
        s = *(const float4*)&g_part[base];
    } else if (k == 1) {
        s = *(const float4*)&g_part[SL + base];
    } else if (k == 2) {
        float4 s0 = *(const float4*)&g_part[2 * SL + base];
        float4 s1 = *(const float4*)&g_part[3 * SL + base];
        s = make_float4(s0.x + s1.x, s0.y + s1.y, s0.z + s1.z, s0.w + s1.w);
    } else {
        float4 s0 = *(const float4*)&g_part[4 * SL + base];
        float4 s1 = *(const float4*)&g_part[5 * SL + base];
        float4 s2 = *(const float4*)&g_part[6 * SL + base];
        float4 s3 = *(const float4*)&g_part[7 * SL + base];
        s = make_float4(s0.x + s1.x + s2.x + s3.x, s0.y + s1.y + s2.y + s3.y,
                        s0.z + s1.z + s2.z + s3.z, s0.w + s1.w + s2.w + s3.w);
    }
    float4 v;
    v.x = fmaxf(s.x * Aa + Bb, 0.f);
    v.y = fmaxf(s.y * Aa + Bb, 0.f);
    v.z = fmaxf(s.z * Aa + Bb, 0.f);
    v.w = fmaxf(s.w * Aa + Bb, 0.f);
    *(float4*)&feats[(size_t)k * SL + base] = v;
}

// ---------------------------------------------------------------------------
// S[b,c] = mean over pixels of sum-over-branches of feats
// ---------------------------------------------------------------------------
__global__ __launch_bounds__(128) void sreduce_kernel(float* __restrict__ S) {
    int bc = blockIdx.x;
    int t  = threadIdx.x;
    float s = 0.f;
#pragma unroll
    for (int k = 0; k < 4; k++) {
        const float* p = g_feats + ((size_t)k * (BATCH * CC) + bc) * NPIX;
        for (int n = t; n < NPIX; n += 128) s += p[n];
    }
#pragma unroll
    for (int off = 16; off; off >>= 1) s += __shfl_down_sync(0xffffffffu, s, off);
    __shared__ float red[4];
    if ((t & 31) == 0) red[t >> 5] = s;
    __syncthreads();
    if (t == 0) S[bc] = (red[0] + red[1] + red[2] + red[3]) * (1.f / 1024.f);
}

// ---------------------------------------------------------------------------
// fc -> per-branch logits -> softmax over branches
// ---------------------------------------------------------------------------
__global__ __launch_bounds__(256) void select_kernel(
    const float* __restrict__ S, const float* __restrict__ fc_w,
    const float* __restrict__ fc_b, const float* __restrict__ fcs_w,
    const float* __restrict__ fcs_b, float* __restrict__ attnw) {
    __shared__ float Ss[BATCH * CC];
    __shared__ float Zs[BATCH * DDIM];
    int t = threadIdx.x;
    for (int i = t; i < BATCH * CC; i += 256) Ss[i] = S[i];
    __syncthreads();
    {
        int b = t >> 5, d = t & 31;
        float z = fc_b[d];
        const float* wr = fc_w + d * CC;
        for (int c = 0; c < CC; c++) z += Ss[b * CC + c] * wr[c];
        Zs[b * DDIM + d] = z;
    }
    __syncthreads();
    for (int it = 0; it < 8; it++) {
        int idx = it * 256 + t;
        int b = idx >> 8, c = idx & 255;
        float lg[4];
#pragma unroll
        for (int k = 0; k < 4; k++) {
            float v = fcs_b[k * CC + c];
            const float* wp = fcs_w + ((size_t)k * CC + c) * DDIM;
#pragma unroll
            for (int d = 0; d < DDIM; d++) v += wp[d] * Zs[b * DDIM + d];
            lg[k] = v;
        }
        float mx  = fmaxf(fmaxf(lg[0], lg[1]), fmaxf(lg[2], lg[3]));
        float e0 = __expf(lg[0] - mx), e1 = __expf(lg[1] - mx);
        float e2 = __expf(lg[2] - mx), e3 = __expf(lg[3] - mx);
        float inv = 1.f / (e0 + e1 + e2 + e3);
        attnw[0 * 2048 + idx] = e0 * inv;
        attnw[1 * 2048 + idx] = e1 * inv;
        attnw[2 * 2048 + idx] = e2 * inv;
        attnw[3 * 2048 + idx] = e3 * inv;
    }
}

// ---------------------------------------------------------------------------
// V = sum_k attn[k,b,c] * feats[k,b,c,:]
// ---------------------------------------------------------------------------
__global__ __launch_bounds__(256) void combine_kernel(const float* __restrict__ attnw,
                                                      float* __restrict__ out) {
    int idx = blockIdx.x * 256 + threadIdx.x;
    if (idx >= BATCH * CC * NPIX) return;
    int bc = idx >> 10;
    const size_t KSTRIDE = (size_t)BATCH * CC * NPIX;
    float v = attnw[bc]        * g_feats[idx] +
              attnw[2048 + bc] * g_feats[KSTRIDE + idx] +
              attnw[4096 + bc] * g_feats[2 * KSTRIDE + idx] +
              attnw[6144 + bc] * g_feats[3 * KSTRIDE + idx];
    out[idx] = v;
}

// ---------------------------------------------------------------------------
// Launch
// ---------------------------------------------------------------------------
extern "C" void kernel_launch(void* const* d_in, const int* in_sizes, int n_in,
                              void* d_out, int out_size) {
    const float* x      = (const float*)d_in[0];
    const float* qkv_w  = (const float*)d_in[1];
    const float* out_w  = (const float*)d_in[2];
    const float* w1     = (const float*)d_in[3];
    const float* w3     = (const float*)d_in[4];
    const float* w5     = (const float*)d_in[5];
    const float* w7     = (const float*)d_in[6];
    const float* conv_b = (const float*)d_in[7];
    const float* gamma  = (const float*)d_in[8];
    const float* beta   = (const float*)d_in[9];
    const float* mean   = (const float*)d_in[10];
    const float* var    = (const float*)d_in[11];
    const float* fc_w   = (const float*)d_in[12];
    const float* fc_b   = (const float*)d_in[13];
    const float* fcs_w  = (const float*)d_in[14];
    const float* fcs_b  = (const float*)d_in[15];
    float* out = (float*)d_out;

    float *p_qkv, *p_ctx, *p_ao, *p_feats, *p_S, *p_attnw;
    float *p_qw, *p_ow;
    cudaGetSymbolAddress((void**)&p_qkv,   g_qkv);
    cudaGetSymbolAddress((void**)&p_ctx,   g_ctx);
    cudaGetSymbolAddress((void**)&p_ao,    g_ao);
    cudaGetSymbolAddress((void**)&p_feats, g_feats);
    cudaGetSymbolAddress((void**)&p_S,     g_S);
    cudaGetSymbolAddress((void**)&p_attnw, g_attnw);
    cudaGetSymbolAddress((void**)&p_qw,    g_qkvwT);
    cudaGetSymbolAddress((void**)&p_ow,    g_outwT);

    static int attr_set = 0;
    if (!attr_set) {
        cudaFuncSetAttribute(attn_mma_kernel,
                             cudaFuncAttributeMaxDynamicSharedMemorySize,
                             ATTN_SMEM_BYTES);
        cudaFuncSetAttribute(conv_mma_kernel,
                             cudaFuncAttributeMaxDynamicSharedMemorySize,
                             CONV_SMEM_BYTES);
        attr_set = 1;
    }

    wtrans_kernel<<<21504, 256>>>(w1, w3, w5, w7);
    wsplit_kernel<<<1024, 256>>>(qkv_w, out_w);
    bnprep_kernel<<<1, 1024>>>(conv_b, gamma, beta, mean, var);

    gemm_mma_kernel<<<dim3(4, 12, 8), 256>>>(p_qw, x, p_qkv, 768);
    attn_mma_kernel<<<dim3(8, 64), 256, ATTN_SMEM_BYTES>>>(p_qkv, p_ctx);
    gemm_mma_kernel<<<dim3(4, 4, 8), 256>>>(p_ow, p_ctx, p_ao, 256);

    conv_mma_kernel<<<dim3(4, 4, 64), 256, CONV_SMEM_BYTES>>>(p_ao);
    epi_kernel<<<4 * 2048, 256>>>(p_feats);

    sreduce_kernel<<<2048, 128>>>(p_S);
    select_kernel<<<1, 256>>>(p_S, fc_w, fc_b, fcs_w, fcs_b, p_attnw);
    combine_kernel<<<8192, 256>>>(p_attnw, out);
}

// round 10
// speedup vs baseline: 3.9421x; 1.0401x over previous
#include <cuda_runtime.h>
#include <math_constants.h>
#include <cstdint>

#define BATCH 8
#define CC 256
#define NPIX 1024
#define NHEAD 8
#define HDIM 32
#define DDIM 32

// Scratch (device globals)
__device__ float g_qkv[BATCH * 3 * CC * NPIX];
__device__ float g_ctx[BATCH * CC * NPIX];
__device__ float g_ao[BATCH * CC * NPIX];
__device__ float g_feats[4 * BATCH * CC * NPIX];
__device__ float2 g_wT2[2752512];                 // conv weights [tap][cpair][o] f2
__device__ float g_part[2 * BATCH * CC * NPIX];   // k7 split-K partials
__device__ float g_bnA[4 * CC];
__device__ float g_bnB[4 * CC];
__device__ float g_S[BATCH * CC];
__device__ float g_attnw[4 * BATCH * CC];
__device__ float g_qkvwT[768 * 256];
__device__ float g_outwT[256 * 256];

// f2-unit branch offsets: k1@0(1 tap), k3@32768(9), k5@327680(25), k7@1146880(49)
#define WT2_OFF1 0
#define WT2_OFF3 32768
#define WT2_OFF5 327680
#define WT2_OFF7 1146880

__device__ __forceinline__ float to_tf32(float x) {
    uint32_t y;
    asm("cvt.rna.tf32.f32 %0, %1;" : "=r"(y) : "f"(x));
    return __uint_as_float(y);
}
__device__ __forceinline__ uint32_t to_tf32_u(float x) {
    uint32_t y;
    asm("cvt.rna.tf32.f32 %0, %1;" : "=r"(y) : "f"(x));
    return y;
}

__device__ __forceinline__ void mma_tf32(float* d, const uint32_t* a, const uint32_t* b) {
    asm volatile(
        "mma.sync.aligned.m16n8k8.row.col.f32.tf32.tf32.f32 "
        "{%0,%1,%2,%3}, {%4,%5,%6,%7}, {%8,%9}, {%0,%1,%2,%3};"
        : "+f"(d[0]), "+f"(d[1]), "+f"(d[2]), "+f"(d[3])
        : "r"(a[0]), "r"(a[1]), "r"(a[2]), "r"(a[3]), "r"(b[0]), "r"(b[1]));
}

// ---------------------------------------------------------------------------
// Repack conv weights OIHW -> [tap][cpair][o] float2 (channels c, c+4), tf32
// cpair cp: chunk = cp>>3, pi = cp&7, s = pi>>2, lk = pi&3
//   c_x = chunk*16 + s*8 + lk ; c_y = c_x + 4
// ---------------------------------------------------------------------------
__global__ void wtrans_kernel(const float* __restrict__ w1, const float* __restrict__ w3,
                              const float* __restrict__ w5, const float* __restrict__ w7) {
    int idx = blockIdx.x * 256 + threadIdx.x;
    if (idx >= 2752512) return;
    const float* src;
    int k2, base;
    if (idx < 327680)       { if (idx < 32768) { src = w1; k2 = 1;  base = 0; }
                              else              { src = w3; k2 = 9;  base = 32768; } }
    else if (idx < 1146880) { src = w5; k2 = 25; base = 327680; }
    else                    { src = w7; k2 = 49; base = 1146880; }
    int r   = idx - base;
    int o   = r & 255;
    int cp  = (r >> 8) & 127;
    int tap = r >> 15;
    int chunk = cp >> 3, pi = cp & 7;
    int cx = chunk * 16 + (pi >> 2) * 8 + (pi & 3);
    float vx = src[(o * 256 + cx) * k2 + tap];
    float vy = src[(o * 256 + cx + 4) * k2 + tap];
    g_wT2[idx] = make_float2(to_tf32(vx), to_tf32(vy));
}

// ---------------------------------------------------------------------------
// Transpose projection weights: W[m][k] -> WT[k][m], tf32
// ---------------------------------------------------------------------------
__global__ void wsplit_kernel(const float* __restrict__ qkv_w,
                              const float* __restrict__ out_w) {
    int idx = blockIdx.x * 256 + threadIdx.x;
    if (idx < 196608) {
        int m = idx / 256, k = idx & 255;
        g_qkvwT[k * 768 + m] = to_tf32(qkv_w[idx]);
    } else {
        int r = idx - 196608;
        int m = r / 256, k = r & 255;
        g_outwT[k * 256 + m] = to_tf32(out_w[r]);
    }
}

// ---------------------------------------------------------------------------
// GEMM via tf32 mma (single tf32). 3 CTAs/SM for latency hiding.
// ---------------------------------------------------------------------------
#define GW_STRIDE 72
#define GX_STRIDE 264

__global__ __launch_bounds__(256, 3) void gemm_mma_kernel(
    const float* __restrict__ WT, const float* __restrict__ X,
    float* __restrict__ D, int M) {
    __shared__ float sW[16 * GW_STRIDE];
    __shared__ float sX[16 * GX_STRIDE];
    int tid = threadIdx.x;
    int n0 = blockIdx.x * 256, m0 = blockIdx.y * 64, b = blockIdx.z;
    const float* Xb = X + (size_t)b * 256 * NPIX;
    float*       Db = D + (size_t)b * M * NPIX;
    int wid = tid >> 5, lane = tid & 31;
    int g = lane >> 2, tq = lane & 3;
    int mw = (wid >> 2) * 32;
    int nw = (wid & 3) * 64;
    float acc[2][8][4] = {};
    for (int k0 = 0; k0 < 256; k0 += 16) {
        __syncthreads();
        {
            int k = tid >> 4, col = (tid & 15) * 4;
            *(float4*)&sW[k * GW_STRIDE + col] =
                *(const float4*)&WT[(size_t)(k0 + k) * M + m0 + col];
        }
        for (int i = tid; i < 1024; i += 256) {
            int k = i >> 6, c4 = (i & 63) * 4;
            float4 v = *(const float4*)&Xb[(size_t)(k0 + k) * NPIX + n0 + c4];
            v.x = to_tf32(v.x); v.y = to_tf32(v.y);
            v.z = to_tf32(v.z); v.w = to_tf32(v.w);
            *(float4*)&sX[k * GX_STRIDE + c4] = v;
        }
        __syncthreads();
#pragma unroll
        for (int s = 0; s < 2; s++) {
            int k = 8 * s + tq;
            uint32_t a[2][4];
#pragma unroll
            for (int t = 0; t < 2; t++) {
                int m = mw + 16 * t + g;
                a[t][0] = __float_as_uint(sW[k * GW_STRIDE + m]);
                a[t][1] = __float_as_uint(sW[k * GW_STRIDE + m + 8]);
                a[t][2] = __float_as_uint(sW[(k + 4) * GW_STRIDE + m]);
                a[t][3] = __float_as_uint(sW[(k + 4) * GW_STRIDE + m + 8]);
            }
#pragma unroll
            for (int j = 0; j < 8; j++) {
                int nj = nw + 8 * j + g;
                uint32_t bb[2];
                bb[0] = __float_as_uint(sX[k * GX_STRIDE + nj]);
                bb[1] = __float_as_uint(sX[(k + 4) * GX_STRIDE + nj]);
#pragma unroll
                for (int t = 0; t < 2; t++) mma_tf32(acc[t][j], a[t], bb);
            }
        }
    }
#pragma unroll
    for (int t = 0; t < 2; t++) {
        int o = m0 + mw + 16 * t + g;
#pragma unroll
        for (int j = 0; j < 8; j++) {
            int n = n0 + nw + 8 * j + 2 * tq;
            *(float2*)&Db[(size_t)o * NPIX + n] =
                make_float2(acc[t][j][0], acc[t][j][1]);
            *(float2*)&Db[(size_t)(o + 8) * NPIX + n] =
                make_float2(acc[t][j][2], acc[t][j][3]);
        }
    }
}

// ---------------------------------------------------------------------------
// Attention via tf32 mma (unchanged - passing)
// ---------------------------------------------------------------------------
#define ATTN_SMEM_BYTES 55296

__global__ __launch_bounds__(256) void attn_mma_kernel(const float* __restrict__ qkv,
                                                       float* __restrict__ ctx) {
    extern __shared__ float sm[];
    float* sK = sm;
    float* sV = sm + 2304;
    float* sQ = sm + 4608;

    int t    = threadIdx.x;
    int wid  = t >> 5, lane = t & 31;
    int g    = lane >> 2;
    int tq   = lane & 3;
    int qw   = wid * 16;
    float* sP = sm + 4608 + wid * (16 * 72);

    int bh = blockIdx.y;
    int b = bh >> 3, h = bh & 7;
    int q0 = blockIdx.x * 128;
    const float* base = qkv + (size_t)b * (3 * CC * NPIX);
    const float* qp = base + (h * HDIM) * NPIX;
    const float* kp = base + (CC + h * HDIM) * NPIX;
    const float* vp = base + (2 * CC + h * HDIM) * NPIX;
    const float scale = 0.17677669529663687f;

    for (int i = t; i < 1024; i += 256) {
        int d  = i >> 5;
        int q4 = (i & 31) * 4;
        float4 v = *(const float4*)&qp[(size_t)d * NPIX + q0 + q4];
        sQ[(q4 + 0) * 36 + d] = v.x * scale;
        sQ[(q4 + 1) * 36 + d] = v.y * scale;
        sQ[(q4 + 2) * 36 + d] = v.z * scale;
        sQ[(q4 + 3) * 36 + d] = v.w * scale;
    }
    __syncthreads();

    uint32_t qf[4][4];
#pragma unroll
    for (int kc = 0; kc < 4; kc++) {
#pragma unroll
        for (int r = 0; r < 4; r++) {
            int row = qw + ((r & 1) ? g + 8 : g);
            int col = 8 * kc + tq + ((r >> 1) ? 4 : 0);
            qf[kc][r] = to_tf32_u(sQ[row * 36 + col]);
        }
    }

    float mrow[2] = {-1e30f, -1e30f};
    float lrow[2] = {0.f, 0.f};
    float oacc[4][4] = {};

    for (int k0 = 0; k0 < NPIX; k0 += 64) {
        __syncthreads();
        for (int i = t; i < 512; i += 256) {
            int d  = i >> 4;
            int c4 = (i & 15) * 4;
            float4 v = *(const float4*)&kp[(size_t)d * NPIX + k0 + c4];
            v.x = to_tf32(v.x); v.y = to_tf32(v.y);
            v.z = to_tf32(v.z); v.w = to_tf32(v.w);
            *(float4*)&sK[d * 72 + c4] = v;
            float4 vv = *(const float4*)&vp[(size_t)d * NPIX + k0 + c4];
            vv.x = to_tf32(vv.x); vv.y = to_tf32(vv.y);
            vv.z = to_tf32(vv.z); vv.w = to_tf32(vv.w);
            *(float4*)&sV[d * 72 + c4] = vv;
        }
        __syncthreads();

        float sv[8][4];
#pragma unroll
        for (int nt = 0; nt < 8; nt++) {
            float acc[4] = {0.f, 0.f, 0.f, 0.f};
#pragma unroll
            for (int kc = 0; kc < 4; kc++) {
                int i0 = (8 * kc + tq) * 72 + 8 * nt + g;
                int i1 = (8 * kc + tq + 4) * 72 + 8 * nt + g;
                uint32_t bb[2] = {__float_as_uint(sK[i0]), __float_as_uint(sK[i1])};
                mma_tf32(acc, qf[kc], bb);
            }
            sv[nt][0] = acc[0]; sv[nt][1] = acc[1];
            sv[nt][2] = acc[2]; sv[nt][3] = acc[3];
        }

        float tm0 = -1e30f, tm1 = -1e30f;
#pragma unroll
        for (int nt = 0; nt < 8; nt++) {
            tm0 = fmaxf(tm0, fmaxf(sv[nt][0], sv[nt][1]));
            tm1 = fmaxf(tm1, fmaxf(sv[nt][2], sv[nt][3]));
        }
        tm0 = fmaxf(tm0, __shfl_xor_sync(0xffffffffu, tm0, 1));
        tm0 = fmaxf(tm0, __shfl_xor_sync(0xffffffffu, tm0, 2));
        tm1 = fmaxf(tm1, __shfl_xor_sync(0xffffffffu, tm1, 1));
        tm1 = fmaxf(tm1, __shfl_xor_sync(0xffffffffu, tm1, 2));
        float m0n = fmaxf(mrow[0], tm0);
        float m1n = fmaxf(mrow[1], tm1);
        float c0 = __expf(mrow[0] - m0n);
        float c1 = __expf(mrow[1] - m1n);
        mrow[0] = m0n; mrow[1] = m1n;
        lrow[0] *= c0; lrow[1] *= c1;
#pragma unroll
        for (int dt = 0; dt < 4; dt++) {
            oacc[dt][0] *= c0; oacc[dt][1] *= c0;
            oacc[dt][2] *= c1; oacc[dt][3] *= c1;
        }
#pragma unroll
        for (int nt = 0; nt < 8; nt++) {
            float p0 = __expf(sv[nt][0] - m0n);
            float p1 = __expf(sv[nt][1] - m0n);
            float p2 = __expf(sv[nt][2] - m1n);
            float p3 = __expf(sv[nt][3] - m1n);
            lrow[0] += p0 + p1;
            lrow[1] += p2 + p3;
            *(float2*)&sP[g * 72 + 8 * nt + 2 * tq] =
                make_float2(to_tf32(p0), to_tf32(p1));
            *(float2*)&sP[(g + 8) * 72 + 8 * nt + 2 * tq] =
                make_float2(to_tf32(p2), to_tf32(p3));
        }
        __syncwarp();

#pragma unroll
        for (int kc = 0; kc < 8; kc++) {
            uint32_t a[4];
            a[0] = __float_as_uint(sP[g * 72 + 8 * kc + tq]);
            a[1] = __float_as_uint(sP[(g + 8) * 72 + 8 * kc + tq]);
            a[2] = __float_as_uint(sP[g * 72 + 8 * kc + tq + 4]);
            a[3] = __float_as_uint(sP[(g + 8) * 72 + 8 * kc + tq + 4]);
#pragma unroll
            for (int dt = 0; dt < 4; dt++) {
                uint32_t bb[2];
                bb[0] = __float_as_uint(sV[(8 * dt + g) * 72 + 8 * kc + tq]);
                bb[1] = __float_as_uint(sV[(8 * dt + g) * 72 + 8 * kc + tq + 4]);
                mma_tf32(oacc[dt], a, bb);
            }
        }
        __syncwarp();
    }

    lrow[0] += __shfl_xor_sync(0xffffffffu, lrow[0], 1);
    lrow[0] += __shfl_xor_sync(0xffffffffu, lrow[0], 2);
    lrow[1] += __shfl_xor_sync(0xffffffffu, lrow[1], 1);
    lrow[1] += __shfl_xor_sync(0xffffffffu, lrow[1], 2);
    float inv0 = 1.f / lrow[0];
    float inv1 = 1.f / lrow[1];
    float* cp = ctx + (size_t)b * (CC * NPIX) + (size_t)(h * HDIM) * NPIX;
    int qr0 = q0 + qw + g;
    int qr1 = qr0 + 8;
#pragma unroll
    for (int dt = 0; dt < 4; dt++) {
        int d0 = 8 * dt + 2 * tq;
        cp[(size_t)d0 * NPIX + qr0]       = oacc[dt][0] * inv0;
        cp[(size_t)(d0 + 1) * NPIX + qr0] = oacc[dt][1] * inv0;
        cp[(size_t)d0 * NPIX + qr1]       = oacc[dt][2] * inv1;
        cp[(size_t)(d0 + 1) * NPIX + qr1] = oacc[dt][3] * inv1;
    }
}

// ---------------------------------------------------------------------------
// Conv v4: pair-plane float2 layout -> all fragment loads are LDS.64.
//   Patch: 8 planes (pi = s*4+lk) of [14 rows x 40 cols] float2 (ch k, k+4),
//          plane stride 564 f2. A: [pi][64 o] float2, stride 68 f2.
// k1/k3/k5: fused BN+ReLU epilogue -> feats. k7: 2 splits -> g_part, epi.
// ---------------------------------------------------------------------------
#define PL2 564                       // patch plane stride (f2)
#define A2S 68                        // A plane stride (f2)
#define A2_TAP (8 * A2S)              // 544 f2 per tap
#define A2_GRP (4 * A2_TAP)           // 4-tap group
#define CONV_SMEM_F2 (8 * PL2 + 2 * A2_GRP)    // 4512 + 4352 = 8864
#define CONV_SMEM_BYTES (CONV_SMEM_F2 * 8)     // 70912

__global__ __launch_bounds__(256, 2) void conv_mma_kernel(const float* __restrict__ in,
                                                          float* __restrict__ feats) {
    extern __shared__ float2 cs2[];
    float2* sPatch = cs2;
    float2* sA     = cs2 + 8 * PL2;

    int z = blockIdx.z;
    int ks, tap0, tap1, slot, kb, b;
    size_t wtoff2;
    bool fused;
    if (z < 16) {            // k7: 2 splits
        int s = z >> 3; b = z & 7;
        ks = 7; tap0 = s ? 24 : 0; tap1 = s ? 49 : 24;
        slot = s; kb = 3; fused = false; wtoff2 = WT2_OFF7;
    } else if (z < 24) {     // k5 fused
        b = z - 16; ks = 5; tap0 = 0; tap1 = 25;
        slot = 0; kb = 2; fused = true; wtoff2 = WT2_OFF5;
    } else if (z < 32) {     // k3 fused
        b = z - 24; ks = 3; tap0 = 0; tap1 = 9;
        slot = 0; kb = 1; fused = true; wtoff2 = WT2_OFF3;
    } else {                 // k1 fused
        b = z - 32; ks = 1; tap0 = 0; tap1 = 1;
        slot = 0; kb = 0; fused = true; wtoff2 = WT2_OFF1;
    }
    const int P = ks >> 1;
    const int rows = 8 + 2 * P;

    int n0 = blockIdx.x * 256;
    int m0 = blockIdx.y * 64;
    int r0 = n0 >> 5;
    int tid = threadIdx.x;
    int wid = tid >> 5, lane = tid & 31;
    int mw = (wid >> 2) * 32;
    int nw = (wid & 3) * 64;
    int lg = lane >> 2;
    int lk = lane & 3;

    // zero patch (halo + out-of-image rows stay zero)
    for (int i = tid; i < (8 * PL2) / 2; i += 256)
        *(float4*)&sPatch[i * 2] = make_float4(0.f, 0.f, 0.f, 0.f);

    int njoff[8];
#pragma unroll
    for (int j = 0; j < 8; j++) {
        int n = nw + 8 * j + lg;
        njoff[j] = (n >> 5) * 40 + (n & 31) + 4;
    }

    const float* inb = in + (size_t)b * (CC * NPIX);
    float acc[2][8][4] = {};

    for (int c0 = 0; c0 < 256; c0 += 16) {
        __syncthreads();
        // --- patch: channel c -> plane ((c>>3)<<2)+(c&3), comp (c>>2)&1 ---
        {
            int per_plane = rows * 8;
            int total = 16 * per_plane;
            for (int i = tid; i < total; i += 256) {
                int c  = i / per_plane;
                int rm = i - c * per_plane;
                int py = rm >> 3;
                int xq = (rm & 7) * 4;
                int iy = r0 - P + py;
                if ((unsigned)iy < 32u) {
                    float4 v = *(const float4*)&inb[(size_t)(c0 + c) * NPIX + iy * 32 + xq];
                    int p = ((c >> 3) << 2) + (c & 3);
                    int comp = (c >> 2) & 1;
                    float* dst = ((float*)&sPatch[p * PL2 + py * 40 + 4 + xq]) + comp;
                    dst[0] = to_tf32(v.x);
                    dst[2] = to_tf32(v.y);
                    dst[4] = to_tf32(v.z);
                    dst[6] = to_tf32(v.w);
                }
            }
        }
        // --- preload first tap group ---
        {
            size_t cb = wtoff2 + (size_t)(c0 >> 1) * 256;
            int gcnt = tap1 - tap0; if (gcnt > 4) gcnt = 4;
            for (int i = tid; i < gcnt * 256; i += 256) {
                int tg = i >> 8;
                int pi = (i >> 5) & 7;
                int c4 = (i & 31) * 2;
                *(float4*)&sA[tg * A2_TAP + pi * A2S + c4] =
                    *(const float4*)&g_wT2[cb + (size_t)(tap0 + tg) * 32768 +
                                           pi * 256 + m0 + c4];
            }
        }
        __syncthreads();

        int buf = 0;
        for (int g0 = tap0; g0 < tap1; g0 += 4) {
            int gcnt = tap1 - g0; if (gcnt > 4) gcnt = 4;
            int h0 = g0 + 4;
            if (h0 < tap1) {
                int hcnt = tap1 - h0; if (hcnt > 4) hcnt = 4;
                float2* dst = sA + (buf ^ 1) * A2_GRP;
                size_t cb = wtoff2 + (size_t)(c0 >> 1) * 256;
                for (int i = tid; i < hcnt * 256; i += 256) {
                    int tg = i >> 8;
                    int pi = (i >> 5) & 7;
                    int c4 = (i & 31) * 2;
                    *(float4*)&dst[tg * A2_TAP + pi * A2S + c4] =
                        *(const float4*)&g_wT2[cb + (size_t)(h0 + tg) * 32768 +
                                               pi * 256 + m0 + c4];
                }
            }
            for (int ti = 0; ti < gcnt; ti++) {
                int tap = g0 + ti;
                int ty = tap / ks;
                int tx = tap - ty * ks;
                int tadd = ty * 40 + tx - P;
                const float2* At = sA + buf * A2_GRP + ti * A2_TAP;
#pragma unroll
                for (int s = 0; s < 2; s++) {
                    int pi = s * 4 + lk;
                    uint32_t a[2][4];
#pragma unroll
                    for (int t = 0; t < 2; t++) {
                        float2 l = At[pi * A2S + mw + 16 * t + lg];
                        float2 h = At[pi * A2S + mw + 16 * t + lg + 8];
                        a[t][0] = __float_as_uint(l.x);
                        a[t][1] = __float_as_uint(h.x);
                        a[t][2] = __float_as_uint(l.y);
                        a[t][3] = __float_as_uint(h.y);
                    }
                    uint32_t bb[8][2];
#pragma unroll
                    for (int j = 0; j < 8; j++) {
                        float2 bv = sPatch[pi * PL2 + njoff[j] + tadd];
                        bb[j][0] = __float_as_uint(bv.x);
                        bb[j][1] = __float_as_uint(bv.y);
                    }
#pragma unroll
                    for (int t = 0; t < 2; t++)
#pragma unroll
                        for (int j = 0; j < 8; j++) mma_tf32(acc[t][j], a[t], bb[j]);
                }
            }
            __syncthreads();
            buf ^= 1;
        }
    }

    if (fused) {
        float* fp = feats + (size_t)kb * (BATCH * CC * NPIX) + (size_t)b * (CC * NPIX);
#pragma unroll
        for (int t = 0; t < 2; t++) {
            int o = m0 + mw + 16 * t + lg;
            float A0 = g_bnA[kb * 256 + o],     B0 = g_bnB[kb * 256 + o];
            float A1 = g_bnA[kb * 256 + o + 8], B1 = g_bnB[kb * 256 + o + 8];
#pragma unroll
            for (int j = 0; j < 8; j++) {
                int n = n0 + nw + 8 * j + 2 * lk;
                *(float2*)&fp[(size_t)o * NPIX + n] = make_float2(
                    fmaxf(acc[t][j][0] * A0 + B0, 0.f),
                    fmaxf(acc[t][j][1] * A0 + B0, 0.f));
                *(float2*)&fp[(size_t)(o + 8) * NPIX + n] = make_float2(
                    fmaxf(acc[t][j][2] * A1 + B1, 0.f),
                    fmaxf(acc[t][j][3] * A1 + B1, 0.f));
            }
        }
    } else {
        float* pp = g_part + (size_t)slot * (BATCH * CC * NPIX) + (size_t)b * (CC * NPIX);
#pragma unroll
        for (int t = 0; t < 2; t++) {
            int o = m0 + mw + 16 * t + lg;
#pragma unroll
            for (int j = 0; j < 8; j++) {
                int n = n0 + nw + 8 * j + 2 * lk;
                *(float2*)&pp[(size_t)o * NPIX + n] =
                    make_float2(acc[t][j][0], acc[t][j][1]);
                *(float2*)&pp[(size_t)(o + 8) * NPIX + n] =
                    make_float2(acc[t][j][2], acc[t][j][3]);
            }
        }
    }
}

// ---------------------------------------------------------------------------
// BN constants
// ---------------------------------------------------------------------------
__global__ void bnprep_kernel(const float* __restrict__ conv_b,
                              const float* __restrict__ gamma,
                              const float* __restrict__ beta,
                              const float* __restrict__ mean,
                              const float* __restrict__ var) {
    int i = threadIdx.x;
    float inv = gamma[i] * rsqrtf(var[i] + 1e-5f);
    g_bnA[i] = inv;
    g_bnB[i] = beta[i] - mean[i] * inv + conv_b[i] * inv;
}

// ---------------------------------------------------------------------------
// Epilogue (k7 only): sum the 2 split slots, BN + ReLU -> feats[3]
// ---------------------------------------------------------------------------
__global__ __launch_bounds__(256) void epi_kernel(float* __restrict__ feats) {
    int row = blockIdx.x;          // b*256 + o, 2048 rows
    int o   = row & 255;
    float Aa = g_bnA[768 + o];
    float Bb = g_bnB[768 + o];
    size_t base = (size_t)row * NPIX + threadIdx.x * 4;
    const size_t SL = (size_t)BATCH * CC * NPIX;
    float4 s0 = *(const float4*)&g_part[base];
    float4 s1 = *(const float4*)&g_part[SL + base];
    float4 v;
    v.x = fmaxf((s0.x + s1.x) * Aa + Bb, 0.f);
    v.y = fmaxf((s0.y + s1.y) * Aa + Bb, 0.f);
    v.z = fmaxf((s0.z + s1.z) * Aa + Bb, 0.f);
    v.w = fmaxf((s0.w + s1.w) * Aa + Bb, 0.f);
    *(float4*)&feats[3 * SL + base] = v;
}

// ---------------------------------------------------------------------------
// S[b,c] = mean over pixels of sum-over-branches of feats
// ---------------------------------------------------------------------------
__global__ __launch_bounds__(128) void sreduce_kernel(float* __restrict__ S) {
    int bc = blockIdx.x;
    int t  = threadIdx.x;
    float s = 0.f;
#pragma unroll
    for (int k = 0; k < 4; k++) {
        const float* p = g_feats + ((size_t)k * (BATCH * CC) + bc) * NPIX;
        for (int n = t; n < NPIX; n += 128) s += p[n];
    }
#pragma unroll
    for (int off = 16; off; off >>= 1) s += __shfl_down_sync(0xffffffffu, s, off);
    __shared__ float red[4];
    if ((t & 31) == 0) red[t >> 5] = s;
    __syncthreads();
    if (t == 0) S[bc] = (red[0] + red[1] + red[2] + red[3]) * (1.f / 1024.f);
}

// ---------------------------------------------------------------------------
// fc -> per-branch logits -> softmax over branches
// ---------------------------------------------------------------------------
__global__ __launch_bounds__(256) void select_kernel(
    const float* __restrict__ S, const float* __restrict__ fc_w,
    const float* __restrict__ fc_b, const float* __restrict__ fcs_w,
    const float* __restrict__ fcs_b, float* __restrict__ attnw) {
    __shared__ float Ss[BATCH * CC];
    __shared__ float Zs[BATCH * DDIM];
    int t = threadIdx.x;
    for (int i = t; i < BATCH * CC; i += 256) Ss[i] = S[i];
    __syncthreads();
    {
        int b = t >> 5, d = t & 31;
        float z = fc_b[d];
        const float* wr = fc_w + d * CC;
        for (int c = 0; c < CC; c++) z += Ss[b * CC + c] * wr[c];
        Zs[b * DDIM + d] = z;
    }
    __syncthreads();
    for (int it = 0; it < 8; it++) {
        int idx = it * 256 + t;
        int b = idx >> 8, c = idx & 255;
        float lg[4];
#pragma unroll
        for (int k = 0; k < 4; k++) {
            float v = fcs_b[k * CC + c];
            const float* wp = fcs_w + ((size_t)k * CC + c) * DDIM;
#pragma unroll
            for (int d = 0; d < DDIM; d++) v += wp[d] * Zs[b * DDIM + d];
            lg[k] = v;
        }
        float mx  = fmaxf(fmaxf(lg[0], lg[1]), fmaxf(lg[2], lg[3]));
        float e0 = __expf(lg[0] - mx), e1 = __expf(lg[1] - mx);
        float e2 = __expf(lg[2] - mx), e3 = __expf(lg[3] - mx);
        float inv = 1.f / (e0 + e1 + e2 + e3);
        attnw[0 * 2048 + idx] = e0 * inv;
        attnw[1 * 2048 + idx] = e1 * inv;
        attnw[2 * 2048 + idx] = e2 * inv;
        attnw[3 * 2048 + idx] = e3 * inv;
    }
}

// ---------------------------------------------------------------------------
// V = sum_k attn[k,b,c] * feats[k,b,c,:]
// ---------------------------------------------------------------------------
__global__ __launch_bounds__(256) void combine_kernel(const float* __restrict__ attnw,
                                                      float* __restrict__ out) {
    int idx = blockIdx.x * 256 + threadIdx.x;
    if (idx >= BATCH * CC * NPIX) return;
    int bc = idx >> 10;
    const size_t KSTRIDE = (size_t)BATCH * CC * NPIX;
    float v = attnw[bc]        * g_feats[idx] +
              attnw[2048 + bc] * g_feats[KSTRIDE + idx] +
              attnw[4096 + bc] * g_feats[2 * KSTRIDE + idx] +
              attnw[6144 + bc] * g_feats[3 * KSTRIDE + idx];
    out[idx] = v;
}

// ---------------------------------------------------------------------------
// Launch
// ---------------------------------------------------------------------------
extern "C" void kernel_launch(void* const* d_in, const int* in_sizes, int n_in,
                              void* d_out, int out_size) {
    const float* x      = (const float*)d_in[0];
    const float* qkv_w  = (const float*)d_in[1];
    const float* out_w  = (const float*)d_in[2];
    const float* w1     = (const float*)d_in[3];
    const float* w3     = (const float*)d_in[4];
    const float* w5     = (const float*)d_in[5];
    const float* w7     = (const float*)d_in[6];
    const float* conv_b = (const float*)d_in[7];
    const float* gamma  = (const float*)d_in[8];
    const float* beta   = (const float*)d_in[9];
    const float* mean   = (const float*)d_in[10];
    const float* var    = (const float*)d_in[11];
    const float* fc_w   = (const float*)d_in[12];
    const float* fc_b   = (const float*)d_in[13];
    const float* fcs_w  = (const float*)d_in[14];
    const float* fcs_b  = (const float*)d_in[15];
    float* out = (float*)d_out;

    float *p_qkv, *p_ctx, *p_ao, *p_feats, *p_S, *p_attnw;
    float *p_qw, *p_ow;
    cudaGetSymbolAddress((void**)&p_qkv,   g_qkv);
    cudaGetSymbolAddress((void**)&p_ctx,   g_ctx);
    cudaGetSymbolAddress((void**)&p_ao,    g_ao);
    cudaGetSymbolAddress((void**)&p_feats, g_feats);
    cudaGetSymbolAddress((void**)&p_S,     g_S);
    cudaGetSymbolAddress((void**)&p_attnw, g_attnw);
    cudaGetSymbolAddress((void**)&p_qw,    g_qkvwT);
    cudaGetSymbolAddress((void**)&p_ow,    g_outwT);

    static int attr_set = 0;
    if (!attr_set) {
        cudaFuncSetAttribute(attn_mma_kernel,
                             cudaFuncAttributeMaxDynamicSharedMemorySize,
                             ATTN_SMEM_BYTES);
        cudaFuncSetAttribute(conv_mma_kernel,
                             cudaFuncAttributeMaxDynamicSharedMemorySize,
                             CONV_SMEM_BYTES);
        attr_set = 1;
    }

    wtrans_kernel<<<10752, 256>>>(w1, w3, w5, w7);
    wsplit_kernel<<<1024, 256>>>(qkv_w, out_w);
    bnprep_kernel<<<1, 1024>>>(conv_b, gamma, beta, mean, var);

    gemm_mma_kernel<<<dim3(4, 12, 8), 256>>>(p_qw, x, p_qkv, 768);
    attn_mma_kernel<<<dim3(8, 64), 256, ATTN_SMEM_BYTES>>>(p_qkv, p_ctx);
    gemm_mma_kernel<<<dim3(4, 4, 8), 256>>>(p_ow, p_ctx, p_ao, 256);

    conv_mma_kernel<<<dim3(4, 4, 40), 256, CONV_SMEM_BYTES>>>(p_ao, p_feats);
    epi_kernel<<<2048, 256>>>(p_feats);

    sreduce_kernel<<<2048, 128>>>(p_S);
    select_kernel<<<1, 256>>>(p_S, fc_w, fc_b, fcs_w, fcs_b, p_attnw);
    combine_kernel<<<8192, 256>>>(p_attnw, out);
}